// round 2
// baseline (speedup 1.0000x reference)
#include <cuda_runtime.h>
#include <cuda_bf16.h>

// Problem constants
#define BB 2
#define TT 2048
#define DM 1024
#define NH 16
#define HS 64
#define QKVW 3072          // 3 * DM
#define CHUNK 64
#define NCK (TT / CHUNK)   // 32 chunks
#define NBH (BB * NH)      // 32 (b,h) pairs
#define STSZ (HS * HS + HS) // 4160 floats per chunk state (S[64][64] + den[64])

// Scratch (no cudaMalloc allowed)
__device__ float g_qkv[(size_t)BB * TT * QKVW];   // 50.3 MB
__device__ float g_xo[(size_t)BB * TT * DM];      // 16.8 MB
__device__ float g_state[(size_t)NBH * NCK * STSZ]; // 17 MB

// ---------------------------------------------------------------------------
// Tiled fp32 "NT" GEMM: C[m][n] = sum_k A[m][k] * B[n][k]
// A: M x K row-major, B: N x K row-major, C: M x N row-major.
// 128x128 tile, BK=32, 256 threads, 8x8 per thread.
// M,N multiples of 128; K multiple of 32 (true for all our shapes).
// ---------------------------------------------------------------------------
__global__ __launch_bounds__(256) void gemm_nt(const float* __restrict__ A,
                                               const float* __restrict__ B,
                                               float* __restrict__ C,
                                               int M, int N, int K) {
    __shared__ float As[32][128];
    __shared__ float Bs[32][128];
    const int tid = threadIdx.x;
    const int bm = blockIdx.y * 128;
    const int bn = blockIdx.x * 128;
    const int tm = (tid >> 4) << 3;
    const int tn = (tid & 15) << 3;

    float acc[8][8];
#pragma unroll
    for (int i = 0; i < 8; i++)
#pragma unroll
        for (int j = 0; j < 8; j++) acc[i][j] = 0.f;

    for (int k0 = 0; k0 < K; k0 += 32) {
#pragma unroll
        for (int i = 0; i < 4; i++) {
            int v = tid + i * 256;          // 0..1023
            int r = v >> 3;                 // 0..127
            int kc = (v & 7) << 2;          // 0,4,...,28
            float4 a = *(const float4*)&A[(size_t)(bm + r) * K + k0 + kc];
            As[kc + 0][r] = a.x; As[kc + 1][r] = a.y;
            As[kc + 2][r] = a.z; As[kc + 3][r] = a.w;
            float4 b = *(const float4*)&B[(size_t)(bn + r) * K + k0 + kc];
            Bs[kc + 0][r] = b.x; Bs[kc + 1][r] = b.y;
            Bs[kc + 2][r] = b.z; Bs[kc + 3][r] = b.w;
        }
        __syncthreads();
#pragma unroll
        for (int kk = 0; kk < 32; kk++) {
            float ar[8], br[8];
            *(float4*)&ar[0] = *(const float4*)&As[kk][tm];
            *(float4*)&ar[4] = *(const float4*)&As[kk][tm + 4];
            *(float4*)&br[0] = *(const float4*)&Bs[kk][tn];
            *(float4*)&br[4] = *(const float4*)&Bs[kk][tn + 4];
#pragma unroll
            for (int i = 0; i < 8; i++)
#pragma unroll
                for (int j = 0; j < 8; j++) acc[i][j] += ar[i] * br[j];
        }
        __syncthreads();
    }

#pragma unroll
    for (int i = 0; i < 8; i++) {
        float4 c0 = make_float4(acc[i][0], acc[i][1], acc[i][2], acc[i][3]);
        float4 c1 = make_float4(acc[i][4], acc[i][5], acc[i][6], acc[i][7]);
        *(float4*)&C[(size_t)(bm + tm + i) * N + bn + tn] = c0;
        *(float4*)&C[(size_t)(bm + tm + i) * N + bn + tn + 4] = c1;
    }
}

// ---------------------------------------------------------------------------
// Pass A: per (bh, chunk) compute chunk totals:
//   sumKV[c][d] = sum_t exp(k[t,c]) * v[t,d],   sumK[c] = sum_t exp(k[t,c])
// Written to g_state[(bh*NCK + ck)].
// ---------------------------------------------------------------------------
__global__ __launch_bounds__(256) void chunk_sums() {
    const int ck = blockIdx.x, bh = blockIdx.y;
    const int b = bh >> 4, h = bh & 15;
    __shared__ float ke[64][65];   // ke[c][t]  (transposed, exp applied)
    __shared__ float vs[64][65];   // vs[t][d]
    const int tid = threadIdx.x;

    for (int i = tid; i < 4096; i += 256) {
        int tt = i >> 6, c = i & 63;
        const float* row = g_qkv + (size_t)(b * TT + ck * CHUNK + tt) * QKVW;
        ke[c][tt] = __expf(row[(NH + h) * HS + c]);
        vs[tt][c] = row[(2 * NH + h) * HS + c];
    }
    __syncthreads();

    const int c = tid >> 2, dg = tid & 3;
    float acc[16];
#pragma unroll
    for (int j = 0; j < 16; j++) acc[j] = 0.f;
    float sk = 0.f;
    for (int t = 0; t < 64; t++) {
        float kv = ke[c][t];
        sk += kv;
        const float* vr = &vs[t][dg * 16];
#pragma unroll
        for (int j = 0; j < 16; j++) acc[j] += kv * vr[j];
    }
    float* st = g_state + (size_t)(bh * NCK + ck) * STSZ;
#pragma unroll
    for (int j = 0; j < 16; j++) st[c * 64 + dg * 16 + j] = acc[j];
    if (dg == 0) st[4096 + c] = sk;
}

// ---------------------------------------------------------------------------
// Pass B: exclusive prefix over the 32 chunks, per (bh, state-element).
// ---------------------------------------------------------------------------
__global__ __launch_bounds__(256) void chunk_prefix() {
    const int bh = blockIdx.y;
    const int idx = blockIdx.x * 256 + threadIdx.x;
    if (idx >= STSZ) return;
    float run = 0.f;
    float* base = g_state + (size_t)bh * NCK * STSZ + idx;
    for (int ck = 0; ck < NCK; ck++) {
        float t = base[(size_t)ck * STSZ];
        base[(size_t)ck * STSZ] = run;
        run += t;
    }
}

// ---------------------------------------------------------------------------
// Pass C: per (bh, chunk):
//   qn[t,c] = softmax(q)[t,c] * HS^-0.5 / (den0[c] + cumsum_t kexp[t,c] + 1e-9)
//   xo[t]   = qn[t] @ S0  +  causalmask(qn @ kexp^T) @ V
// Writes xo into g_xo in (b, t, h*64+d) layout so the final GEMM is plain.
// Dynamic smem: 4 arrays of 64x65 floats = 66560 B.
// ---------------------------------------------------------------------------
__global__ __launch_bounds__(256) void intra_chunk() {
    extern __shared__ float sm[];
    float* qn  = sm;            // [t][c] 64x65 : q -> softmax -> qn
    float* keT = sm + 4160;     // [c][t] 64x65 : exp(k), transposed
    float* vsm = sm + 8320;     // [t][d] 64x65
    float* SA  = sm + 12480;    // [c][d] S0, later reused as A[t][s]
    __shared__ float den0[64];

    const int ck = blockIdx.x, bh = blockIdx.y;
    const int b = bh >> 4, h = bh & 15;
    const int tid = threadIdx.x;
    const float* st = g_state + (size_t)(bh * NCK + ck) * STSZ;

    for (int i = tid; i < 4096; i += 256) {
        int tt = i >> 6, c = i & 63;
        const float* row = g_qkv + (size_t)(b * TT + ck * CHUNK + tt) * QKVW;
        qn[tt * 65 + c]  = row[h * HS + c];
        keT[c * 65 + tt] = __expf(row[(NH + h) * HS + c]);
        vsm[tt * 65 + c] = row[(2 * NH + h) * HS + c];
        SA[i + (i >> 6)] = st[i];          // S0[c][d] with 65-stride pad
    }
    if (tid < 64) den0[tid] = st[4096 + tid];
    __syncthreads();

    // softmax over the 64-wide head dim, per row t, then * HS^-0.5
    if (tid < 64) {
        float* qrow = qn + tid * 65;
        float m = qrow[0];
        for (int c = 1; c < 64; c++) m = fmaxf(m, qrow[c]);
        float s = 0.f;
        for (int c = 0; c < 64; c++) { float e = __expf(qrow[c] - m); qrow[c] = e; s += e; }
        float inv = 0.125f / s;            // HS^-0.5 = 1/8
        for (int c = 0; c < 64; c++) qrow[c] *= inv;
    }
    __syncthreads();

    // per-column running denominator; fold division into qn
    if (tid < 64) {
        const int c = tid;
        float run = den0[c];
        for (int t = 0; t < 64; t++) {
            run += keT[c * 65 + t];
            qn[t * 65 + c] = qn[t * 65 + c] / (run + 1e-9f);
        }
    }
    __syncthreads();

    const int t = tid >> 2, dg = tid & 3;
    const float* qrow = qn + t * 65;

    float acc[16], a[16];
#pragma unroll
    for (int j = 0; j < 16; j++) { acc[j] = 0.f; a[j] = 0.f; }

    // fused: acc = qn[t] @ S0 (this thread's 16 d's)
    //        a   = A[t][dg*16 .. +16] = qn[t] @ kexp^T slice
    for (int c = 0; c < 64; c++) {
        float qv = qrow[c];
        const float* srow = SA + c * 65 + dg * 16;
        const float* krow = keT + c * 65 + dg * 16;   // krow[j] = kexp[s=dg*16+j][c]
#pragma unroll
        for (int j = 0; j < 16; j++) {
            acc[j] += qv * srow[j];
            a[j]   += qv * krow[j];
        }
    }
    __syncthreads();   // all S0 reads done before overwriting SA with A
    {
        float* arow = SA + t * 65 + dg * 16;
#pragma unroll
        for (int j = 0; j < 16; j++) arow[j] = a[j];
    }
    __syncthreads();

    // causal (inclusive) A @ V
    const float* Arow = SA + t * 65;
    for (int s = 0; s <= t; s++) {
        float av = Arow[s];
        const float* vr = vsm + s * 65 + dg * 16;
#pragma unroll
        for (int j = 0; j < 16; j++) acc[j] += av * vr[j];
    }

    float* orow = g_xo + (size_t)(b * TT + ck * CHUNK + t) * DM + h * HS + dg * 16;
#pragma unroll
    for (int j = 0; j < 16; j++) orow[j] = acc[j];
}

// ---------------------------------------------------------------------------
extern "C" void kernel_launch(void* const* d_in, const int* in_sizes, int n_in,
                              void* d_out, int out_size) {
    const float* x    = (const float*)d_in[0];   // (2, 2048, 1024)
    const float* Wqkv = (const float*)d_in[1];   // (3072, 1024)
    const float* Wout = (const float*)d_in[2];   // (1024, 1024)
    float* out = (float*)d_out;                  // (2, 2048, 1024)

    float *qkv, *xo;
    cudaGetSymbolAddress((void**)&qkv, g_qkv);
    cudaGetSymbolAddress((void**)&xo, g_xo);

    cudaFuncSetAttribute(intra_chunk, cudaFuncAttributeMaxDynamicSharedMemorySize,
                         4 * 4160 * (int)sizeof(float));

    // 1) qkv = x @ Wqkv^T : M=4096, N=3072, K=1024
    gemm_nt<<<dim3(QKVW / 128, (BB * TT) / 128), 256>>>(x, Wqkv, qkv, BB * TT, QKVW, DM);
    // 2) chunk totals
    chunk_sums<<<dim3(NCK, NBH), 256>>>();
    // 3) exclusive prefix across chunks
    chunk_prefix<<<dim3((STSZ + 255) / 256, NBH), 256>>>();
    // 4) intra-chunk attention -> g_xo
    intra_chunk<<<dim3(NCK, NBH), 256, 4 * 4160 * (int)sizeof(float)>>>();
    // 5) out = xo @ Wout^T : M=4096, N=1024, K=1024
    gemm_nt<<<dim3(DM / 128, (BB * TT) / 128), 256>>>(xo, Wout, out, BB * TT, DM, DM);
}

// round 4
// speedup vs baseline: 1.9432x; 1.9432x over previous
#include <cuda_runtime.h>
#include <cuda_bf16.h>
#include <cstdint>

// Problem constants
#define BB 2
#define TT 2048
#define DM 1024
#define NH 16
#define HS 64
#define QKVW 3072          // 3 * DM
#define CHUNK 64
#define NCK (TT / CHUNK)   // 32 chunks
#define NBH (BB * NH)      // 32 (b,h) pairs
#define STSZ (HS * HS + HS) // 4160 floats per chunk state

// Scratch (no cudaMalloc allowed)
__device__ float g_qkv[(size_t)BB * TT * QKVW];   // 50.3 MB
__device__ float g_xo[(size_t)BB * TT * DM];      // 16.8 MB
__device__ float g_state[(size_t)NBH * NCK * STSZ]; // 17 MB

// ===========================================================================
// Warp-level tensor-core GEMM (mma.sync bf16, split hi/lo for fp32 accuracy)
// C[m][n] = sum_k A[m][k] * B[n][k];  A: MxK, B: NxK, C: MxN row-major fp32.
// CTA tile 128x128, BK=32, 256 threads (8 warps, each 64x32).
// ===========================================================================
#define KT 32
#define ROWP 40                     // padded row length in bf16 elems (80 B)
#define TILE_E (128 * ROWP)         // 5120 elems per tile
#define STAGE_E (4 * TILE_E)        // Ahi, Alo, Bhi, Blo
#define GEMM_SMEM_B (2 * STAGE_E * 2)  // 81920 bytes

__device__ __forceinline__ uint32_t smem_u32(const void* p) {
    uint32_t a;
    asm("{ .reg .u64 t; cvta.to.shared.u64 t, %1; cvt.u32.u64 %0, t; }"
        : "=r"(a) : "l"(p));
    return a;
}

__device__ __forceinline__ void ldsm_x4(uint32_t* r, uint32_t addr) {
    asm volatile("ldmatrix.sync.aligned.m8n8.x4.shared.b16 {%0,%1,%2,%3}, [%4];"
                 : "=r"(r[0]), "=r"(r[1]), "=r"(r[2]), "=r"(r[3]) : "r"(addr));
}

__device__ __forceinline__ void mma_bf16(float* c, const uint32_t* a, const uint32_t* b) {
    asm volatile(
        "mma.sync.aligned.m16n8k16.row.col.f32.bf16.bf16.f32 "
        "{%0,%1,%2,%3}, {%4,%5,%6,%7}, {%8,%9}, {%0,%1,%2,%3};"
        : "+f"(c[0]), "+f"(c[1]), "+f"(c[2]), "+f"(c[3])
        : "r"(a[0]), "r"(a[1]), "r"(a[2]), "r"(a[3]), "r"(b[0]), "r"(b[1]));
}

// convert 16 floats -> 16 bf16 hi + 16 bf16 lo, store 32B each
__device__ __forceinline__ void cvt_store16(__nv_bfloat16* hi, __nv_bfloat16* lo,
                                            const float4* r) {
    uint32_t hp[8], lp[8];
    const float* f = (const float*)r;
#pragma unroll
    for (int j = 0; j < 8; j++) {
        float a = f[2 * j], b = f[2 * j + 1];
        __nv_bfloat162 h = __floats2bfloat162_rn(a, b);
        float2 hf = __bfloat1622float2(h);
        __nv_bfloat162 l = __floats2bfloat162_rn(a - hf.x, b - hf.y);
        hp[j] = *(uint32_t*)&h;
        lp[j] = *(uint32_t*)&l;
    }
    ((uint4*)hi)[0] = make_uint4(hp[0], hp[1], hp[2], hp[3]);
    ((uint4*)hi)[1] = make_uint4(hp[4], hp[5], hp[6], hp[7]);
    ((uint4*)lo)[0] = make_uint4(lp[0], lp[1], lp[2], lp[3]);
    ((uint4*)lo)[1] = make_uint4(lp[4], lp[5], lp[6], lp[7]);
}

__global__ __launch_bounds__(256) void gemm_mma(const float* __restrict__ A,
                                                const float* __restrict__ B,
                                                float* __restrict__ C,
                                                int M, int N, int K) {
    extern __shared__ __nv_bfloat16 smbuf[];
    const int tid = threadIdx.x, wid = tid >> 5, lid = tid & 31;
    const int bm = blockIdx.y * 128, bn = blockIdx.x * 128;
    const int wm = (wid & 1) * 64, wn = (wid >> 1) * 32;

    // loader mapping: row = tid>>1 (0..127), col segment = (tid&1)*16 floats
    const int lrow = tid >> 1, lcol = (tid & 1) * 16;

    float acc[4][4][4];
#pragma unroll
    for (int mi = 0; mi < 4; mi++)
#pragma unroll
        for (int ni = 0; ni < 4; ni++)
#pragma unroll
            for (int q = 0; q < 4; q++) acc[mi][ni][q] = 0.f;

    float4 ra[4], rb[4];
    const int NC = K / KT;

    // ---- lane-invariant ldmatrix address components ----
    const int a_mrow = (lid < 16 ? lid : lid - 16);          // + wm + mi*16
    const int a_kadd = (lid < 16 ? 0 : 8);
    const int b_q = lid & 7, b_g = lid >> 3;
    const int b_nrow = b_q + (b_g >> 1) * 8;                 // + wn + nb*16
    const int b_kadd = (b_g & 1) * 8;

    const uint32_t sb = smem_u32(smbuf);

#define LDG_CHUNK(kc)                                                          \
    {                                                                          \
        const float4* ap = (const float4*)(A + (size_t)(bm + lrow) * K + (kc) * KT + lcol); \
        ra[0] = ap[0]; ra[1] = ap[1]; ra[2] = ap[2]; ra[3] = ap[3];            \
        const float4* bp = (const float4*)(B + (size_t)(bn + lrow) * K + (kc) * KT + lcol); \
        rb[0] = bp[0]; rb[1] = bp[1]; rb[2] = bp[2]; rb[3] = bp[3];            \
    }

#define STS_CHUNK(s)                                                           \
    {                                                                          \
        __nv_bfloat16* base = smbuf + (s) * STAGE_E;                           \
        int off = lrow * ROWP + lcol;                                          \
        cvt_store16(base + off, base + TILE_E + off, ra);                      \
        cvt_store16(base + 2 * TILE_E + off, base + 3 * TILE_E + off, rb);     \
    }

    LDG_CHUNK(0);
    STS_CHUNK(0);
    __syncthreads();

    for (int kc = 0; kc < NC; kc++) {
        if (kc + 1 < NC) LDG_CHUNK(kc + 1);

        const int s = kc & 1;
        const uint32_t stage = sb + s * (STAGE_E * 2);
#pragma unroll
        for (int ks = 0; ks < 2; ks++) {
            const int k0 = ks * 16;
            uint32_t Ah[4][4], Al[4][4], Bh[4][2], Bl[4][2];
#pragma unroll
            for (int mi = 0; mi < 4; mi++) {
                uint32_t addr = stage +
                    (uint32_t)(((wm + mi * 16 + a_mrow) * ROWP + k0 + a_kadd) * 2);
                ldsm_x4(Ah[mi], addr);
                ldsm_x4(Al[mi], addr + TILE_E * 2);
            }
#pragma unroll
            for (int nb = 0; nb < 2; nb++) {
                uint32_t addr = stage + 2 * TILE_E * 2 +
                    (uint32_t)(((wn + nb * 16 + b_nrow) * ROWP + k0 + b_kadd) * 2);
                uint32_t t[4];
                ldsm_x4(t, addr);
                Bh[nb * 2][0] = t[0]; Bh[nb * 2][1] = t[1];
                Bh[nb * 2 + 1][0] = t[2]; Bh[nb * 2 + 1][1] = t[3];
                ldsm_x4(t, addr + TILE_E * 2);
                Bl[nb * 2][0] = t[0]; Bl[nb * 2][1] = t[1];
                Bl[nb * 2 + 1][0] = t[2]; Bl[nb * 2 + 1][1] = t[3];
            }
#pragma unroll
            for (int mi = 0; mi < 4; mi++)
#pragma unroll
                for (int ni = 0; ni < 4; ni++) {
                    mma_bf16(acc[mi][ni], Ah[mi], Bh[ni]);
                    mma_bf16(acc[mi][ni], Ah[mi], Bl[ni]);
                    mma_bf16(acc[mi][ni], Al[mi], Bh[ni]);
                }
        }

        if (kc + 1 < NC) STS_CHUNK((kc + 1) & 1);
        __syncthreads();
    }

    // epilogue: c0,c1 at (row, col..col+1); c2,c3 at (row+8, col..col+1)
    const int erow = lid >> 2, ecol = 2 * (lid & 3);
#pragma unroll
    for (int mi = 0; mi < 4; mi++) {
#pragma unroll
        for (int ni = 0; ni < 4; ni++) {
            float* c0 = C + (size_t)(bm + wm + mi * 16 + erow) * N + bn + wn + ni * 8 + ecol;
            *(float2*)c0 = make_float2(acc[mi][ni][0], acc[mi][ni][1]);
            *(float2*)(c0 + 8 * N) = make_float2(acc[mi][ni][2], acc[mi][ni][3]);
        }
    }
}

// ---------------------------------------------------------------------------
// Pass A: per (bh, chunk) chunk totals: sumKV[c][d], sumK[c]
// ---------------------------------------------------------------------------
__global__ __launch_bounds__(256) void chunk_sums() {
    const int ck = blockIdx.x, bh = blockIdx.y;
    const int b = bh >> 4, h = bh & 15;
    __shared__ float ke[64][65];   // ke[c][t]
    __shared__ float vs[64][65];   // vs[t][d]
    const int tid = threadIdx.x;

    for (int i = tid; i < 4096; i += 256) {
        int tt = i >> 6, c = i & 63;
        const float* row = g_qkv + (size_t)(b * TT + ck * CHUNK + tt) * QKVW;
        ke[c][tt] = __expf(row[(NH + h) * HS + c]);
        vs[tt][c] = row[(2 * NH + h) * HS + c];
    }
    __syncthreads();

    const int c = tid >> 2, dg = tid & 3;
    float acc[16];
#pragma unroll
    for (int j = 0; j < 16; j++) acc[j] = 0.f;
    float sk = 0.f;
    for (int t = 0; t < 64; t++) {
        float kv = ke[c][t];
        sk += kv;
        const float* vr = &vs[t][dg * 16];
#pragma unroll
        for (int j = 0; j < 16; j++) acc[j] += kv * vr[j];
    }
    float* st = g_state + (size_t)(bh * NCK + ck) * STSZ;
#pragma unroll
    for (int j = 0; j < 16; j++) st[c * 64 + dg * 16 + j] = acc[j];
    if (dg == 0) st[4096 + c] = sk;
}

// ---------------------------------------------------------------------------
// Pass B: exclusive prefix over the 32 chunks
// ---------------------------------------------------------------------------
__global__ __launch_bounds__(256) void chunk_prefix() {
    const int bh = blockIdx.y;
    const int idx = blockIdx.x * 256 + threadIdx.x;
    if (idx >= STSZ) return;
    float run = 0.f;
    float* base = g_state + (size_t)bh * NCK * STSZ + idx;
    for (int ck = 0; ck < NCK; ck++) {
        float t = base[(size_t)ck * STSZ];
        base[(size_t)ck * STSZ] = run;
        run += t;
    }
}

// ---------------------------------------------------------------------------
// Pass C: intra-chunk attention
// ---------------------------------------------------------------------------
__global__ __launch_bounds__(256) void intra_chunk() {
    extern __shared__ float sm[];
    float* qn  = sm;            // [t][c]
    float* keT = sm + 4160;     // [c][t]
    float* vsm = sm + 8320;     // [t][d]
    float* SA  = sm + 12480;    // S0 then A
    __shared__ float den0[64];

    const int ck = blockIdx.x, bh = blockIdx.y;
    const int b = bh >> 4, h = bh & 15;
    const int tid = threadIdx.x;
    const float* st = g_state + (size_t)(bh * NCK + ck) * STSZ;

    for (int i = tid; i < 4096; i += 256) {
        int tt = i >> 6, c = i & 63;
        const float* row = g_qkv + (size_t)(b * TT + ck * CHUNK + tt) * QKVW;
        qn[tt * 65 + c]  = row[h * HS + c];
        keT[c * 65 + tt] = __expf(row[(NH + h) * HS + c]);
        vsm[tt * 65 + c] = row[(2 * NH + h) * HS + c];
        SA[i + (i >> 6)] = st[i];
    }
    if (tid < 64) den0[tid] = st[4096 + tid];
    __syncthreads();

    if (tid < 64) {
        float* qrow = qn + tid * 65;
        float m = qrow[0];
        for (int c = 1; c < 64; c++) m = fmaxf(m, qrow[c]);
        float s = 0.f;
        for (int c = 0; c < 64; c++) { float e = __expf(qrow[c] - m); qrow[c] = e; s += e; }
        float inv = 0.125f / s;
        for (int c = 0; c < 64; c++) qrow[c] *= inv;
    }
    __syncthreads();

    if (tid < 64) {
        const int c = tid;
        float run = den0[c];
        for (int t = 0; t < 64; t++) {
            run += keT[c * 65 + t];
            qn[t * 65 + c] = qn[t * 65 + c] / (run + 1e-9f);
        }
    }
    __syncthreads();

    const int t = tid >> 2, dg = tid & 3;
    const float* qrow = qn + t * 65;

    float acc[16], a[16];
#pragma unroll
    for (int j = 0; j < 16; j++) { acc[j] = 0.f; a[j] = 0.f; }

    for (int c = 0; c < 64; c++) {
        float qv = qrow[c];
        const float* srow = SA + c * 65 + dg * 16;
        const float* krow = keT + c * 65 + dg * 16;
#pragma unroll
        for (int j = 0; j < 16; j++) {
            acc[j] += qv * srow[j];
            a[j]   += qv * krow[j];
        }
    }
    __syncthreads();
    {
        float* arow = SA + t * 65 + dg * 16;
#pragma unroll
        for (int j = 0; j < 16; j++) arow[j] = a[j];
    }
    __syncthreads();

    const float* Arow = SA + t * 65;
    for (int s = 0; s <= t; s++) {
        float av = Arow[s];
        const float* vr = vsm + s * 65 + dg * 16;
#pragma unroll
        for (int j = 0; j < 16; j++) acc[j] += av * vr[j];
    }

    float* orow = g_xo + (size_t)(b * TT + ck * CHUNK + t) * DM + h * HS + dg * 16;
#pragma unroll
    for (int j = 0; j < 16; j++) orow[j] = acc[j];
}

// ---------------------------------------------------------------------------
extern "C" void kernel_launch(void* const* d_in, const int* in_sizes, int n_in,
                              void* d_out, int out_size) {
    const float* x    = (const float*)d_in[0];   // (2, 2048, 1024)
    const float* Wqkv = (const float*)d_in[1];   // (3072, 1024)
    const float* Wout = (const float*)d_in[2];   // (1024, 1024)
    float* out = (float*)d_out;                  // (2, 2048, 1024)

    float *qkv, *xo;
    cudaGetSymbolAddress((void**)&qkv, g_qkv);
    cudaGetSymbolAddress((void**)&xo, g_xo);

    cudaFuncSetAttribute(gemm_mma, cudaFuncAttributeMaxDynamicSharedMemorySize, GEMM_SMEM_B);
    cudaFuncSetAttribute(intra_chunk, cudaFuncAttributeMaxDynamicSharedMemorySize,
                         4 * 4160 * (int)sizeof(float));

    // 1) qkv = x @ Wqkv^T : M=4096, N=3072, K=1024
    gemm_mma<<<dim3(QKVW / 128, (BB * TT) / 128), 256, GEMM_SMEM_B>>>(x, Wqkv, qkv, BB * TT, QKVW, DM);
    // 2) chunk totals
    chunk_sums<<<dim3(NCK, NBH), 256>>>();
    // 3) exclusive prefix across chunks
    chunk_prefix<<<dim3((STSZ + 255) / 256, NBH), 256>>>();
    // 4) intra-chunk attention -> g_xo
    intra_chunk<<<dim3(NCK, NBH), 256, 4 * 4160 * (int)sizeof(float)>>>();
    // 5) out = xo @ Wout^T : M=4096, N=1024, K=1024
    gemm_mma<<<dim3(DM / 128, (BB * TT) / 128), 256, GEMM_SMEM_B>>>(xo, Wout, out, BB * TT, DM, DM);
}

// round 5
// speedup vs baseline: 2.0940x; 1.0776x over previous
#include <cuda_runtime.h>
#include <cuda_bf16.h>
#include <cstdint>

// Problem constants
#define BB 2
#define TT 2048
#define DM 1024
#define NH 16
#define HS 64
#define QKVW 3072          // 3 * DM
#define CHUNK 64
#define NCK (TT / CHUNK)   // 32 chunks
#define NBH (BB * NH)      // 32 (b,h) pairs
#define STSZ (HS * HS + HS) // 4160 floats per chunk state
#define PAD 68             // smem row pitch (floats), 16B-aligned rows

// Scratch (no cudaMalloc allowed)
__device__ float g_qkv[(size_t)BB * TT * QKVW];             // 50.3 MB fp32
__device__ float g_state[(size_t)NBH * NCK * STSZ];         // 17 MB
__device__ __nv_bfloat16 g_xhi[(size_t)BB * TT * DM];       // x split
__device__ __nv_bfloat16 g_xlo[(size_t)BB * TT * DM];
__device__ __nv_bfloat16 g_wqh[(size_t)QKVW * DM];          // W_qkv split
__device__ __nv_bfloat16 g_wql[(size_t)QKVW * DM];
__device__ __nv_bfloat16 g_woh[(size_t)DM * DM];            // W_out split
__device__ __nv_bfloat16 g_wol[(size_t)DM * DM];
__device__ __nv_bfloat16 g_xoh[(size_t)BB * TT * DM];       // xo split (from intra_chunk)
__device__ __nv_bfloat16 g_xol[(size_t)BB * TT * DM];

// ===========================================================================
// Helpers
// ===========================================================================
__device__ __forceinline__ uint32_t smem_u32(const void* p) {
    uint32_t a;
    asm("{ .reg .u64 t; cvta.to.shared.u64 t, %1; cvt.u32.u64 %0, t; }"
        : "=r"(a) : "l"(p));
    return a;
}

#define CP_ASYNC16(dst, src) \
    asm volatile("cp.async.cg.shared.global [%0], [%1], 16;" :: "r"(dst), "l"(src))
#define CP_COMMIT() asm volatile("cp.async.commit_group;" ::: "memory")
#define CP_WAIT1()  asm volatile("cp.async.wait_group 1;" ::: "memory")
#define CP_WAIT0()  asm volatile("cp.async.wait_group 0;" ::: "memory")

__device__ __forceinline__ void ldsm_x4(uint32_t* r, uint32_t addr) {
    asm volatile("ldmatrix.sync.aligned.m8n8.x4.shared.b16 {%0,%1,%2,%3}, [%4];"
                 : "=r"(r[0]), "=r"(r[1]), "=r"(r[2]), "=r"(r[3]) : "r"(addr));
}

__device__ __forceinline__ void mma_bf16(float* c, const uint32_t* a, const uint32_t* b) {
    asm volatile(
        "mma.sync.aligned.m16n8k16.row.col.f32.bf16.bf16.f32 "
        "{%0,%1,%2,%3}, {%4,%5,%6,%7}, {%8,%9}, {%0,%1,%2,%3};"
        : "+f"(c[0]), "+f"(c[1]), "+f"(c[2]), "+f"(c[3])
        : "r"(a[0]), "r"(a[1]), "r"(a[2]), "r"(a[3]), "r"(b[0]), "r"(b[1]));
}

// split 2 floats -> bf16 hi pair + lo pair (packed u32 each)
__device__ __forceinline__ void split2(float a, float b, uint32_t& hp, uint32_t& lp) {
    __nv_bfloat162 h = __floats2bfloat162_rn(a, b);
    float2 hf = __bfloat1622float2(h);
    __nv_bfloat162 l = __floats2bfloat162_rn(a - hf.x, b - hf.y);
    hp = *(uint32_t*)&h;
    lp = *(uint32_t*)&l;
}

// ---------------------------------------------------------------------------
// Prep: elementwise fp32 -> bf16 hi/lo split (vectorized, n multiple of 4)
// ---------------------------------------------------------------------------
__global__ __launch_bounds__(256) void split_f32(const float* __restrict__ src,
                                                 __nv_bfloat16* __restrict__ hi,
                                                 __nv_bfloat16* __restrict__ lo,
                                                 int n) {
    int i = (blockIdx.x * 256 + threadIdx.x) * 4;
    if (i >= n) return;
    float4 v = *(const float4*)(src + i);
    uint32_t h0, l0, h1, l1;
    split2(v.x, v.y, h0, l0);
    split2(v.z, v.w, h1, l1);
    *(uint2*)(hi + i) = make_uint2(h0, h1);
    *(uint2*)(lo + i) = make_uint2(l0, l1);
}

// ===========================================================================
// Tensor-core NT GEMM on pre-split bf16 hi/lo inputs.
// C[m][n] = sum_k A[m][k]*B[n][k], fp32 out. CTA 128x128, BK=32, 256 thr.
// cp.async double-buffered; no conversion in mainloop.
// ===========================================================================
#define KT 32
#define ROWB 80                      // bytes per smem row (32 bf16 + pad)
#define TILE_B (128 * ROWB)          // 10240 B
#define STAGE_B (4 * TILE_B)         // Ahi Alo Bhi Blo = 40960 B
#define GEMM_SMEM_B (2 * STAGE_B)    // 81920 B

__global__ __launch_bounds__(256) void gemm_bf16(const __nv_bfloat16* __restrict__ Ahi,
                                                 const __nv_bfloat16* __restrict__ Alo,
                                                 const __nv_bfloat16* __restrict__ Bhi,
                                                 const __nv_bfloat16* __restrict__ Blo,
                                                 float* __restrict__ C,
                                                 int M, int N, int K) {
    extern __shared__ char smraw[];
    const uint32_t sb = smem_u32(smraw);
    const int tid = threadIdx.x, wid = tid >> 5, lid = tid & 31;
    const int bm = blockIdx.y * 128, bn = blockIdx.x * 128;
    const int wm = (wid & 1) * 64, wn = (wid >> 1) * 32;
    const int NC = K / KT;

    const __nv_bfloat16* bases[4] = {Ahi, Alo, Bhi, Blo};

#define CP_STAGE(kc, s)                                                        \
    {                                                                          \
        uint32_t stb = sb + (s) * STAGE_B;                                     \
        _Pragma("unroll")                                                      \
        for (int it = 0; it < 8; it++) {                                       \
            int cid = it * 256 + tid;                                          \
            int tile = it >> 1;                                                \
            int r = (cid >> 2) & 127;                                          \
            int q = cid & 3;                                                   \
            int row0 = (tile < 2) ? bm : bn;                                   \
            const __nv_bfloat16* src =                                         \
                bases[tile] + (size_t)(row0 + r) * K + (kc) * KT + q * 8;      \
            CP_ASYNC16(stb + tile * TILE_B + r * ROWB + q * 16, src);          \
        }                                                                      \
        CP_COMMIT();                                                           \
    }

    float acc[4][4][4];
#pragma unroll
    for (int mi = 0; mi < 4; mi++)
#pragma unroll
        for (int ni = 0; ni < 4; ni++)
#pragma unroll
            for (int q = 0; q < 4; q++) acc[mi][ni][q] = 0.f;

    // lane-invariant ldmatrix address components
    const int a_mrow = (lid < 16 ? lid : lid - 16);
    const int a_kadd = (lid < 16 ? 0 : 8);
    const int b_q = lid & 7, b_g = lid >> 3;
    const int b_nrow = b_q + (b_g >> 1) * 8;
    const int b_kadd = (b_g & 1) * 8;

    CP_STAGE(0, 0);
    CP_STAGE(1, 1);

    for (int kc = 0; kc < NC; kc++) {
        if (kc < NC - 1) { CP_WAIT1(); } else { CP_WAIT0(); }
        __syncthreads();

        const uint32_t stage = sb + (kc & 1) * STAGE_B;
#pragma unroll
        for (int ks = 0; ks < 2; ks++) {
            const int k0 = ks * 16;
            uint32_t Ah[4][4], Al[4][4], Bh[4][2], Bl[4][2];
#pragma unroll
            for (int mi = 0; mi < 4; mi++) {
                uint32_t addr = stage +
                    (uint32_t)((wm + mi * 16 + a_mrow) * ROWB + (k0 + a_kadd) * 2);
                ldsm_x4(Ah[mi], addr);
                ldsm_x4(Al[mi], addr + TILE_B);
            }
#pragma unroll
            for (int nb = 0; nb < 2; nb++) {
                uint32_t addr = stage + 2 * TILE_B +
                    (uint32_t)((wn + nb * 16 + b_nrow) * ROWB + (k0 + b_kadd) * 2);
                uint32_t t[4];
                ldsm_x4(t, addr);
                Bh[nb * 2][0] = t[0]; Bh[nb * 2][1] = t[1];
                Bh[nb * 2 + 1][0] = t[2]; Bh[nb * 2 + 1][1] = t[3];
                ldsm_x4(t, addr + TILE_B);
                Bl[nb * 2][0] = t[0]; Bl[nb * 2][1] = t[1];
                Bl[nb * 2 + 1][0] = t[2]; Bl[nb * 2 + 1][1] = t[3];
            }
#pragma unroll
            for (int mi = 0; mi < 4; mi++)
#pragma unroll
                for (int ni = 0; ni < 4; ni++) {
                    mma_bf16(acc[mi][ni], Ah[mi], Bh[ni]);
                    mma_bf16(acc[mi][ni], Ah[mi], Bl[ni]);
                    mma_bf16(acc[mi][ni], Al[mi], Bh[ni]);
                }
        }
        __syncthreads();                 // done reading this stage
        if (kc + 2 < NC) CP_STAGE(kc + 2, kc & 1);
    }

    const int erow = lid >> 2, ecol = 2 * (lid & 3);
#pragma unroll
    for (int mi = 0; mi < 4; mi++) {
#pragma unroll
        for (int ni = 0; ni < 4; ni++) {
            float* c0 = C + (size_t)(bm + wm + mi * 16 + erow) * N + bn + wn + ni * 8 + ecol;
            *(float2*)c0 = make_float2(acc[mi][ni][0], acc[mi][ni][1]);
            *(float2*)(c0 + 8 * N) = make_float2(acc[mi][ni][2], acc[mi][ni][3]);
        }
    }
}

// ---------------------------------------------------------------------------
// Pass A: per (bh, chunk) chunk totals: sumKV[c][d], sumK[c]
// ---------------------------------------------------------------------------
__global__ __launch_bounds__(256) void chunk_sums() {
    const int ck = blockIdx.x, bh = blockIdx.y;
    const int b = bh >> 4, h = bh & 15;
    __shared__ float ke[64][65];    // ke[c][t] (scalar reads; 65 keeps writes clean)
    __shared__ float vs[64][PAD];   // vs[t][d] (float4 reads)
    const int tid = threadIdx.x;

    for (int i = tid; i < 4096; i += 256) {
        int tt = i >> 6, c = i & 63;
        const float* row = g_qkv + (size_t)(b * TT + ck * CHUNK + tt) * QKVW;
        ke[c][tt] = __expf(row[(NH + h) * HS + c]);
        vs[tt][c] = row[(2 * NH + h) * HS + c];
    }
    __syncthreads();

    const int c = tid >> 2, dg = tid & 3;
    float4 a0 = {0,0,0,0}, a1 = {0,0,0,0}, a2 = {0,0,0,0}, a3 = {0,0,0,0};
    float sk = 0.f;
    for (int t = 0; t < 64; t++) {
        float kv = ke[c][t];
        sk += kv;
        const float4* vr = (const float4*)(&vs[t][dg * 16]);
        float4 v0 = vr[0], v1 = vr[1], v2 = vr[2], v3 = vr[3];
        a0.x += kv * v0.x; a0.y += kv * v0.y; a0.z += kv * v0.z; a0.w += kv * v0.w;
        a1.x += kv * v1.x; a1.y += kv * v1.y; a1.z += kv * v1.z; a1.w += kv * v1.w;
        a2.x += kv * v2.x; a2.y += kv * v2.y; a2.z += kv * v2.z; a2.w += kv * v2.w;
        a3.x += kv * v3.x; a3.y += kv * v3.y; a3.z += kv * v3.z; a3.w += kv * v3.w;
    }
    float* st = g_state + (size_t)(bh * NCK + ck) * STSZ;
    float4* sp = (float4*)(st + c * 64 + dg * 16);
    sp[0] = a0; sp[1] = a1; sp[2] = a2; sp[3] = a3;
    if (dg == 0) st[4096 + c] = sk;
}

// ---------------------------------------------------------------------------
// Pass B: exclusive prefix over the 32 chunks
// ---------------------------------------------------------------------------
__global__ __launch_bounds__(256) void chunk_prefix() {
    const int bh = blockIdx.y;
    const int idx = blockIdx.x * 256 + threadIdx.x;
    if (idx >= STSZ) return;
    float run = 0.f;
    float* base = g_state + (size_t)bh * NCK * STSZ + idx;
    for (int ck = 0; ck < NCK; ck++) {
        float t = base[(size_t)ck * STSZ];
        base[(size_t)ck * STSZ] = run;
        run += t;
    }
}

// ---------------------------------------------------------------------------
// Pass C: intra-chunk attention; emits xo as bf16 hi/lo for GEMM2.
// Dynamic smem: 4 arrays of 64*PAD floats = 69632 B.
// ---------------------------------------------------------------------------
#define IC_SMEM (4 * 64 * PAD * (int)sizeof(float))

__global__ __launch_bounds__(256) void intra_chunk() {
    extern __shared__ float sm[];
    float* qn  = sm;                 // [t][c]
    float* keT = sm + 64 * PAD;      // [c][t]
    float* vsm = sm + 2 * 64 * PAD;  // [t][d]
    float* SA  = sm + 3 * 64 * PAD;  // S0 then A
    __shared__ float den0[64];

    const int ck = blockIdx.x, bh = blockIdx.y;
    const int b = bh >> 4, h = bh & 15;
    const int tid = threadIdx.x;
    const float* st = g_state + (size_t)(bh * NCK + ck) * STSZ;

    for (int i = tid; i < 4096; i += 256) {
        int tt = i >> 6, c = i & 63;
        const float* row = g_qkv + (size_t)(b * TT + ck * CHUNK + tt) * QKVW;
        qn[tt * PAD + c]  = row[h * HS + c];
        keT[c * PAD + tt] = __expf(row[(NH + h) * HS + c]);
        vsm[tt * PAD + c] = row[(2 * NH + h) * HS + c];
        SA[tt * PAD + c]  = st[i];           // S0[c][d]: tt==c-index here
    }
    if (tid < 64) den0[tid] = st[4096 + tid];
    __syncthreads();

    if (tid < 64) {
        float* qrow = qn + tid * PAD;
        float m = qrow[0];
        for (int c = 1; c < 64; c++) m = fmaxf(m, qrow[c]);
        float s = 0.f;
        for (int c = 0; c < 64; c++) { float e = __expf(qrow[c] - m); qrow[c] = e; s += e; }
        float inv = 0.125f / s;
        for (int c = 0; c < 64; c++) qrow[c] *= inv;
    }
    __syncthreads();

    if (tid < 64) {
        const int c = tid;
        float run = den0[c];
        for (int t = 0; t < 64; t++) {
            run += keT[c * PAD + t];
            qn[t * PAD + c] = qn[t * PAD + c] / (run + 1e-9f);
        }
    }
    __syncthreads();

    const int t = tid >> 2, dg = tid & 3;
    const float* qrow = qn + t * PAD;

    float acc[16], a[16];
#pragma unroll
    for (int j = 0; j < 16; j++) { acc[j] = 0.f; a[j] = 0.f; }

    for (int c = 0; c < 64; c++) {
        float qv = qrow[c];
        const float4* srow = (const float4*)(SA + c * PAD + dg * 16);
        const float4* krow = (const float4*)(keT + c * PAD + dg * 16);
#pragma unroll
        for (int q = 0; q < 4; q++) {
            float4 sv = srow[q], kv = krow[q];
            acc[4 * q + 0] += qv * sv.x; acc[4 * q + 1] += qv * sv.y;
            acc[4 * q + 2] += qv * sv.z; acc[4 * q + 3] += qv * sv.w;
            a[4 * q + 0] += qv * kv.x; a[4 * q + 1] += qv * kv.y;
            a[4 * q + 2] += qv * kv.z; a[4 * q + 3] += qv * kv.w;
        }
    }
    __syncthreads();   // all S0 reads done before overwriting SA with A
    {
        float4* arow = (float4*)(SA + t * PAD + dg * 16);
#pragma unroll
        for (int q = 0; q < 4; q++)
            arow[q] = make_float4(a[4 * q], a[4 * q + 1], a[4 * q + 2], a[4 * q + 3]);
    }
    __syncthreads();

    const float* Arow = SA + t * PAD;
    for (int s = 0; s <= t; s++) {
        float av = Arow[s];
        const float4* vr = (const float4*)(vsm + s * PAD + dg * 16);
#pragma unroll
        for (int q = 0; q < 4; q++) {
            float4 vv = vr[q];
            acc[4 * q + 0] += av * vv.x; acc[4 * q + 1] += av * vv.y;
            acc[4 * q + 2] += av * vv.z; acc[4 * q + 3] += av * vv.w;
        }
    }

    // store xo as bf16 hi/lo
    size_t off = (size_t)(b * TT + ck * CHUNK + t) * DM + h * HS + dg * 16;
    uint32_t hp[8], lp[8];
#pragma unroll
    for (int j = 0; j < 8; j++) split2(acc[2 * j], acc[2 * j + 1], hp[j], lp[j]);
    uint4* ho = (uint4*)(g_xoh + off);
    uint4* lo = (uint4*)(g_xol + off);
    ho[0] = make_uint4(hp[0], hp[1], hp[2], hp[3]);
    ho[1] = make_uint4(hp[4], hp[5], hp[6], hp[7]);
    lo[0] = make_uint4(lp[0], lp[1], lp[2], lp[3]);
    lo[1] = make_uint4(lp[4], lp[5], lp[6], lp[7]);
}

// ---------------------------------------------------------------------------
extern "C" void kernel_launch(void* const* d_in, const int* in_sizes, int n_in,
                              void* d_out, int out_size) {
    const float* x    = (const float*)d_in[0];   // (2, 2048, 1024)
    const float* Wqkv = (const float*)d_in[1];   // (3072, 1024)
    const float* Wout = (const float*)d_in[2];   // (1024, 1024)
    float* out = (float*)d_out;                  // (2, 2048, 1024)

    float* qkv;
    cudaGetSymbolAddress((void**)&qkv, g_qkv);
    __nv_bfloat16 *xhi, *xlo, *wqh, *wql, *woh, *wol, *xoh, *xol;
    cudaGetSymbolAddress((void**)&xhi, g_xhi);
    cudaGetSymbolAddress((void**)&xlo, g_xlo);
    cudaGetSymbolAddress((void**)&wqh, g_wqh);
    cudaGetSymbolAddress((void**)&wql, g_wql);
    cudaGetSymbolAddress((void**)&woh, g_woh);
    cudaGetSymbolAddress((void**)&wol, g_wol);
    cudaGetSymbolAddress((void**)&xoh, g_xoh);
    cudaGetSymbolAddress((void**)&xol, g_xol);

    cudaFuncSetAttribute(gemm_bf16, cudaFuncAttributeMaxDynamicSharedMemorySize, GEMM_SMEM_B);
    cudaFuncSetAttribute(intra_chunk, cudaFuncAttributeMaxDynamicSharedMemorySize, IC_SMEM);

    // 0) split inputs into bf16 hi/lo
    split_f32<<<(BB * TT * DM) / 1024, 256>>>(x, xhi, xlo, BB * TT * DM);
    split_f32<<<(QKVW * DM) / 1024, 256>>>(Wqkv, wqh, wql, QKVW * DM);
    split_f32<<<(DM * DM) / 1024, 256>>>(Wout, woh, wol, DM * DM);

    // 1) qkv = x @ Wqkv^T
    gemm_bf16<<<dim3(QKVW / 128, (BB * TT) / 128), 256, GEMM_SMEM_B>>>(
        xhi, xlo, wqh, wql, qkv, BB * TT, QKVW, DM);
    // 2) chunk totals
    chunk_sums<<<dim3(NCK, NBH), 256>>>();
    // 3) exclusive prefix across chunks
    chunk_prefix<<<dim3((STSZ + 255) / 256, NBH), 256>>>();
    // 4) intra-chunk attention -> xo (bf16 hi/lo)
    intra_chunk<<<dim3(NCK, NBH), 256, IC_SMEM>>>();
    // 5) out = xo @ Wout^T
    gemm_bf16<<<dim3(DM / 128, (BB * TT) / 128), 256, GEMM_SMEM_B>>>(
        xoh, xol, woh, wol, out, BB * TT, DM, DM);
}

// round 6
// speedup vs baseline: 2.2864x; 1.0919x over previous
#include <cuda_runtime.h>
#include <cuda_bf16.h>
#include <cstdint>

// Problem constants
#define BB 2
#define TT 2048
#define DM 1024
#define NH 16
#define HS 64
#define QKVW 3072          // 3 * DM
#define CHUNK 64
#define NCK (TT / CHUNK)   // 32 chunks
#define NBH (BB * NH)      // 32 (b,h) pairs
#define STSZ (HS * HS + HS) // 4160 floats per chunk state
#define PAD 68             // smem row pitch (floats), 16B-aligned rows

// Scratch (no cudaMalloc allowed)
__device__ float g_qkv[(size_t)BB * TT * QKVW];             // 50.3 MB fp32
__device__ float g_state[(size_t)NBH * NCK * STSZ];         // 17 MB
__device__ __nv_bfloat16 g_xhi[(size_t)BB * TT * DM];       // x split
__device__ __nv_bfloat16 g_xlo[(size_t)BB * TT * DM];
__device__ __nv_bfloat16 g_wqh[(size_t)QKVW * DM];          // W_qkv split
__device__ __nv_bfloat16 g_wql[(size_t)QKVW * DM];
__device__ __nv_bfloat16 g_woh[(size_t)DM * DM];            // W_out split
__device__ __nv_bfloat16 g_wol[(size_t)DM * DM];
__device__ __nv_bfloat16 g_xoh[(size_t)BB * TT * DM];       // xo split (from intra_chunk)
__device__ __nv_bfloat16 g_xol[(size_t)BB * TT * DM];

// ===========================================================================
// Helpers
// ===========================================================================
__device__ __forceinline__ uint32_t smem_u32(const void* p) {
    uint32_t a;
    asm("{ .reg .u64 t; cvta.to.shared.u64 t, %1; cvt.u32.u64 %0, t; }"
        : "=r"(a) : "l"(p));
    return a;
}

#define CP_ASYNC16(dst, src) \
    asm volatile("cp.async.cg.shared.global [%0], [%1], 16;" :: "r"(dst), "l"(src))
#define CP_COMMIT() asm volatile("cp.async.commit_group;" ::: "memory")
#define CP_WAIT1()  asm volatile("cp.async.wait_group 1;" ::: "memory")
#define CP_WAIT0()  asm volatile("cp.async.wait_group 0;" ::: "memory")

__device__ __forceinline__ void ldsm_x4(uint32_t* r, uint32_t addr) {
    asm volatile("ldmatrix.sync.aligned.m8n8.x4.shared.b16 {%0,%1,%2,%3}, [%4];"
                 : "=r"(r[0]), "=r"(r[1]), "=r"(r[2]), "=r"(r[3]) : "r"(addr));
}

__device__ __forceinline__ void mma_bf16(float* c, const uint32_t* a, const uint32_t* b) {
    asm volatile(
        "mma.sync.aligned.m16n8k16.row.col.f32.bf16.bf16.f32 "
        "{%0,%1,%2,%3}, {%4,%5,%6,%7}, {%8,%9}, {%0,%1,%2,%3};"
        : "+f"(c[0]), "+f"(c[1]), "+f"(c[2]), "+f"(c[3])
        : "r"(a[0]), "r"(a[1]), "r"(a[2]), "r"(a[3]), "r"(b[0]), "r"(b[1]));
}

// split 2 floats -> bf16 hi pair + lo pair (packed u32 each)
__device__ __forceinline__ void split2(float a, float b, uint32_t& hp, uint32_t& lp) {
    __nv_bfloat162 h = __floats2bfloat162_rn(a, b);
    float2 hf = __bfloat1622float2(h);
    __nv_bfloat162 l = __floats2bfloat162_rn(a - hf.x, b - hf.y);
    hp = *(uint32_t*)&h;
    lp = *(uint32_t*)&l;
}

// ---------------------------------------------------------------------------
// Prep: elementwise fp32 -> bf16 hi/lo split (vectorized, n multiple of 4)
// ---------------------------------------------------------------------------
__global__ __launch_bounds__(256) void split_f32(const float* __restrict__ src,
                                                 __nv_bfloat16* __restrict__ hi,
                                                 __nv_bfloat16* __restrict__ lo,
                                                 int n) {
    int i = (blockIdx.x * 256 + threadIdx.x) * 4;
    if (i >= n) return;
    float4 v = *(const float4*)(src + i);
    uint32_t h0, l0, h1, l1;
    split2(v.x, v.y, h0, l0);
    split2(v.z, v.w, h1, l1);
    *(uint2*)(hi + i) = make_uint2(h0, h1);
    *(uint2*)(lo + i) = make_uint2(l0, l1);
}

// ===========================================================================
// Tensor-core NT GEMM on pre-split bf16 hi/lo inputs.
// C[m][n] = sum_k A[m][k]*B[n][k], fp32 out. CTA 128x128, BK=32, 256 thr.
// 3-stage cp.async ring, XOR-swizzled smem (64B rows, no padding),
// ONE __syncthreads per K-chunk.
// Swizzle: 16B granule index g (0..3) within a 64B row r -> g ^ ((r>>1)&3).
//   - cp.async write phase (8 lanes): 2 rows x 4 granules = 32 banks, clean.
//   - ldmatrix read phase (8 lanes): 8 consecutive rows, fixed g; even rows
//     get granules g^0..g^3 (distinct), odd rows likewise -> 32 banks, clean.
// ===========================================================================
#define KT 32
#define TILE_B 8192                  // 128 rows * 64 B
#define STAGE_B (4 * TILE_B)         // Ahi Alo Bhi Blo = 32768 B
#define NSTAGE 3
#define GEMM_SMEM_B (NSTAGE * STAGE_B)  // 98304 B

__global__ __launch_bounds__(256) void gemm_bf16(const __nv_bfloat16* __restrict__ Ahi,
                                                 const __nv_bfloat16* __restrict__ Alo,
                                                 const __nv_bfloat16* __restrict__ Bhi,
                                                 const __nv_bfloat16* __restrict__ Blo,
                                                 float* __restrict__ C,
                                                 int M, int N, int K) {
    extern __shared__ char smraw[];
    const uint32_t sb = smem_u32(smraw);
    const int tid = threadIdx.x, wid = tid >> 5, lid = tid & 31;
    const int bm = blockIdx.y * 128, bn = blockIdx.x * 128;
    const int wm = (wid & 1) * 64, wn = (wid >> 1) * 32;
    const int NC = K / KT;

    const __nv_bfloat16* bases[4] = {Ahi, Alo, Bhi, Blo};

    // 2048 granules (16B) per stage; 8 per thread
#define CP_STAGE(kc, s)                                                        \
    {                                                                          \
        uint32_t stb = sb + (s) * STAGE_B;                                     \
        _Pragma("unroll")                                                      \
        for (int it = 0; it < 8; it++) {                                       \
            int cid = it * 256 + tid;                                          \
            int tile = cid >> 9;                                               \
            int rem = cid & 511;                                               \
            int r = rem >> 2;                                                  \
            int g = rem & 3;                                                   \
            int row0 = (tile < 2) ? bm : bn;                                   \
            const __nv_bfloat16* src =                                         \
                bases[tile] + (size_t)(row0 + r) * K + (kc) * KT + g * 8;      \
            uint32_t dst = stb + tile * TILE_B + r * 64 +                      \
                           (((g ^ ((r >> 1) & 3))) << 4);                      \
            CP_ASYNC16(dst, src);                                              \
        }                                                                      \
        CP_COMMIT();                                                           \
    }

    float acc[4][4][4];
#pragma unroll
    for (int mi = 0; mi < 4; mi++)
#pragma unroll
        for (int ni = 0; ni < 4; ni++)
#pragma unroll
            for (int q = 0; q < 4; q++) acc[mi][ni][q] = 0.f;

    // lane-invariant ldmatrix row/granule components
    const int a_mrow = (lid < 16 ? lid : lid - 16);
    const int a_g    = (lid < 16 ? 0 : 1);
    const int b_q = lid & 7, b_g4 = lid >> 3;
    const int b_nrow = b_q + (b_g4 >> 1) * 8;
    const int b_g    = (b_g4 & 1);

    CP_STAGE(0, 0);
    CP_STAGE(1, 1);

    for (int kc = 0; kc < NC; kc++) {
        if (kc < NC - 1) { CP_WAIT1(); } else { CP_WAIT0(); }
        __syncthreads();                       // stage kc ready; slot (kc+2)%3 free
        if (kc + 2 < NC) CP_STAGE(kc + 2, (kc + 2) % NSTAGE);

        const uint32_t stage = sb + (kc % NSTAGE) * STAGE_B;
#pragma unroll
        for (int ks = 0; ks < 2; ks++) {
            uint32_t Ah[4][4], Al[4][4], Bh[4][2], Bl[4][2];
#pragma unroll
            for (int mi = 0; mi < 4; mi++) {
                int row = wm + mi * 16 + a_mrow;
                int gran = ks * 2 + a_g;
                uint32_t addr = stage + row * 64 + ((gran ^ ((row >> 1) & 3)) << 4);
                ldsm_x4(Ah[mi], addr);
                ldsm_x4(Al[mi], addr + TILE_B);
            }
#pragma unroll
            for (int nb = 0; nb < 2; nb++) {
                int row = wn + nb * 16 + b_nrow;
                int gran = ks * 2 + b_g;
                uint32_t addr = stage + 2 * TILE_B + row * 64 +
                                ((gran ^ ((row >> 1) & 3)) << 4);
                uint32_t t[4];
                ldsm_x4(t, addr);
                Bh[nb * 2][0] = t[0]; Bh[nb * 2][1] = t[1];
                Bh[nb * 2 + 1][0] = t[2]; Bh[nb * 2 + 1][1] = t[3];
                ldsm_x4(t, addr + TILE_B);
                Bl[nb * 2][0] = t[0]; Bl[nb * 2][1] = t[1];
                Bl[nb * 2 + 1][0] = t[2]; Bl[nb * 2 + 1][1] = t[3];
            }
#pragma unroll
            for (int mi = 0; mi < 4; mi++)
#pragma unroll
                for (int ni = 0; ni < 4; ni++) {
                    mma_bf16(acc[mi][ni], Ah[mi], Bh[ni]);
                    mma_bf16(acc[mi][ni], Ah[mi], Bl[ni]);
                    mma_bf16(acc[mi][ni], Al[mi], Bh[ni]);
                }
        }
    }

    const int erow = lid >> 2, ecol = 2 * (lid & 3);
#pragma unroll
    for (int mi = 0; mi < 4; mi++) {
#pragma unroll
        for (int ni = 0; ni < 4; ni++) {
            float* c0 = C + (size_t)(bm + wm + mi * 16 + erow) * N + bn + wn + ni * 8 + ecol;
            *(float2*)c0 = make_float2(acc[mi][ni][0], acc[mi][ni][1]);
            *(float2*)(c0 + 8 * N) = make_float2(acc[mi][ni][2], acc[mi][ni][3]);
        }
    }
}

// ---------------------------------------------------------------------------
// Pass A: per (bh, chunk) chunk totals: sumKV[c][d], sumK[c]
// ---------------------------------------------------------------------------
__global__ __launch_bounds__(256) void chunk_sums() {
    const int ck = blockIdx.x, bh = blockIdx.y;
    const int b = bh >> 4, h = bh & 15;
    __shared__ float ke[64][65];    // ke[c][t] (scalar reads)
    __shared__ float vs[64][PAD];   // vs[t][d] (float4 reads)
    const int tid = threadIdx.x;

    for (int i = tid; i < 4096; i += 256) {
        int tt = i >> 6, c = i & 63;
        const float* row = g_qkv + (size_t)(b * TT + ck * CHUNK + tt) * QKVW;
        ke[c][tt] = __expf(row[(NH + h) * HS + c]);
        vs[tt][c] = row[(2 * NH + h) * HS + c];
    }
    __syncthreads();

    const int c = tid >> 2, dg = tid & 3;
    float4 a0 = {0,0,0,0}, a1 = {0,0,0,0}, a2 = {0,0,0,0}, a3 = {0,0,0,0};
    float sk = 0.f;
    for (int t = 0; t < 64; t++) {
        float kv = ke[c][t];
        sk += kv;
        const float4* vr = (const float4*)(&vs[t][dg * 16]);
        float4 v0 = vr[0], v1 = vr[1], v2 = vr[2], v3 = vr[3];
        a0.x += kv * v0.x; a0.y += kv * v0.y; a0.z += kv * v0.z; a0.w += kv * v0.w;
        a1.x += kv * v1.x; a1.y += kv * v1.y; a1.z += kv * v1.z; a1.w += kv * v1.w;
        a2.x += kv * v2.x; a2.y += kv * v2.y; a2.z += kv * v2.z; a2.w += kv * v2.w;
        a3.x += kv * v3.x; a3.y += kv * v3.y; a3.z += kv * v3.z; a3.w += kv * v3.w;
    }
    float* st = g_state + (size_t)(bh * NCK + ck) * STSZ;
    float4* sp = (float4*)(st + c * 64 + dg * 16);
    sp[0] = a0; sp[1] = a1; sp[2] = a2; sp[3] = a3;
    if (dg == 0) st[4096 + c] = sk;
}

// ---------------------------------------------------------------------------
// Pass B: exclusive prefix over the 32 chunks
// ---------------------------------------------------------------------------
__global__ __launch_bounds__(256) void chunk_prefix() {
    const int bh = blockIdx.y;
    const int idx = blockIdx.x * 256 + threadIdx.x;
    if (idx >= STSZ) return;
    float run = 0.f;
    float* base = g_state + (size_t)bh * NCK * STSZ + idx;
    for (int ck = 0; ck < NCK; ck++) {
        float t = base[(size_t)ck * STSZ];
        base[(size_t)ck * STSZ] = run;
        run += t;
    }
}

// ---------------------------------------------------------------------------
// Pass C: intra-chunk attention; emits xo as bf16 hi/lo for GEMM2.
// ---------------------------------------------------------------------------
#define IC_SMEM (4 * 64 * PAD * (int)sizeof(float))

__global__ __launch_bounds__(256) void intra_chunk() {
    extern __shared__ float sm[];
    float* qn  = sm;                 // [t][c]
    float* keT = sm + 64 * PAD;      // [c][t]
    float* vsm = sm + 2 * 64 * PAD;  // [t][d]
    float* SA  = sm + 3 * 64 * PAD;  // S0 then A
    __shared__ float den0[64];

    const int ck = blockIdx.x, bh = blockIdx.y;
    const int b = bh >> 4, h = bh & 15;
    const int tid = threadIdx.x;
    const float* st = g_state + (size_t)(bh * NCK + ck) * STSZ;

    for (int i = tid; i < 4096; i += 256) {
        int tt = i >> 6, c = i & 63;
        const float* row = g_qkv + (size_t)(b * TT + ck * CHUNK + tt) * QKVW;
        qn[tt * PAD + c]  = row[h * HS + c];
        keT[c * PAD + tt] = __expf(row[(NH + h) * HS + c]);
        vsm[tt * PAD + c] = row[(2 * NH + h) * HS + c];
        SA[tt * PAD + c]  = st[i];
    }
    if (tid < 64) den0[tid] = st[4096 + tid];
    __syncthreads();

    if (tid < 64) {
        float* qrow = qn + tid * PAD;
        float m = qrow[0];
        for (int c = 1; c < 64; c++) m = fmaxf(m, qrow[c]);
        float s = 0.f;
        for (int c = 0; c < 64; c++) { float e = __expf(qrow[c] - m); qrow[c] = e; s += e; }
        float inv = 0.125f / s;
        for (int c = 0; c < 64; c++) qrow[c] *= inv;
    }
    __syncthreads();

    if (tid < 64) {
        const int c = tid;
        float run = den0[c];
        for (int t = 0; t < 64; t++) {
            run += keT[c * PAD + t];
            qn[t * PAD + c] = qn[t * PAD + c] / (run + 1e-9f);
        }
    }
    __syncthreads();

    const int t = tid >> 2, dg = tid & 3;
    const float* qrow = qn + t * PAD;

    float acc[16], a[16];
#pragma unroll
    for (int j = 0; j < 16; j++) { acc[j] = 0.f; a[j] = 0.f; }

    for (int c = 0; c < 64; c++) {
        float qv = qrow[c];
        const float4* srow = (const float4*)(SA + c * PAD + dg * 16);
        const float4* krow = (const float4*)(keT + c * PAD + dg * 16);
#pragma unroll
        for (int q = 0; q < 4; q++) {
            float4 sv = srow[q], kv = krow[q];
            acc[4 * q + 0] += qv * sv.x; acc[4 * q + 1] += qv * sv.y;
            acc[4 * q + 2] += qv * sv.z; acc[4 * q + 3] += qv * sv.w;
            a[4 * q + 0] += qv * kv.x; a[4 * q + 1] += qv * kv.y;
            a[4 * q + 2] += qv * kv.z; a[4 * q + 3] += qv * kv.w;
        }
    }
    __syncthreads();
    {
        float4* arow = (float4*)(SA + t * PAD + dg * 16);
#pragma unroll
        for (int q = 0; q < 4; q++)
            arow[q] = make_float4(a[4 * q], a[4 * q + 1], a[4 * q + 2], a[4 * q + 3]);
    }
    __syncthreads();

    const float* Arow = SA + t * PAD;
    for (int s = 0; s <= t; s++) {
        float av = Arow[s];
        const float4* vr = (const float4*)(vsm + s * PAD + dg * 16);
#pragma unroll
        for (int q = 0; q < 4; q++) {
            float4 vv = vr[q];
            acc[4 * q + 0] += av * vv.x; acc[4 * q + 1] += av * vv.y;
            acc[4 * q + 2] += av * vv.z; acc[4 * q + 3] += av * vv.w;
        }
    }

    size_t off = (size_t)(b * TT + ck * CHUNK + t) * DM + h * HS + dg * 16;
    uint32_t hp[8], lp[8];
#pragma unroll
    for (int j = 0; j < 8; j++) split2(acc[2 * j], acc[2 * j + 1], hp[j], lp[j]);
    uint4* ho = (uint4*)(g_xoh + off);
    uint4* lo = (uint4*)(g_xol + off);
    ho[0] = make_uint4(hp[0], hp[1], hp[2], hp[3]);
    ho[1] = make_uint4(hp[4], hp[5], hp[6], hp[7]);
    lo[0] = make_uint4(lp[0], lp[1], lp[2], lp[3]);
    lo[1] = make_uint4(lp[4], lp[5], lp[6], lp[7]);
}

// ---------------------------------------------------------------------------
extern "C" void kernel_launch(void* const* d_in, const int* in_sizes, int n_in,
                              void* d_out, int out_size) {
    const float* x    = (const float*)d_in[0];   // (2, 2048, 1024)
    const float* Wqkv = (const float*)d_in[1];   // (3072, 1024)
    const float* Wout = (const float*)d_in[2];   // (1024, 1024)
    float* out = (float*)d_out;                  // (2, 2048, 1024)

    float* qkv;
    cudaGetSymbolAddress((void**)&qkv, g_qkv);
    __nv_bfloat16 *xhi, *xlo, *wqh, *wql, *woh, *wol, *xoh, *xol;
    cudaGetSymbolAddress((void**)&xhi, g_xhi);
    cudaGetSymbolAddress((void**)&xlo, g_xlo);
    cudaGetSymbolAddress((void**)&wqh, g_wqh);
    cudaGetSymbolAddress((void**)&wql, g_wql);
    cudaGetSymbolAddress((void**)&woh, g_woh);
    cudaGetSymbolAddress((void**)&wol, g_wol);
    cudaGetSymbolAddress((void**)&xoh, g_xoh);
    cudaGetSymbolAddress((void**)&xol, g_xol);

    cudaFuncSetAttribute(gemm_bf16, cudaFuncAttributeMaxDynamicSharedMemorySize, GEMM_SMEM_B);
    cudaFuncSetAttribute(intra_chunk, cudaFuncAttributeMaxDynamicSharedMemorySize, IC_SMEM);

    // 0) split inputs into bf16 hi/lo
    split_f32<<<(BB * TT * DM) / 1024, 256>>>(x, xhi, xlo, BB * TT * DM);
    split_f32<<<(QKVW * DM) / 1024, 256>>>(Wqkv, wqh, wql, QKVW * DM);
    split_f32<<<(DM * DM) / 1024, 256>>>(Wout, woh, wol, DM * DM);

    // 1) qkv = x @ Wqkv^T
    gemm_bf16<<<dim3(QKVW / 128, (BB * TT) / 128), 256, GEMM_SMEM_B>>>(
        xhi, xlo, wqh, wql, qkv, BB * TT, QKVW, DM);
    // 2) chunk totals
    chunk_sums<<<dim3(NCK, NBH), 256>>>();
    // 3) exclusive prefix across chunks
    chunk_prefix<<<dim3((STSZ + 255) / 256, NBH), 256>>>();
    // 4) intra-chunk attention -> xo (bf16 hi/lo)
    intra_chunk<<<dim3(NCK, NBH), 256, IC_SMEM>>>();
    // 5) out = xo @ Wout^T
    gemm_bf16<<<dim3(DM / 128, (BB * TT) / 128), 256, GEMM_SMEM_B>>>(
        xoh, xol, woh, wol, out, BB * TT, DM, DM);
}

// round 8
// speedup vs baseline: 2.3027x; 1.0071x over previous
#include <cuda_runtime.h>
#include <cuda_bf16.h>
#include <cstdint>

// Problem constants
#define BB 2
#define TT 2048
#define DM 1024
#define NH 16
#define HS 64
#define QKVW 3072          // 3 * DM
#define CHUNK 64
#define NCK (TT / CHUNK)   // 32 chunks
#define NBH (BB * NH)      // 32 (b,h) pairs
#define STSZ (HS * HS + HS) // 4160 floats per chunk state
#define PAD 68             // smem row pitch (floats), 16B-aligned rows

// Scratch (no cudaMalloc allowed)
__device__ float g_qkv[(size_t)BB * TT * QKVW];             // 50.3 MB fp32
__device__ float g_state[(size_t)NBH * NCK * STSZ];         // 17 MB
__device__ __nv_bfloat16 g_xhi[(size_t)BB * TT * DM];       // x split
__device__ __nv_bfloat16 g_xlo[(size_t)BB * TT * DM];
__device__ __nv_bfloat16 g_wqh[(size_t)QKVW * DM];          // W_qkv split
__device__ __nv_bfloat16 g_wql[(size_t)QKVW * DM];
__device__ __nv_bfloat16 g_woh[(size_t)DM * DM];            // W_out split
__device__ __nv_bfloat16 g_wol[(size_t)DM * DM];
__device__ __nv_bfloat16 g_xoh[(size_t)BB * TT * DM];       // xo split (from intra_chunk)
__device__ __nv_bfloat16 g_xol[(size_t)BB * TT * DM];

// ===========================================================================
// Helpers
// ===========================================================================
__device__ __forceinline__ uint32_t smem_u32(const void* p) {
    uint32_t a;
    asm("{ .reg .u64 t; cvta.to.shared.u64 t, %1; cvt.u32.u64 %0, t; }"
        : "=r"(a) : "l"(p));
    return a;
}

#define CP_ASYNC16(dst, src) \
    asm volatile("cp.async.cg.shared.global [%0], [%1], 16;" :: "r"(dst), "l"(src))
#define CP_COMMIT() asm volatile("cp.async.commit_group;" ::: "memory")
#define CP_WAIT1()  asm volatile("cp.async.wait_group 1;" ::: "memory")
#define CP_WAIT0()  asm volatile("cp.async.wait_group 0;" ::: "memory")

// Split barrier: 256 "read-done" arrives + 256 syncs = 512 total arrivals.
#define BAR_ARRIVE() asm volatile("bar.arrive 1, 512;" ::: "memory")
#define BAR_SYNC()   asm volatile("bar.sync 1, 512;" ::: "memory")

__device__ __forceinline__ void ldsm_x4(uint32_t* r, uint32_t addr) {
    asm volatile("ldmatrix.sync.aligned.m8n8.x4.shared.b16 {%0,%1,%2,%3}, [%4];"
                 : "=r"(r[0]), "=r"(r[1]), "=r"(r[2]), "=r"(r[3]) : "r"(addr));
}

__device__ __forceinline__ void mma_bf16(float* c, const uint32_t* a, const uint32_t* b) {
    asm volatile(
        "mma.sync.aligned.m16n8k16.row.col.f32.bf16.bf16.f32 "
        "{%0,%1,%2,%3}, {%4,%5,%6,%7}, {%8,%9}, {%0,%1,%2,%3};"
        : "+f"(c[0]), "+f"(c[1]), "+f"(c[2]), "+f"(c[3])
        : "r"(a[0]), "r"(a[1]), "r"(a[2]), "r"(a[3]), "r"(b[0]), "r"(b[1]));
}

// split 2 floats -> bf16 hi pair + lo pair (packed u32 each)
__device__ __forceinline__ void split2(float a, float b, uint32_t& hp, uint32_t& lp) {
    __nv_bfloat162 h = __floats2bfloat162_rn(a, b);
    float2 hf = __bfloat1622float2(h);
    __nv_bfloat162 l = __floats2bfloat162_rn(a - hf.x, b - hf.y);
    hp = *(uint32_t*)&h;
    lp = *(uint32_t*)&l;
}

// ---------------------------------------------------------------------------
// Prep: elementwise fp32 -> bf16 hi/lo split (vectorized, n multiple of 4)
// ---------------------------------------------------------------------------
__global__ __launch_bounds__(256) void split_f32(const float* __restrict__ src,
                                                 __nv_bfloat16* __restrict__ hi,
                                                 __nv_bfloat16* __restrict__ lo,
                                                 int n) {
    int i = (blockIdx.x * 256 + threadIdx.x) * 4;
    if (i >= n) return;
    float4 v = *(const float4*)(src + i);
    uint32_t h0, l0, h1, l1;
    split2(v.x, v.y, h0, l0);
    split2(v.z, v.w, h1, l1);
    *(uint2*)(hi + i) = make_uint2(h0, h1);
    *(uint2*)(lo + i) = make_uint2(l0, l1);
}

// ===========================================================================
// Tensor-core NT GEMM on pre-split bf16 hi/lo inputs.
// C[m][n] = sum_k A[m][k]*B[n][k], fp32 out. CTA 128x128, BK=32, 256 thr.
// 3-stage cp.async ring, XOR-swizzled smem (64B rows), split named barrier:
// warps arrive after their ldmatrix reads (before MMA drain), so the per-chunk
// rendezvous no longer serializes on tensor-pipe drain.
// ===========================================================================
#define KT 32
#define TILE_B 8192                  // 128 rows * 64 B
#define STAGE_B (4 * TILE_B)         // Ahi Alo Bhi Blo = 32768 B
#define NSTAGE 3
#define GEMM_SMEM_B (NSTAGE * STAGE_B)  // 98304 B

__global__ __launch_bounds__(256) void gemm_bf16(const __nv_bfloat16* __restrict__ Ahi,
                                                 const __nv_bfloat16* __restrict__ Alo,
                                                 const __nv_bfloat16* __restrict__ Bhi,
                                                 const __nv_bfloat16* __restrict__ Blo,
                                                 float* __restrict__ C,
                                                 int M, int N, int K) {
    extern __shared__ char smraw[];
    const uint32_t sb = smem_u32(smraw);
    const int tid = threadIdx.x, wid = tid >> 5, lid = tid & 31;
    const int bm = blockIdx.y * 128, bn = blockIdx.x * 128;
    const int wm = (wid & 1) * 64, wn = (wid >> 1) * 32;
    const int NC = K / KT;

    const __nv_bfloat16* bases[4] = {Ahi, Alo, Bhi, Blo};

    // 2048 granules (16B) per stage; 8 per thread
#define CP_STAGE(kc, s)                                                        \
    {                                                                          \
        uint32_t stb = sb + (s) * STAGE_B;                                     \
        _Pragma("unroll")                                                      \
        for (int it = 0; it < 8; it++) {                                       \
            int cid = it * 256 + tid;                                          \
            int tile = cid >> 9;                                               \
            int rem = cid & 511;                                               \
            int r = rem >> 2;                                                  \
            int g = rem & 3;                                                   \
            int row0 = (tile < 2) ? bm : bn;                                   \
            const __nv_bfloat16* src =                                         \
                bases[tile] + (size_t)(row0 + r) * K + (kc) * KT + g * 8;      \
            uint32_t dst = stb + tile * TILE_B + r * 64 +                      \
                           (((g ^ ((r >> 1) & 3))) << 4);                      \
            CP_ASYNC16(dst, src);                                              \
        }                                                                      \
        CP_COMMIT();                                                           \
    }

    float acc[4][4][4];
#pragma unroll
    for (int mi = 0; mi < 4; mi++)
#pragma unroll
        for (int ni = 0; ni < 4; ni++)
#pragma unroll
            for (int q = 0; q < 4; q++) acc[mi][ni][q] = 0.f;

    // lane-invariant ldmatrix row/granule components
    const int a_mrow = (lid < 16 ? lid : lid - 16);
    const int a_g    = (lid < 16 ? 0 : 1);
    const int b_q = lid & 7, b_g4 = lid >> 3;
    const int b_nrow = b_q + (b_g4 >> 1) * 8;
    const int b_g    = (b_g4 & 1);

    CP_STAGE(0, 0);
    CP_STAGE(1, 1);
    BAR_ARRIVE();                      // seed the first sync window

    for (int kc = 0; kc < NC; kc++) {
        if (kc < NC - 1) { CP_WAIT1(); } else { CP_WAIT0(); }
        BAR_SYNC();                    // releases on peers' READ-done, not MMA drain
        if (kc + 2 < NC) CP_STAGE(kc + 2, (kc + 2) % NSTAGE);

        const uint32_t stage = sb + (kc % NSTAGE) * STAGE_B;
#pragma unroll
        for (int ks = 0; ks < 2; ks++) {
            uint32_t Ah[4][4], Al[4][4], Bh[4][2], Bl[4][2];
#pragma unroll
            for (int mi = 0; mi < 4; mi++) {
                int row = wm + mi * 16 + a_mrow;
                int gran = ks * 2 + a_g;
                uint32_t addr = stage + row * 64 + ((gran ^ ((row >> 1) & 3)) << 4);
                ldsm_x4(Ah[mi], addr);
                ldsm_x4(Al[mi], addr + TILE_B);
            }
#pragma unroll
            for (int nb = 0; nb < 2; nb++) {
                int row = wn + nb * 16 + b_nrow;
                int gran = ks * 2 + b_g;
                uint32_t addr = stage + 2 * TILE_B + row * 64 +
                                ((gran ^ ((row >> 1) & 3)) << 4);
                uint32_t t[4];
                ldsm_x4(t, addr);
                Bh[nb * 2][0] = t[0]; Bh[nb * 2][1] = t[1];
                Bh[nb * 2 + 1][0] = t[2]; Bh[nb * 2 + 1][1] = t[3];
                ldsm_x4(t, addr + TILE_B);
                Bl[nb * 2][0] = t[0]; Bl[nb * 2][1] = t[1];
                Bl[nb * 2 + 1][0] = t[2]; Bl[nb * 2 + 1][1] = t[3];
            }
            if (ks == 1) BAR_ARRIVE(); // all smem reads of this stage retired
#pragma unroll
            for (int mi = 0; mi < 4; mi++)
#pragma unroll
                for (int ni = 0; ni < 4; ni++) {
                    mma_bf16(acc[mi][ni], Ah[mi], Bh[ni]);
                    mma_bf16(acc[mi][ni], Ah[mi], Bl[ni]);
                    mma_bf16(acc[mi][ni], Al[mi], Bh[ni]);
                }
        }
    }

    const int erow = lid >> 2, ecol = 2 * (lid & 3);
#pragma unroll
    for (int mi = 0; mi < 4; mi++) {
#pragma unroll
        for (int ni = 0; ni < 4; ni++) {
            float* c0 = C + (size_t)(bm + wm + mi * 16 + erow) * N + bn + wn + ni * 8 + ecol;
            *(float2*)c0 = make_float2(acc[mi][ni][0], acc[mi][ni][1]);
            *(float2*)(c0 + 8 * N) = make_float2(acc[mi][ni][2], acc[mi][ni][3]);
        }
    }
}

// ---------------------------------------------------------------------------
// Pass A: per (bh, chunk) chunk totals: sumKV[c][d], sumK[c]
// ---------------------------------------------------------------------------
__global__ __launch_bounds__(256) void chunk_sums() {
    const int ck = blockIdx.x, bh = blockIdx.y;
    const int b = bh >> 4, h = bh & 15;
    __shared__ float ke[64][65];    // ke[c][t] (scalar reads)
    __shared__ float vs[64][PAD];   // vs[t][d] (float4 reads)
    const int tid = threadIdx.x;

    for (int i = tid; i < 4096; i += 256) {
        int tt = i >> 6, c = i & 63;
        const float* row = g_qkv + (size_t)(b * TT + ck * CHUNK + tt) * QKVW;
        ke[c][tt] = __expf(row[(NH + h) * HS + c]);
        vs[tt][c] = row[(2 * NH + h) * HS + c];
    }
    __syncthreads();

    const int c = tid >> 2, dg = tid & 3;
    float4 a0 = {0,0,0,0}, a1 = {0,0,0,0}, a2 = {0,0,0,0}, a3 = {0,0,0,0};
    float sk = 0.f;
    for (int t = 0; t < 64; t++) {
        float kv = ke[c][t];
        sk += kv;
        const float4* vr = (const float4*)(&vs[t][dg * 16]);
        float4 v0 = vr[0], v1 = vr[1], v2 = vr[2], v3 = vr[3];
        a0.x += kv * v0.x; a0.y += kv * v0.y; a0.z += kv * v0.z; a0.w += kv * v0.w;
        a1.x += kv * v1.x; a1.y += kv * v1.y; a1.z += kv * v1.z; a1.w += kv * v1.w;
        a2.x += kv * v2.x; a2.y += kv * v2.y; a2.z += kv * v2.z; a2.w += kv * v2.w;
        a3.x += kv * v3.x; a3.y += kv * v3.y; a3.z += kv * v3.z; a3.w += kv * v3.w;
    }
    float* st = g_state + (size_t)(bh * NCK + ck) * STSZ;
    float4* sp = (float4*)(st + c * 64 + dg * 16);
    sp[0] = a0; sp[1] = a1; sp[2] = a2; sp[3] = a3;
    if (dg == 0) st[4096 + c] = sk;
}

// ---------------------------------------------------------------------------
// Pass B: exclusive prefix over the 32 chunks
// ---------------------------------------------------------------------------
__global__ __launch_bounds__(256) void chunk_prefix() {
    const int bh = blockIdx.y;
    const int idx = blockIdx.x * 256 + threadIdx.x;
    if (idx >= STSZ) return;
    float run = 0.f;
    float* base = g_state + (size_t)bh * NCK * STSZ + idx;
    for (int ck = 0; ck < NCK; ck++) {
        float t = base[(size_t)ck * STSZ];
        base[(size_t)ck * STSZ] = run;
        run += t;
    }
}

// ---------------------------------------------------------------------------
// Pass C: intra-chunk attention; emits xo as bf16 hi/lo for GEMM2.
// Softmax + denominator phases use all 256 threads (quad-parallel).
// ---------------------------------------------------------------------------
#define IC_SMEM (4 * 64 * PAD * (int)sizeof(float))

__global__ __launch_bounds__(256) void intra_chunk() {
    extern __shared__ float sm[];
    float* qn  = sm;                 // [t][c]
    float* keT = sm + 64 * PAD;      // [c][t]
    float* vsm = sm + 2 * 64 * PAD;  // [t][d]
    float* SA  = sm + 3 * 64 * PAD;  // S0 then A
    __shared__ float den0[64];

    const int ck = blockIdx.x, bh = blockIdx.y;
    const int b = bh >> 4, h = bh & 15;
    const int tid = threadIdx.x;
    const float* st = g_state + (size_t)(bh * NCK + ck) * STSZ;

    for (int i = tid; i < 4096; i += 256) {
        int tt = i >> 6, c = i & 63;
        const float* row = g_qkv + (size_t)(b * TT + ck * CHUNK + tt) * QKVW;
        qn[tt * PAD + c]  = row[h * HS + c];
        keT[c * PAD + tt] = __expf(row[(NH + h) * HS + c]);
        vsm[tt * PAD + c] = row[(2 * NH + h) * HS + c];
        SA[tt * PAD + c]  = st[i];
    }
    if (tid < 64) den0[tid] = st[4096 + tid];
    __syncthreads();

    // --- softmax over head dim per row t, 4 lanes per row ---
    {
        const int tq = tid >> 2, qd = tid & 3;
        float* qseg = qn + tq * PAD + qd * 16;
        float v[16];
#pragma unroll
        for (int q = 0; q < 4; q++) {
            float4 f = ((const float4*)qseg)[q];
            v[4*q] = f.x; v[4*q+1] = f.y; v[4*q+2] = f.z; v[4*q+3] = f.w;
        }
        float m = v[0];
#pragma unroll
        for (int j = 1; j < 16; j++) m = fmaxf(m, v[j]);
        m = fmaxf(m, __shfl_xor_sync(0xFFFFFFFFu, m, 1));
        m = fmaxf(m, __shfl_xor_sync(0xFFFFFFFFu, m, 2));
        float s = 0.f;
#pragma unroll
        for (int j = 0; j < 16; j++) { v[j] = __expf(v[j] - m); s += v[j]; }
        s += __shfl_xor_sync(0xFFFFFFFFu, s, 1);
        s += __shfl_xor_sync(0xFFFFFFFFu, s, 2);
        float inv = 0.125f / s;
#pragma unroll
        for (int q = 0; q < 4; q++)
            ((float4*)qseg)[q] = make_float4(v[4*q] * inv, v[4*q+1] * inv,
                                             v[4*q+2] * inv, v[4*q+3] * inv);
    }
    __syncthreads();

    // --- per-column running denominator folded into qn; 4 lanes per column ---
    {
        const int c = tid >> 2, sg = tid & 3;
        const float4* krow = (const float4*)(keT + c * PAD + sg * 16);
        float cum[16];
        float s = 0.f;
#pragma unroll
        for (int q = 0; q < 4; q++) {
            float4 f = krow[q];
            s += f.x; cum[4*q]   = s;
            s += f.y; cum[4*q+1] = s;
            s += f.z; cum[4*q+2] = s;
            s += f.w; cum[4*q+3] = s;
        }
        float x = s;
        float u1 = __shfl_up_sync(0xFFFFFFFFu, x, 1); if (sg >= 1) x += u1;
        float u2 = __shfl_up_sync(0xFFFFFFFFu, x, 2); if (sg >= 2) x += u2;
        float base = den0[c] + (x - s);   // exclusive prefix of earlier segments
#pragma unroll
        for (int j = 0; j < 16; j++) {
            int t = sg * 16 + j;
            qn[t * PAD + c] = qn[t * PAD + c] / (base + cum[j] + 1e-9f);
        }
    }
    __syncthreads();

    const int t = tid >> 2, dg = tid & 3;
    const float* qrow = qn + t * PAD;

    float acc[16], a[16];
#pragma unroll
    for (int j = 0; j < 16; j++) { acc[j] = 0.f; a[j] = 0.f; }

    for (int c = 0; c < 64; c++) {
        float qv = qrow[c];
        const float4* srow = (const float4*)(SA + c * PAD + dg * 16);
        const float4* krow = (const float4*)(keT + c * PAD + dg * 16);
#pragma unroll
        for (int q = 0; q < 4; q++) {
            float4 sv = srow[q], kv = krow[q];
            acc[4 * q + 0] += qv * sv.x; acc[4 * q + 1] += qv * sv.y;
            acc[4 * q + 2] += qv * sv.z; acc[4 * q + 3] += qv * sv.w;
            a[4 * q + 0] += qv * kv.x; a[4 * q + 1] += qv * kv.y;
            a[4 * q + 2] += qv * kv.z; a[4 * q + 3] += qv * kv.w;
        }
    }
    __syncthreads();
    {
        float4* arow = (float4*)(SA + t * PAD + dg * 16);
#pragma unroll
        for (int q = 0; q < 4; q++)
            arow[q] = make_float4(a[4 * q], a[4 * q + 1], a[4 * q + 2], a[4 * q + 3]);
    }
    __syncthreads();

    const float* Arow = SA + t * PAD;
    for (int s = 0; s <= t; s++) {
        float av = Arow[s];
        const float4* vr = (const float4*)(vsm + s * PAD + dg * 16);
#pragma unroll
        for (int q = 0; q < 4; q++) {
            float4 vv = vr[q];
            acc[4 * q + 0] += av * vv.x; acc[4 * q + 1] += av * vv.y;
            acc[4 * q + 2] += av * vv.z; acc[4 * q + 3] += av * vv.w;
        }
    }

    size_t off = (size_t)(b * TT + ck * CHUNK + t) * DM + h * HS + dg * 16;
    uint32_t hp[8], lp[8];
#pragma unroll
    for (int j = 0; j < 8; j++) split2(acc[2 * j], acc[2 * j + 1], hp[j], lp[j]);
    uint4* ho = (uint4*)(g_xoh + off);
    uint4* lo = (uint4*)(g_xol + off);
    ho[0] = make_uint4(hp[0], hp[1], hp[2], hp[3]);
    ho[1] = make_uint4(hp[4], hp[5], hp[6], hp[7]);
    lo[0] = make_uint4(lp[0], lp[1], lp[2], lp[3]);
    lo[1] = make_uint4(lp[4], lp[5], lp[6], lp[7]);
}

// ---------------------------------------------------------------------------
extern "C" void kernel_launch(void* const* d_in, const int* in_sizes, int n_in,
                              void* d_out, int out_size) {
    const float* x    = (const float*)d_in[0];   // (2, 2048, 1024)
    const float* Wqkv = (const float*)d_in[1];   // (3072, 1024)
    const float* Wout = (const float*)d_in[2];   // (1024, 1024)
    float* out = (float*)d_out;                  // (2, 2048, 1024)

    float* qkv;
    cudaGetSymbolAddress((void**)&qkv, g_qkv);
    __nv_bfloat16 *xhi, *xlo, *wqh, *wql, *woh, *wol, *xoh, *xol;
    cudaGetSymbolAddress((void**)&xhi, g_xhi);
    cudaGetSymbolAddress((void**)&xlo, g_xlo);
    cudaGetSymbolAddress((void**)&wqh, g_wqh);
    cudaGetSymbolAddress((void**)&wql, g_wql);
    cudaGetSymbolAddress((void**)&woh, g_woh);
    cudaGetSymbolAddress((void**)&wol, g_wol);
    cudaGetSymbolAddress((void**)&xoh, g_xoh);
    cudaGetSymbolAddress((void**)&xol, g_xol);

    cudaFuncSetAttribute(gemm_bf16, cudaFuncAttributeMaxDynamicSharedMemorySize, GEMM_SMEM_B);
    cudaFuncSetAttribute(intra_chunk, cudaFuncAttributeMaxDynamicSharedMemorySize, IC_SMEM);

    // 0) split inputs into bf16 hi/lo
    split_f32<<<(BB * TT * DM) / 1024, 256>>>(x, xhi, xlo, BB * TT * DM);
    split_f32<<<(QKVW * DM) / 1024, 256>>>(Wqkv, wqh, wql, QKVW * DM);
    split_f32<<<(DM * DM) / 1024, 256>>>(Wout, woh, wol, DM * DM);

    // 1) qkv = x @ Wqkv^T
    gemm_bf16<<<dim3(QKVW / 128, (BB * TT) / 128), 256, GEMM_SMEM_B>>>(
        xhi, xlo, wqh, wql, qkv, BB * TT, QKVW, DM);
    // 2) chunk totals
    chunk_sums<<<dim3(NCK, NBH), 256>>>();
    // 3) exclusive prefix across chunks
    chunk_prefix<<<dim3((STSZ + 255) / 256, NBH), 256>>>();
    // 4) intra-chunk attention -> xo (bf16 hi/lo)
    intra_chunk<<<dim3(NCK, NBH), 256, IC_SMEM>>>();
    // 5) out = xo @ Wout^T
    gemm_bf16<<<dim3(DM / 128, (BB * TT) / 128), 256, GEMM_SMEM_B>>>(
        xoh, xol, woh, wol, out, BB * TT, DM, DM);
}

// round 9
// speedup vs baseline: 3.1716x; 1.3773x over previous
#include <cuda_runtime.h>
#include <cuda_bf16.h>
#include <cstdint>

// Problem constants
#define BB 2
#define TT 2048
#define DM 1024
#define NH 16
#define HS 64
#define QKVW 3072          // 3 * DM
#define CHUNK 64
#define NCK (TT / CHUNK)   // 32 chunks
#define NBH (BB * NH)      // 32 (b,h) pairs
#define STSZ (HS * HS + HS) // 4160 floats per chunk state
#define PAD 68             // f32 smem row pitch
#define P72 72             // bf16 smem row pitch (144 B, odd granule count -> ldmatrix conflict-free)

// Scratch (no cudaMalloc allowed)
__device__ float g_qkv[(size_t)BB * TT * QKVW];             // 50.3 MB fp32
__device__ float g_state[(size_t)NBH * NCK * STSZ];         // 17 MB
__device__ __nv_bfloat16 g_xhi[(size_t)BB * TT * DM];
__device__ __nv_bfloat16 g_xlo[(size_t)BB * TT * DM];
__device__ __nv_bfloat16 g_wqh[(size_t)QKVW * DM];
__device__ __nv_bfloat16 g_wql[(size_t)QKVW * DM];
__device__ __nv_bfloat16 g_woh[(size_t)DM * DM];
__device__ __nv_bfloat16 g_wol[(size_t)DM * DM];
__device__ __nv_bfloat16 g_xoh[(size_t)BB * TT * DM];
__device__ __nv_bfloat16 g_xol[(size_t)BB * TT * DM];

// ===========================================================================
// Helpers
// ===========================================================================
__device__ __forceinline__ uint32_t smem_u32(const void* p) {
    uint32_t a;
    asm("{ .reg .u64 t; cvta.to.shared.u64 t, %1; cvt.u32.u64 %0, t; }"
        : "=r"(a) : "l"(p));
    return a;
}

#define CP_ASYNC16(dst, src) \
    asm volatile("cp.async.cg.shared.global [%0], [%1], 16;" :: "r"(dst), "l"(src))
#define CP_COMMIT() asm volatile("cp.async.commit_group;" ::: "memory")
#define CP_WAIT1()  asm volatile("cp.async.wait_group 1;" ::: "memory")
#define CP_WAIT0()  asm volatile("cp.async.wait_group 0;" ::: "memory")

#define BAR_ARRIVE() asm volatile("bar.arrive 1, 512;" ::: "memory")
#define BAR_SYNC()   asm volatile("bar.sync 1, 512;" ::: "memory")

__device__ __forceinline__ void ldsm_x4(uint32_t* r, uint32_t addr) {
    asm volatile("ldmatrix.sync.aligned.m8n8.x4.shared.b16 {%0,%1,%2,%3}, [%4];"
                 : "=r"(r[0]), "=r"(r[1]), "=r"(r[2]), "=r"(r[3]) : "r"(addr));
}

__device__ __forceinline__ void mma_bf16(float* c, const uint32_t* a, const uint32_t* b) {
    asm volatile(
        "mma.sync.aligned.m16n8k16.row.col.f32.bf16.bf16.f32 "
        "{%0,%1,%2,%3}, {%4,%5,%6,%7}, {%8,%9}, {%0,%1,%2,%3};"
        : "+f"(c[0]), "+f"(c[1]), "+f"(c[2]), "+f"(c[3])
        : "r"(a[0]), "r"(a[1]), "r"(a[2]), "r"(a[3]), "r"(b[0]), "r"(b[1]));
}

__device__ __forceinline__ void split2(float a, float b, uint32_t& hp, uint32_t& lp) {
    __nv_bfloat162 h = __floats2bfloat162_rn(a, b);
    float2 hf = __bfloat1622float2(h);
    __nv_bfloat162 l = __floats2bfloat162_rn(a - hf.x, b - hf.y);
    hp = *(uint32_t*)&h;
    lp = *(uint32_t*)&l;
}

__device__ __forceinline__ void split1(float v, __nv_bfloat16& h, __nv_bfloat16& l) {
    h = __float2bfloat16(v);
    l = __float2bfloat16(v - __bfloat162float(h));
}

// Generic split-bf16 MMA tile on pitch-72 bf16 smem operands (NT, K=64).
// A tile: MI*16 rows at wm;  B tile: NB*16 rows at wn (2 n8-frags per 16 rows).
template<int MI, int NB>
__device__ __forceinline__ void mm_tile(uint32_t Ahb, uint32_t Alb,
                                        uint32_t Bhb, uint32_t Blb,
                                        int wm, int wn,
                                        int a_mrow, int a_g, int b_nrow, int b_g,
                                        float acc[MI][2 * NB][4]) {
#pragma unroll
    for (int ks = 0; ks < 4; ks++) {
        uint32_t Ah[MI][4], Al[MI][4], Bh[2 * NB][2], Bl[2 * NB][2];
#pragma unroll
        for (int mi = 0; mi < MI; mi++) {
            uint32_t ao = (uint32_t)((wm + mi * 16 + a_mrow) * (P72 * 2) + (ks * 2 + a_g) * 16);
            ldsm_x4(Ah[mi], Ahb + ao);
            ldsm_x4(Al[mi], Alb + ao);
        }
#pragma unroll
        for (int nb = 0; nb < NB; nb++) {
            uint32_t bo = (uint32_t)((wn + nb * 16 + b_nrow) * (P72 * 2) + (ks * 2 + b_g) * 16);
            uint32_t t0[4], t1[4];
            ldsm_x4(t0, Bhb + bo);
            ldsm_x4(t1, Blb + bo);
            Bh[nb * 2][0] = t0[0]; Bh[nb * 2][1] = t0[1];
            Bh[nb * 2 + 1][0] = t0[2]; Bh[nb * 2 + 1][1] = t0[3];
            Bl[nb * 2][0] = t1[0]; Bl[nb * 2][1] = t1[1];
            Bl[nb * 2 + 1][0] = t1[2]; Bl[nb * 2 + 1][1] = t1[3];
        }
#pragma unroll
        for (int mi = 0; mi < MI; mi++)
#pragma unroll
            for (int ni = 0; ni < 2 * NB; ni++) {
                mma_bf16(acc[mi][ni], Ah[mi], Bh[ni]);
                mma_bf16(acc[mi][ni], Ah[mi], Bl[ni]);
                mma_bf16(acc[mi][ni], Al[mi], Bh[ni]);
            }
    }
}

// ---------------------------------------------------------------------------
// Prep: elementwise fp32 -> bf16 hi/lo split
// ---------------------------------------------------------------------------
__global__ __launch_bounds__(256) void split_f32(const float* __restrict__ src,
                                                 __nv_bfloat16* __restrict__ hi,
                                                 __nv_bfloat16* __restrict__ lo,
                                                 int n) {
    int i = (blockIdx.x * 256 + threadIdx.x) * 4;
    if (i >= n) return;
    float4 v = *(const float4*)(src + i);
    uint32_t h0, l0, h1, l1;
    split2(v.x, v.y, h0, l0);
    split2(v.z, v.w, h1, l1);
    *(uint2*)(hi + i) = make_uint2(h0, h1);
    *(uint2*)(lo + i) = make_uint2(l0, l1);
}

// ===========================================================================
// Tensor-core NT GEMM (unchanged from the 575us passing version)
// ===========================================================================
#define KT 32
#define TILE_B 8192
#define STAGE_B (4 * TILE_B)
#define NSTAGE 3
#define GEMM_SMEM_B (NSTAGE * STAGE_B)

__global__ __launch_bounds__(256) void gemm_bf16(const __nv_bfloat16* __restrict__ Ahi,
                                                 const __nv_bfloat16* __restrict__ Alo,
                                                 const __nv_bfloat16* __restrict__ Bhi,
                                                 const __nv_bfloat16* __restrict__ Blo,
                                                 float* __restrict__ C,
                                                 int M, int N, int K) {
    extern __shared__ char smraw[];
    const uint32_t sb = smem_u32(smraw);
    const int tid = threadIdx.x, wid = tid >> 5, lid = tid & 31;
    const int bm = blockIdx.y * 128, bn = blockIdx.x * 128;
    const int wm = (wid & 1) * 64, wn = (wid >> 1) * 32;
    const int NC = K / KT;

    const __nv_bfloat16* bases[4] = {Ahi, Alo, Bhi, Blo};

#define CP_STAGE(kc, s)                                                        \
    {                                                                          \
        uint32_t stb = sb + (s) * STAGE_B;                                     \
        _Pragma("unroll")                                                      \
        for (int it = 0; it < 8; it++) {                                       \
            int cid = it * 256 + tid;                                          \
            int tile = cid >> 9;                                               \
            int rem = cid & 511;                                               \
            int r = rem >> 2;                                                  \
            int g = rem & 3;                                                   \
            int row0 = (tile < 2) ? bm : bn;                                   \
            const __nv_bfloat16* src =                                         \
                bases[tile] + (size_t)(row0 + r) * K + (kc) * KT + g * 8;      \
            uint32_t dst = stb + tile * TILE_B + r * 64 +                      \
                           (((g ^ ((r >> 1) & 3))) << 4);                      \
            CP_ASYNC16(dst, src);                                              \
        }                                                                      \
        CP_COMMIT();                                                           \
    }

    float acc[4][4][4];
#pragma unroll
    for (int mi = 0; mi < 4; mi++)
#pragma unroll
        for (int ni = 0; ni < 4; ni++)
#pragma unroll
            for (int q = 0; q < 4; q++) acc[mi][ni][q] = 0.f;

    const int a_mrow = (lid < 16 ? lid : lid - 16);
    const int a_g    = (lid < 16 ? 0 : 1);
    const int b_q = lid & 7, b_g4 = lid >> 3;
    const int b_nrow = b_q + (b_g4 >> 1) * 8;
    const int b_g    = (b_g4 & 1);

    CP_STAGE(0, 0);
    CP_STAGE(1, 1);
    BAR_ARRIVE();

    for (int kc = 0; kc < NC; kc++) {
        if (kc < NC - 1) { CP_WAIT1(); } else { CP_WAIT0(); }
        BAR_SYNC();
        if (kc + 2 < NC) CP_STAGE(kc + 2, (kc + 2) % NSTAGE);

        const uint32_t stage = sb + (kc % NSTAGE) * STAGE_B;
#pragma unroll
        for (int ks = 0; ks < 2; ks++) {
            uint32_t Ah[4][4], Al[4][4], Bh[4][2], Bl[4][2];
#pragma unroll
            for (int mi = 0; mi < 4; mi++) {
                int row = wm + mi * 16 + a_mrow;
                int gran = ks * 2 + a_g;
                uint32_t addr = stage + row * 64 + ((gran ^ ((row >> 1) & 3)) << 4);
                ldsm_x4(Ah[mi], addr);
                ldsm_x4(Al[mi], addr + TILE_B);
            }
#pragma unroll
            for (int nb = 0; nb < 2; nb++) {
                int row = wn + nb * 16 + b_nrow;
                int gran = ks * 2 + b_g;
                uint32_t addr = stage + 2 * TILE_B + row * 64 +
                                ((gran ^ ((row >> 1) & 3)) << 4);
                uint32_t t[4];
                ldsm_x4(t, addr);
                Bh[nb * 2][0] = t[0]; Bh[nb * 2][1] = t[1];
                Bh[nb * 2 + 1][0] = t[2]; Bh[nb * 2 + 1][1] = t[3];
                ldsm_x4(t, addr + TILE_B);
                Bl[nb * 2][0] = t[0]; Bl[nb * 2][1] = t[1];
                Bl[nb * 2 + 1][0] = t[2]; Bl[nb * 2 + 1][1] = t[3];
            }
            if (ks == 1) BAR_ARRIVE();
#pragma unroll
            for (int mi = 0; mi < 4; mi++)
#pragma unroll
                for (int ni = 0; ni < 4; ni++) {
                    mma_bf16(acc[mi][ni], Ah[mi], Bh[ni]);
                    mma_bf16(acc[mi][ni], Ah[mi], Bl[ni]);
                    mma_bf16(acc[mi][ni], Al[mi], Bh[ni]);
                }
        }
    }

    const int erow = lid >> 2, ecol = 2 * (lid & 3);
#pragma unroll
    for (int mi = 0; mi < 4; mi++) {
#pragma unroll
        for (int ni = 0; ni < 4; ni++) {
            float* c0 = C + (size_t)(bm + wm + mi * 16 + erow) * N + bn + wn + ni * 8 + ecol;
            *(float2*)c0 = make_float2(acc[mi][ni][0], acc[mi][ni][1]);
            *(float2*)(c0 + 8 * N) = make_float2(acc[mi][ni][2], acc[mi][ni][3]);
        }
    }
}

// ---------------------------------------------------------------------------
// Pass A (tensor-core): S_c[c][d] = sum_t exp(k[t,c]) * v[t,d]; sumK[c].
// A = kexp^T [c][t], B = V^T [d][t], both pitch-72 bf16 hi/lo in smem.
// ---------------------------------------------------------------------------
#define CS_TILE (64 * P72 * 2)   // 9216 B per bf16 array

__global__ __launch_bounds__(256) void chunk_sums_tc() {
    __shared__ char sm[4 * CS_TILE];
    const uint32_t sb = smem_u32(sm);
    __nv_bfloat16* Ah = (__nv_bfloat16*)sm;
    __nv_bfloat16* Al = (__nv_bfloat16*)(sm + CS_TILE);
    __nv_bfloat16* Bh = (__nv_bfloat16*)(sm + 2 * CS_TILE);
    __nv_bfloat16* Bl = (__nv_bfloat16*)(sm + 3 * CS_TILE);

    const int ck = blockIdx.x, bh = blockIdx.y;
    const int b = bh >> 4, h = bh & 15;
    const int tid = threadIdx.x;

    for (int i = tid; i < 4096; i += 256) {
        int tt = i >> 6, c = i & 63;
        const float* row = g_qkv + (size_t)(b * TT + ck * CHUNK + tt) * QKVW;
        __nv_bfloat16 hh, ll;
        float e = __expf(row[(NH + h) * HS + c]);
        split1(e, hh, ll);
        Ah[c * P72 + tt] = hh; Al[c * P72 + tt] = ll;
        float v = row[(2 * NH + h) * HS + c];
        split1(v, hh, ll);
        Bh[c * P72 + tt] = hh; Bl[c * P72 + tt] = ll;
    }
    __syncthreads();

    const int wid = tid >> 5, lid = tid & 31;
    const int a_mrow = (lid < 16 ? lid : lid - 16), a_g = (lid < 16 ? 0 : 1);
    const int b_q = lid & 7, b_g4 = lid >> 3;
    const int b_nrow = b_q + (b_g4 >> 1) * 8, b_g = b_g4 & 1;
    const int wm = (wid & 1) * 32, wn = (wid >> 1) * 16;

    float acc[2][2][4];
#pragma unroll
    for (int mi = 0; mi < 2; mi++)
#pragma unroll
        for (int ni = 0; ni < 2; ni++)
#pragma unroll
            for (int q = 0; q < 4; q++) acc[mi][ni][q] = 0.f;

    mm_tile<2, 1>(sb, sb + CS_TILE, sb + 2 * CS_TILE, sb + 3 * CS_TILE,
                  wm, wn, a_mrow, a_g, b_nrow, b_g, acc);

    float* st = g_state + (size_t)(bh * NCK + ck) * STSZ;
    const int erow = lid >> 2, ecol = 2 * (lid & 3);
#pragma unroll
    for (int mi = 0; mi < 2; mi++)
#pragma unroll
        for (int ni = 0; ni < 2; ni++) {
            int r = wm + mi * 16 + erow, cc = wn + ni * 8 + ecol;
            *(float2*)&st[r * 64 + cc] = make_float2(acc[mi][ni][0], acc[mi][ni][1]);
            *(float2*)&st[(r + 8) * 64 + cc] = make_float2(acc[mi][ni][2], acc[mi][ni][3]);
        }

    if (tid < 64) {   // sumK[c] from hi+lo (exact reconstruction to 2^-18)
        float s = 0.f;
        for (int t2 = 0; t2 < 64; t2++)
            s += __bfloat162float(Ah[tid * P72 + t2]) + __bfloat162float(Al[tid * P72 + t2]);
        st[4096 + tid] = s;
    }
}

// ---------------------------------------------------------------------------
// Pass B: exclusive prefix over the 32 chunks (unchanged)
// ---------------------------------------------------------------------------
__global__ __launch_bounds__(256) void chunk_prefix() {
    const int bh = blockIdx.y;
    const int idx = blockIdx.x * 256 + threadIdx.x;
    if (idx >= STSZ) return;
    float run = 0.f;
    float* base = g_state + (size_t)bh * NCK * STSZ + idx;
    for (int ck = 0; ck < NCK; ck++) {
        float t = base[(size_t)ck * STSZ];
        base[(size_t)ck * STSZ] = run;
        run += t;
    }
}

// ---------------------------------------------------------------------------
// Pass C (tensor-core): softmax + denominators (SIMT), then
//   QS = qn @ S0^T-as-B (warps 0-3)  ||  A = qn @ kexp^T (warps 4-7),
//   mask A causally, AV = A @ V (all warps), xo = QS + AV -> bf16 hi/lo.
// Dynamic smem layout (bytes):
//   R1  f32 [64][68]   q -> qn -> xo_acc        0     .. 17408
//   R2  qn  hi/lo [t][c] pitch72                17408 / 26624
//   R3  kexp hi/lo [s][c] pitch72               35840 / 45056
//   R4  S0^T hi/lo [d][c] pitch72, reused for A [t][s]   54272 / 63488
//   R5  V^T hi/lo [d][s] pitch72                72704 / 81920   (total 91136)
// ---------------------------------------------------------------------------
#define IC2_SMEM 91136

__global__ __launch_bounds__(256) void intra_tc() {
    extern __shared__ char sm[];
    float* R1f = (float*)sm;
    const uint32_t sb = smem_u32(sm);
    const uint32_t R2h = sb + 17408, R2l = sb + 26624;
    const uint32_t R3h = sb + 35840, R3l = sb + 45056;
    const uint32_t R4h = sb + 54272, R4l = sb + 63488;
    const uint32_t R5h = sb + 72704, R5l = sb + 81920;
    __nv_bfloat16* pR2h = (__nv_bfloat16*)(sm + 17408);
    __nv_bfloat16* pR2l = (__nv_bfloat16*)(sm + 26624);
    __nv_bfloat16* pR3h = (__nv_bfloat16*)(sm + 35840);
    __nv_bfloat16* pR3l = (__nv_bfloat16*)(sm + 45056);
    __nv_bfloat16* pR4h = (__nv_bfloat16*)(sm + 54272);
    __nv_bfloat16* pR4l = (__nv_bfloat16*)(sm + 63488);
    __nv_bfloat16* pR5h = (__nv_bfloat16*)(sm + 72704);
    __nv_bfloat16* pR5l = (__nv_bfloat16*)(sm + 81920);
    __shared__ float den0[64];

    const int ck = blockIdx.x, bh = blockIdx.y;
    const int b = bh >> 4, h = bh & 15;
    const int tid = threadIdx.x;
    const float* st = g_state + (size_t)(bh * NCK + ck) * STSZ;

    // Phase 1: loads (+ exp, splits, transposes)
    for (int i = tid; i < 4096; i += 256) {
        int tt = i >> 6, c = i & 63;
        const float* row = g_qkv + (size_t)(b * TT + ck * CHUNK + tt) * QKVW;
        R1f[tt * PAD + c] = row[h * HS + c];
        __nv_bfloat16 hh, ll;
        float e = __expf(row[(NH + h) * HS + c]);
        split1(e, hh, ll);
        pR3h[tt * P72 + c] = hh; pR3l[tt * P72 + c] = ll;       // kexp [s][c]
        float v = row[(2 * NH + h) * HS + c];
        split1(v, hh, ll);
        pR5h[c * P72 + tt] = hh; pR5l[c * P72 + tt] = ll;       // V^T [d][s]
        split1(st[i], hh, ll);                                   // i = cS*64 + d
        pR4h[(i & 63) * P72 + (i >> 6)] = hh;                    // S0^T [d][c]
        pR4l[(i & 63) * P72 + (i >> 6)] = ll;
    }
    if (tid < 64) den0[tid] = st[4096 + tid];
    __syncthreads();

    // Phase 2: softmax over head dim per row t (4 lanes/row)
    {
        const int tq = tid >> 2, qd = tid & 3;
        float* qseg = R1f + tq * PAD + qd * 16;
        float v[16];
#pragma unroll
        for (int q = 0; q < 4; q++) {
            float4 f = ((const float4*)qseg)[q];
            v[4*q] = f.x; v[4*q+1] = f.y; v[4*q+2] = f.z; v[4*q+3] = f.w;
        }
        float m = v[0];
#pragma unroll
        for (int j = 1; j < 16; j++) m = fmaxf(m, v[j]);
        m = fmaxf(m, __shfl_xor_sync(0xFFFFFFFFu, m, 1));
        m = fmaxf(m, __shfl_xor_sync(0xFFFFFFFFu, m, 2));
        float s = 0.f;
#pragma unroll
        for (int j = 0; j < 16; j++) { v[j] = __expf(v[j] - m); s += v[j]; }
        s += __shfl_xor_sync(0xFFFFFFFFu, s, 1);
        s += __shfl_xor_sync(0xFFFFFFFFu, s, 2);
        float inv = 0.125f / s;
#pragma unroll
        for (int q = 0; q < 4; q++)
            ((float4*)qseg)[q] = make_float4(v[4*q] * inv, v[4*q+1] * inv,
                                             v[4*q+2] * inv, v[4*q+3] * inv);
    }
    __syncthreads();

    // Phase 3: per-column denominator cumsum (hi+lo reconstruct), fold into qn
    {
        const int c = tid >> 2, sg = tid & 3;
        float cum[16];
        float s = 0.f;
#pragma unroll
        for (int j = 0; j < 16; j++) {
            int t2 = sg * 16 + j;
            s += __bfloat162float(pR3h[t2 * P72 + c]) + __bfloat162float(pR3l[t2 * P72 + c]);
            cum[j] = s;
        }
        float x = s;
        float u1 = __shfl_up_sync(0xFFFFFFFFu, x, 1); if (sg >= 1) x += u1;
        float u2 = __shfl_up_sync(0xFFFFFFFFu, x, 2); if (sg >= 2) x += u2;
        float base = den0[c] + (x - s);
#pragma unroll
        for (int j = 0; j < 16; j++) {
            int t2 = sg * 16 + j;
            R1f[t2 * PAD + c] = R1f[t2 * PAD + c] / (base + cum[j] + 1e-9f);
        }
    }
    __syncthreads();

    // Phase 4: split qn f32 -> R2 hi/lo
    for (int i = tid; i < 4096; i += 256) {
        int t2 = i >> 6, c = i & 63;
        __nv_bfloat16 hh, ll;
        split1(R1f[t2 * PAD + c], hh, ll);
        pR2h[t2 * P72 + c] = hh; pR2l[t2 * P72 + c] = ll;
    }
    __syncthreads();

    const int wid = tid >> 5, lid = tid & 31;
    const int a_mrow = (lid < 16 ? lid : lid - 16), a_g = (lid < 16 ? 0 : 1);
    const int b_q = lid & 7, b_g4 = lid >> 3;
    const int b_nrow = b_q + (b_g4 >> 1) * 8, b_g = b_g4 & 1;
    const int erow = lid >> 2, ecol = 2 * (lid & 3);

    // Phase 5: QS (warps 0-3) || QK (warps 4-7)
    float accA[2][4][4];   // QK result (warps 4-7) must survive the sync
    if (wid < 4) {
        float accS[2][4][4];
#pragma unroll
        for (int mi = 0; mi < 2; mi++)
#pragma unroll
            for (int ni = 0; ni < 4; ni++)
#pragma unroll
                for (int q = 0; q < 4; q++) accS[mi][ni][q] = 0.f;
        int wm = (wid & 1) * 32, wn = (wid >> 1) * 32;
        mm_tile<2, 2>(R2h, R2l, R4h, R4l, wm, wn, a_mrow, a_g, b_nrow, b_g, accS);
        // epilogue: xo_acc (R1f reuse; qn f32 is dead)
#pragma unroll
        for (int mi = 0; mi < 2; mi++)
#pragma unroll
            for (int ni = 0; ni < 4; ni++) {
                int r = wm + mi * 16 + erow, d = wn + ni * 8 + ecol;
                *(float2*)&R1f[r * PAD + d] = make_float2(accS[mi][ni][0], accS[mi][ni][1]);
                *(float2*)&R1f[(r + 8) * PAD + d] = make_float2(accS[mi][ni][2], accS[mi][ni][3]);
            }
    } else {
#pragma unroll
        for (int mi = 0; mi < 2; mi++)
#pragma unroll
            for (int ni = 0; ni < 4; ni++)
#pragma unroll
                for (int q = 0; q < 4; q++) accA[mi][ni][q] = 0.f;
        int w4 = wid - 4;
        int wm = (w4 & 1) * 32, wn = (w4 >> 1) * 32;
        mm_tile<2, 2>(R2h, R2l, R3h, R3l, wm, wn, a_mrow, a_g, b_nrow, b_g, accA);
    }
    __syncthreads();   // QS done reading R4 (S0^T); safe to overwrite with A

    // Phase 5b: warps 4-7 mask A causally (s <= t) and write bf16 hi/lo to R4
    if (wid >= 4) {
        int w4 = wid - 4;
        int wm = (w4 & 1) * 32, wn = (w4 >> 1) * 32;
#pragma unroll
        for (int mi = 0; mi < 2; mi++)
#pragma unroll
            for (int ni = 0; ni < 4; ni++) {
                int r0 = wm + mi * 16 + erow, s0 = wn + ni * 8 + ecol;
                float v0 = (s0 <= r0) ? accA[mi][ni][0] : 0.f;
                float v1 = (s0 + 1 <= r0) ? accA[mi][ni][1] : 0.f;
                uint32_t hp, lp;
                split2(v0, v1, hp, lp);
                *(uint32_t*)&pR4h[r0 * P72 + s0] = hp;
                *(uint32_t*)&pR4l[r0 * P72 + s0] = lp;
                int r2 = r0 + 8;
                float v2 = (s0 <= r2) ? accA[mi][ni][2] : 0.f;
                float v3 = (s0 + 1 <= r2) ? accA[mi][ni][3] : 0.f;
                split2(v2, v3, hp, lp);
                *(uint32_t*)&pR4h[r2 * P72 + s0] = hp;
                *(uint32_t*)&pR4l[r2 * P72 + s0] = lp;
            }
    }
    __syncthreads();

    // Phase 6: AV (all 8 warps, 16x32 tiles), add xo_acc, split, store
    {
        float accV[1][4][4];
#pragma unroll
        for (int ni = 0; ni < 4; ni++)
#pragma unroll
            for (int q = 0; q < 4; q++) accV[0][ni][q] = 0.f;
        int wm = (wid & 3) * 16, wn = (wid >> 2) * 32;
        mm_tile<1, 2>(R4h, R4l, R5h, R5l, wm, wn, a_mrow, a_g, b_nrow, b_g, accV);
#pragma unroll
        for (int ni = 0; ni < 4; ni++) {
            int r = wm + erow, d = wn + ni * 8 + ecol;
            uint32_t hp, lp;
            float x0 = accV[0][ni][0] + R1f[r * PAD + d];
            float x1 = accV[0][ni][1] + R1f[r * PAD + d + 1];
            split2(x0, x1, hp, lp);
            size_t g0 = (size_t)(b * TT + ck * CHUNK + r) * DM + h * HS + d;
            *(uint32_t*)&g_xoh[g0] = hp;
            *(uint32_t*)&g_xol[g0] = lp;
            int r2 = r + 8;
            float x2 = accV[0][ni][2] + R1f[r2 * PAD + d];
            float x3 = accV[0][ni][3] + R1f[r2 * PAD + d + 1];
            split2(x2, x3, hp, lp);
            size_t g2 = (size_t)(b * TT + ck * CHUNK + r2) * DM + h * HS + d;
            *(uint32_t*)&g_xoh[g2] = hp;
            *(uint32_t*)&g_xol[g2] = lp;
        }
    }
}

// ---------------------------------------------------------------------------
extern "C" void kernel_launch(void* const* d_in, const int* in_sizes, int n_in,
                              void* d_out, int out_size) {
    const float* x    = (const float*)d_in[0];
    const float* Wqkv = (const float*)d_in[1];
    const float* Wout = (const float*)d_in[2];
    float* out = (float*)d_out;

    float* qkv;
    cudaGetSymbolAddress((void**)&qkv, g_qkv);
    __nv_bfloat16 *xhi, *xlo, *wqh, *wql, *woh, *wol, *xoh, *xol;
    cudaGetSymbolAddress((void**)&xhi, g_xhi);
    cudaGetSymbolAddress((void**)&xlo, g_xlo);
    cudaGetSymbolAddress((void**)&wqh, g_wqh);
    cudaGetSymbolAddress((void**)&wql, g_wql);
    cudaGetSymbolAddress((void**)&woh, g_woh);
    cudaGetSymbolAddress((void**)&wol, g_wol);
    cudaGetSymbolAddress((void**)&xoh, g_xoh);
    cudaGetSymbolAddress((void**)&xol, g_xol);

    cudaFuncSetAttribute(gemm_bf16, cudaFuncAttributeMaxDynamicSharedMemorySize, GEMM_SMEM_B);
    cudaFuncSetAttribute(intra_tc, cudaFuncAttributeMaxDynamicSharedMemorySize, IC2_SMEM);

    // 0) split inputs
    split_f32<<<(BB * TT * DM) / 1024, 256>>>(x, xhi, xlo, BB * TT * DM);
    split_f32<<<(QKVW * DM) / 1024, 256>>>(Wqkv, wqh, wql, QKVW * DM);
    split_f32<<<(DM * DM) / 1024, 256>>>(Wout, woh, wol, DM * DM);

    // 1) qkv = x @ Wqkv^T
    gemm_bf16<<<dim3(QKVW / 128, (BB * TT) / 128), 256, GEMM_SMEM_B>>>(
        xhi, xlo, wqh, wql, qkv, BB * TT, QKVW, DM);
    // 2) chunk totals (tensor cores)
    chunk_sums_tc<<<dim3(NCK, NBH), 256>>>();
    // 3) exclusive prefix
    chunk_prefix<<<dim3((STSZ + 255) / 256, NBH), 256>>>();
    // 4) intra-chunk attention (tensor cores) -> xo bf16 hi/lo
    intra_tc<<<dim3(NCK, NBH), 256, IC2_SMEM>>>();
    // 5) out = xo @ Wout^T
    gemm_bf16<<<dim3(DM / 128, (BB * TT) / 128), 256, GEMM_SMEM_B>>>(
        xoh, xol, woh, wol, out, BB * TT, DM, DM);
}

// round 10
// speedup vs baseline: 3.1874x; 1.0050x over previous
#include <cuda_runtime.h>
#include <cuda_bf16.h>
#include <cstdint>

// Problem constants
#define BB 2
#define TT 2048
#define DM 1024
#define NH 16
#define HS 64
#define QKVW 3072          // 3 * DM
#define CHUNK 64
#define NCK (TT / CHUNK)   // 32 chunks
#define NBH (BB * NH)      // 32 (b,h) pairs
#define STSZ (HS * HS + HS) // 4160 floats per chunk state
#define PAD 68             // f32 smem row pitch
#define P72 72             // bf16 smem row pitch (144 B)

// Scratch (no cudaMalloc allowed)
__device__ float g_qkv[(size_t)BB * TT * QKVW];
__device__ float g_state[(size_t)NBH * NCK * STSZ];
__device__ __nv_bfloat16 g_xhi[(size_t)BB * TT * DM];
__device__ __nv_bfloat16 g_xlo[(size_t)BB * TT * DM];
__device__ __nv_bfloat16 g_wqh[(size_t)QKVW * DM];
__device__ __nv_bfloat16 g_wql[(size_t)QKVW * DM];
__device__ __nv_bfloat16 g_woh[(size_t)DM * DM];
__device__ __nv_bfloat16 g_wol[(size_t)DM * DM];
__device__ __nv_bfloat16 g_xoh[(size_t)BB * TT * DM];
__device__ __nv_bfloat16 g_xol[(size_t)BB * TT * DM];

// ===========================================================================
// Helpers
// ===========================================================================
__device__ __forceinline__ uint32_t smem_u32(const void* p) {
    uint32_t a;
    asm("{ .reg .u64 t; cvta.to.shared.u64 t, %1; cvt.u32.u64 %0, t; }"
        : "=r"(a) : "l"(p));
    return a;
}

#define CP_ASYNC16(dst, src) \
    asm volatile("cp.async.cg.shared.global [%0], [%1], 16;" :: "r"(dst), "l"(src))
#define CP_COMMIT() asm volatile("cp.async.commit_group;" ::: "memory")
#define CP_WAIT1()  asm volatile("cp.async.wait_group 1;" ::: "memory")
#define CP_WAIT0()  asm volatile("cp.async.wait_group 0;" ::: "memory")

#define BAR_ARRIVE() asm volatile("bar.arrive 1, 512;" ::: "memory")
#define BAR_SYNC()   asm volatile("bar.sync 1, 512;" ::: "memory")

__device__ __forceinline__ void ldsm_x4(uint32_t* r, uint32_t addr) {
    asm volatile("ldmatrix.sync.aligned.m8n8.x4.shared.b16 {%0,%1,%2,%3}, [%4];"
                 : "=r"(r[0]), "=r"(r[1]), "=r"(r[2]), "=r"(r[3]) : "r"(addr));
}

__device__ __forceinline__ void mma_bf16(float* c, const uint32_t* a, const uint32_t* b) {
    asm volatile(
        "mma.sync.aligned.m16n8k16.row.col.f32.bf16.bf16.f32 "
        "{%0,%1,%2,%3}, {%4,%5,%6,%7}, {%8,%9}, {%0,%1,%2,%3};"
        : "+f"(c[0]), "+f"(c[1]), "+f"(c[2]), "+f"(c[3])
        : "r"(a[0]), "r"(a[1]), "r"(a[2]), "r"(a[3]), "r"(b[0]), "r"(b[1]));
}

__device__ __forceinline__ void split2(float a, float b, uint32_t& hp, uint32_t& lp) {
    __nv_bfloat162 h = __floats2bfloat162_rn(a, b);
    float2 hf = __bfloat1622float2(h);
    __nv_bfloat162 l = __floats2bfloat162_rn(a - hf.x, b - hf.y);
    hp = *(uint32_t*)&h;
    lp = *(uint32_t*)&l;
}

__device__ __forceinline__ void split1(float v, __nv_bfloat16& h, __nv_bfloat16& l) {
    h = __float2bfloat16(v);
    l = __float2bfloat16(v - __bfloat162float(h));
}

// Generic split-bf16 MMA tile on pitch-72 bf16 smem operands (NT, K=64).
// Term-major issue order: all HH, then all HL, then all LH — 2*MI*NB
// independent accumulators between same-acc reuses (hides HMMA latency).
// Per-accumulator order unchanged (HH->HL->LH per ks) => bit-identical.
template<int MI, int NB>
__device__ __forceinline__ void mm_tile(uint32_t Ahb, uint32_t Alb,
                                        uint32_t Bhb, uint32_t Blb,
                                        int wm, int wn,
                                        int a_mrow, int a_g, int b_nrow, int b_g,
                                        float acc[MI][2 * NB][4]) {
#pragma unroll
    for (int ks = 0; ks < 4; ks++) {
        uint32_t Ah[MI][4], Al[MI][4], Bh[2 * NB][2], Bl[2 * NB][2];
#pragma unroll
        for (int mi = 0; mi < MI; mi++) {
            uint32_t ao = (uint32_t)((wm + mi * 16 + a_mrow) * (P72 * 2) + (ks * 2 + a_g) * 16);
            ldsm_x4(Ah[mi], Ahb + ao);
            ldsm_x4(Al[mi], Alb + ao);
        }
#pragma unroll
        for (int nb = 0; nb < NB; nb++) {
            uint32_t bo = (uint32_t)((wn + nb * 16 + b_nrow) * (P72 * 2) + (ks * 2 + b_g) * 16);
            uint32_t t0[4], t1[4];
            ldsm_x4(t0, Bhb + bo);
            ldsm_x4(t1, Blb + bo);
            Bh[nb * 2][0] = t0[0]; Bh[nb * 2][1] = t0[1];
            Bh[nb * 2 + 1][0] = t0[2]; Bh[nb * 2 + 1][1] = t0[3];
            Bl[nb * 2][0] = t1[0]; Bl[nb * 2][1] = t1[1];
            Bl[nb * 2 + 1][0] = t1[2]; Bl[nb * 2 + 1][1] = t1[3];
        }
#pragma unroll
        for (int mi = 0; mi < MI; mi++)
#pragma unroll
            for (int ni = 0; ni < 2 * NB; ni++) mma_bf16(acc[mi][ni], Ah[mi], Bh[ni]);
#pragma unroll
        for (int mi = 0; mi < MI; mi++)
#pragma unroll
            for (int ni = 0; ni < 2 * NB; ni++) mma_bf16(acc[mi][ni], Ah[mi], Bl[ni]);
#pragma unroll
        for (int mi = 0; mi < MI; mi++)
#pragma unroll
            for (int ni = 0; ni < 2 * NB; ni++) mma_bf16(acc[mi][ni], Al[mi], Bh[ni]);
    }
}

// ---------------------------------------------------------------------------
// Prep: elementwise fp32 -> bf16 hi/lo split
// ---------------------------------------------------------------------------
__global__ __launch_bounds__(256) void split_f32(const float* __restrict__ src,
                                                 __nv_bfloat16* __restrict__ hi,
                                                 __nv_bfloat16* __restrict__ lo,
                                                 int n) {
    int i = (blockIdx.x * 256 + threadIdx.x) * 4;
    if (i >= n) return;
    float4 v = *(const float4*)(src + i);
    uint32_t h0, l0, h1, l1;
    split2(v.x, v.y, h0, l0);
    split2(v.z, v.w, h1, l1);
    *(uint2*)(hi + i) = make_uint2(h0, h1);
    *(uint2*)(lo + i) = make_uint2(l0, l1);
}

// ===========================================================================
// Tensor-core NT GEMM. Term-major MMA issue order (see mm_tile comment).
// ===========================================================================
#define KT 32
#define TILE_B 8192
#define STAGE_B (4 * TILE_B)
#define NSTAGE 3
#define GEMM_SMEM_B (NSTAGE * STAGE_B)

__global__ __launch_bounds__(256) void gemm_bf16(const __nv_bfloat16* __restrict__ Ahi,
                                                 const __nv_bfloat16* __restrict__ Alo,
                                                 const __nv_bfloat16* __restrict__ Bhi,
                                                 const __nv_bfloat16* __restrict__ Blo,
                                                 float* __restrict__ C,
                                                 int M, int N, int K) {
    extern __shared__ char smraw[];
    const uint32_t sb = smem_u32(smraw);
    const int tid = threadIdx.x, wid = tid >> 5, lid = tid & 31;
    const int bm = blockIdx.y * 128, bn = blockIdx.x * 128;
    const int wm = (wid & 1) * 64, wn = (wid >> 1) * 32;
    const int NC = K / KT;

    const __nv_bfloat16* bases[4] = {Ahi, Alo, Bhi, Blo};

#define CP_STAGE(kc, s)                                                        \
    {                                                                          \
        uint32_t stb = sb + (s) * STAGE_B;                                     \
        _Pragma("unroll")                                                      \
        for (int it = 0; it < 8; it++) {                                       \
            int cid = it * 256 + tid;                                          \
            int tile = cid >> 9;                                               \
            int rem = cid & 511;                                               \
            int r = rem >> 2;                                                  \
            int g = rem & 3;                                                   \
            int row0 = (tile < 2) ? bm : bn;                                   \
            const __nv_bfloat16* src =                                         \
                bases[tile] + (size_t)(row0 + r) * K + (kc) * KT + g * 8;      \
            uint32_t dst = stb + tile * TILE_B + r * 64 +                      \
                           (((g ^ ((r >> 1) & 3))) << 4);                      \
            CP_ASYNC16(dst, src);                                              \
        }                                                                      \
        CP_COMMIT();                                                           \
    }

    float acc[4][4][4];
#pragma unroll
    for (int mi = 0; mi < 4; mi++)
#pragma unroll
        for (int ni = 0; ni < 4; ni++)
#pragma unroll
            for (int q = 0; q < 4; q++) acc[mi][ni][q] = 0.f;

    const int a_mrow = (lid < 16 ? lid : lid - 16);
    const int a_g    = (lid < 16 ? 0 : 1);
    const int b_q = lid & 7, b_g4 = lid >> 3;
    const int b_nrow = b_q + (b_g4 >> 1) * 8;
    const int b_g    = (b_g4 & 1);

    CP_STAGE(0, 0);
    CP_STAGE(1, 1);
    BAR_ARRIVE();

    for (int kc = 0; kc < NC; kc++) {
        if (kc < NC - 1) { CP_WAIT1(); } else { CP_WAIT0(); }
        BAR_SYNC();
        if (kc + 2 < NC) CP_STAGE(kc + 2, (kc + 2) % NSTAGE);

        const uint32_t stage = sb + (kc % NSTAGE) * STAGE_B;
#pragma unroll
        for (int ks = 0; ks < 2; ks++) {
            uint32_t Ah[4][4], Al[4][4], Bh[4][2], Bl[4][2];
#pragma unroll
            for (int mi = 0; mi < 4; mi++) {
                int row = wm + mi * 16 + a_mrow;
                int gran = ks * 2 + a_g;
                uint32_t addr = stage + row * 64 + ((gran ^ ((row >> 1) & 3)) << 4);
                ldsm_x4(Ah[mi], addr);
                ldsm_x4(Al[mi], addr + TILE_B);
            }
#pragma unroll
            for (int nb = 0; nb < 2; nb++) {
                int row = wn + nb * 16 + b_nrow;
                int gran = ks * 2 + b_g;
                uint32_t addr = stage + 2 * TILE_B + row * 64 +
                                ((gran ^ ((row >> 1) & 3)) << 4);
                uint32_t t[4];
                ldsm_x4(t, addr);
                Bh[nb * 2][0] = t[0]; Bh[nb * 2][1] = t[1];
                Bh[nb * 2 + 1][0] = t[2]; Bh[nb * 2 + 1][1] = t[3];
                ldsm_x4(t, addr + TILE_B);
                Bl[nb * 2][0] = t[0]; Bl[nb * 2][1] = t[1];
                Bl[nb * 2 + 1][0] = t[2]; Bl[nb * 2 + 1][1] = t[3];
            }
            if (ks == 1) BAR_ARRIVE();
            // term-major issue: 16 independent accs between same-acc reuses
#pragma unroll
            for (int mi = 0; mi < 4; mi++)
#pragma unroll
                for (int ni = 0; ni < 4; ni++) mma_bf16(acc[mi][ni], Ah[mi], Bh[ni]);
#pragma unroll
            for (int mi = 0; mi < 4; mi++)
#pragma unroll
                for (int ni = 0; ni < 4; ni++) mma_bf16(acc[mi][ni], Ah[mi], Bl[ni]);
#pragma unroll
            for (int mi = 0; mi < 4; mi++)
#pragma unroll
                for (int ni = 0; ni < 4; ni++) mma_bf16(acc[mi][ni], Al[mi], Bh[ni]);
        }
    }

    const int erow = lid >> 2, ecol = 2 * (lid & 3);
#pragma unroll
    for (int mi = 0; mi < 4; mi++) {
#pragma unroll
        for (int ni = 0; ni < 4; ni++) {
            float* c0 = C + (size_t)(bm + wm + mi * 16 + erow) * N + bn + wn + ni * 8 + ecol;
            *(float2*)c0 = make_float2(acc[mi][ni][0], acc[mi][ni][1]);
            *(float2*)(c0 + 8 * N) = make_float2(acc[mi][ni][2], acc[mi][ni][3]);
        }
    }
}

// ---------------------------------------------------------------------------
// Pass A (tensor-core): S_c[c][d] = sum_t exp(k[t,c]) * v[t,d]; sumK[c].
// ---------------------------------------------------------------------------
#define CS_TILE (64 * P72 * 2)

__global__ __launch_bounds__(256) void chunk_sums_tc() {
    __shared__ char sm[4 * CS_TILE];
    const uint32_t sb = smem_u32(sm);
    __nv_bfloat16* Ah = (__nv_bfloat16*)sm;
    __nv_bfloat16* Al = (__nv_bfloat16*)(sm + CS_TILE);
    __nv_bfloat16* Bh = (__nv_bfloat16*)(sm + 2 * CS_TILE);
    __nv_bfloat16* Bl = (__nv_bfloat16*)(sm + 3 * CS_TILE);

    const int ck = blockIdx.x, bh = blockIdx.y;
    const int b = bh >> 4, h = bh & 15;
    const int tid = threadIdx.x;

    for (int i = tid; i < 4096; i += 256) {
        int tt = i >> 6, c = i & 63;
        const float* row = g_qkv + (size_t)(b * TT + ck * CHUNK + tt) * QKVW;
        __nv_bfloat16 hh, ll;
        float e = __expf(row[(NH + h) * HS + c]);
        split1(e, hh, ll);
        Ah[c * P72 + tt] = hh; Al[c * P72 + tt] = ll;
        float v = row[(2 * NH + h) * HS + c];
        split1(v, hh, ll);
        Bh[c * P72 + tt] = hh; Bl[c * P72 + tt] = ll;
    }
    __syncthreads();

    const int wid = tid >> 5, lid = tid & 31;
    const int a_mrow = (lid < 16 ? lid : lid - 16), a_g = (lid < 16 ? 0 : 1);
    const int b_q = lid & 7, b_g4 = lid >> 3;
    const int b_nrow = b_q + (b_g4 >> 1) * 8, b_g = b_g4 & 1;
    const int wm = (wid & 1) * 32, wn = (wid >> 1) * 16;

    float acc[2][2][4];
#pragma unroll
    for (int mi = 0; mi < 2; mi++)
#pragma unroll
        for (int ni = 0; ni < 2; ni++)
#pragma unroll
            for (int q = 0; q < 4; q++) acc[mi][ni][q] = 0.f;

    mm_tile<2, 1>(sb, sb + CS_TILE, sb + 2 * CS_TILE, sb + 3 * CS_TILE,
                  wm, wn, a_mrow, a_g, b_nrow, b_g, acc);

    float* st = g_state + (size_t)(bh * NCK + ck) * STSZ;
    const int erow = lid >> 2, ecol = 2 * (lid & 3);
#pragma unroll
    for (int mi = 0; mi < 2; mi++)
#pragma unroll
        for (int ni = 0; ni < 2; ni++) {
            int r = wm + mi * 16 + erow, cc = wn + ni * 8 + ecol;
            *(float2*)&st[r * 64 + cc] = make_float2(acc[mi][ni][0], acc[mi][ni][1]);
            *(float2*)&st[(r + 8) * 64 + cc] = make_float2(acc[mi][ni][2], acc[mi][ni][3]);
        }

    if (tid < 64) {
        float s = 0.f;
        for (int t2 = 0; t2 < 64; t2++)
            s += __bfloat162float(Ah[tid * P72 + t2]) + __bfloat162float(Al[tid * P72 + t2]);
        st[4096 + tid] = s;
    }
}

// ---------------------------------------------------------------------------
// Pass B: exclusive prefix over the 32 chunks
// ---------------------------------------------------------------------------
__global__ __launch_bounds__(256) void chunk_prefix() {
    const int bh = blockIdx.y;
    const int idx = blockIdx.x * 256 + threadIdx.x;
    if (idx >= STSZ) return;
    float run = 0.f;
    float* base = g_state + (size_t)bh * NCK * STSZ + idx;
    for (int ck = 0; ck < NCK; ck++) {
        float t = base[(size_t)ck * STSZ];
        base[(size_t)ck * STSZ] = run;
        run += t;
    }
}

// ---------------------------------------------------------------------------
// Pass C (tensor-core): softmax + denominators (SIMT), then
//   QS (warps 0-3) || QK (warps 4-7), causal mask, AV (all warps).
// ---------------------------------------------------------------------------
#define IC2_SMEM 91136

__global__ __launch_bounds__(256) void intra_tc() {
    extern __shared__ char sm[];
    float* R1f = (float*)sm;
    const uint32_t sb = smem_u32(sm);
    const uint32_t R2h = sb + 17408, R2l = sb + 26624;
    const uint32_t R3h = sb + 35840, R3l = sb + 45056;
    const uint32_t R4h = sb + 54272, R4l = sb + 63488;
    const uint32_t R5h = sb + 72704, R5l = sb + 81920;
    __nv_bfloat16* pR2h = (__nv_bfloat16*)(sm + 17408);
    __nv_bfloat16* pR2l = (__nv_bfloat16*)(sm + 26624);
    __nv_bfloat16* pR3h = (__nv_bfloat16*)(sm + 35840);
    __nv_bfloat16* pR3l = (__nv_bfloat16*)(sm + 45056);
    __nv_bfloat16* pR4h = (__nv_bfloat16*)(sm + 54272);
    __nv_bfloat16* pR4l = (__nv_bfloat16*)(sm + 63488);
    __nv_bfloat16* pR5h = (__nv_bfloat16*)(sm + 72704);
    __nv_bfloat16* pR5l = (__nv_bfloat16*)(sm + 81920);
    __shared__ float den0[64];

    const int ck = blockIdx.x, bh = blockIdx.y;
    const int b = bh >> 4, h = bh & 15;
    const int tid = threadIdx.x;
    const float* st = g_state + (size_t)(bh * NCK + ck) * STSZ;

    // Phase 1: loads (+ exp, splits, transposes)
    for (int i = tid; i < 4096; i += 256) {
        int tt = i >> 6, c = i & 63;
        const float* row = g_qkv + (size_t)(b * TT + ck * CHUNK + tt) * QKVW;
        R1f[tt * PAD + c] = row[h * HS + c];
        __nv_bfloat16 hh, ll;
        float e = __expf(row[(NH + h) * HS + c]);
        split1(e, hh, ll);
        pR3h[tt * P72 + c] = hh; pR3l[tt * P72 + c] = ll;
        float v = row[(2 * NH + h) * HS + c];
        split1(v, hh, ll);
        pR5h[c * P72 + tt] = hh; pR5l[c * P72 + tt] = ll;
        split1(st[i], hh, ll);
        pR4h[(i & 63) * P72 + (i >> 6)] = hh;
        pR4l[(i & 63) * P72 + (i >> 6)] = ll;
    }
    if (tid < 64) den0[tid] = st[4096 + tid];
    __syncthreads();

    // Phase 2: softmax over head dim per row t (4 lanes/row)
    {
        const int tq = tid >> 2, qd = tid & 3;
        float* qseg = R1f + tq * PAD + qd * 16;
        float v[16];
#pragma unroll
        for (int q = 0; q < 4; q++) {
            float4 f = ((const float4*)qseg)[q];
            v[4*q] = f.x; v[4*q+1] = f.y; v[4*q+2] = f.z; v[4*q+3] = f.w;
        }
        float m = v[0];
#pragma unroll
        for (int j = 1; j < 16; j++) m = fmaxf(m, v[j]);
        m = fmaxf(m, __shfl_xor_sync(0xFFFFFFFFu, m, 1));
        m = fmaxf(m, __shfl_xor_sync(0xFFFFFFFFu, m, 2));
        float s = 0.f;
#pragma unroll
        for (int j = 0; j < 16; j++) { v[j] = __expf(v[j] - m); s += v[j]; }
        s += __shfl_xor_sync(0xFFFFFFFFu, s, 1);
        s += __shfl_xor_sync(0xFFFFFFFFu, s, 2);
        float inv = 0.125f / s;
#pragma unroll
        for (int q = 0; q < 4; q++)
            ((float4*)qseg)[q] = make_float4(v[4*q] * inv, v[4*q+1] * inv,
                                             v[4*q+2] * inv, v[4*q+3] * inv);
    }
    __syncthreads();

    // Phase 3: per-column denominator cumsum, fold into qn
    {
        const int c = tid >> 2, sg = tid & 3;
        float cum[16];
        float s = 0.f;
#pragma unroll
        for (int j = 0; j < 16; j++) {
            int t2 = sg * 16 + j;
            s += __bfloat162float(pR3h[t2 * P72 + c]) + __bfloat162float(pR3l[t2 * P72 + c]);
            cum[j] = s;
        }
        float x = s;
        float u1 = __shfl_up_sync(0xFFFFFFFFu, x, 1); if (sg >= 1) x += u1;
        float u2 = __shfl_up_sync(0xFFFFFFFFu, x, 2); if (sg >= 2) x += u2;
        float base = den0[c] + (x - s);
#pragma unroll
        for (int j = 0; j < 16; j++) {
            int t2 = sg * 16 + j;
            R1f[t2 * PAD + c] = R1f[t2 * PAD + c] / (base + cum[j] + 1e-9f);
        }
    }
    __syncthreads();

    // Phase 4: split qn f32 -> R2 hi/lo
    for (int i = tid; i < 4096; i += 256) {
        int t2 = i >> 6, c = i & 63;
        __nv_bfloat16 hh, ll;
        split1(R1f[t2 * PAD + c], hh, ll);
        pR2h[t2 * P72 + c] = hh; pR2l[t2 * P72 + c] = ll;
    }
    __syncthreads();

    const int wid = tid >> 5, lid = tid & 31;
    const int a_mrow = (lid < 16 ? lid : lid - 16), a_g = (lid < 16 ? 0 : 1);
    const int b_q = lid & 7, b_g4 = lid >> 3;
    const int b_nrow = b_q + (b_g4 >> 1) * 8, b_g = b_g4 & 1;
    const int erow = lid >> 2, ecol = 2 * (lid & 3);

    // Phase 5: QS (warps 0-3) || QK (warps 4-7)
    float accA[2][4][4];
    if (wid < 4) {
        float accS[2][4][4];
#pragma unroll
        for (int mi = 0; mi < 2; mi++)
#pragma unroll
            for (int ni = 0; ni < 4; ni++)
#pragma unroll
                for (int q = 0; q < 4; q++) accS[mi][ni][q] = 0.f;
        int wm = (wid & 1) * 32, wn = (wid >> 1) * 32;
        mm_tile<2, 2>(R2h, R2l, R4h, R4l, wm, wn, a_mrow, a_g, b_nrow, b_g, accS);
#pragma unroll
        for (int mi = 0; mi < 2; mi++)
#pragma unroll
            for (int ni = 0; ni < 4; ni++) {
                int r = wm + mi * 16 + erow, d = wn + ni * 8 + ecol;
                *(float2*)&R1f[r * PAD + d] = make_float2(accS[mi][ni][0], accS[mi][ni][1]);
                *(float2*)&R1f[(r + 8) * PAD + d] = make_float2(accS[mi][ni][2], accS[mi][ni][3]);
            }
    } else {
#pragma unroll
        for (int mi = 0; mi < 2; mi++)
#pragma unroll
            for (int ni = 0; ni < 4; ni++)
#pragma unroll
                for (int q = 0; q < 4; q++) accA[mi][ni][q] = 0.f;
        int w4 = wid - 4;
        int wm = (w4 & 1) * 32, wn = (w4 >> 1) * 32;
        mm_tile<2, 2>(R2h, R2l, R3h, R3l, wm, wn, a_mrow, a_g, b_nrow, b_g, accA);
    }
    __syncthreads();

    // Phase 5b: warps 4-7 mask A causally and write bf16 hi/lo to R4
    if (wid >= 4) {
        int w4 = wid - 4;
        int wm = (w4 & 1) * 32, wn = (w4 >> 1) * 32;
#pragma unroll
        for (int mi = 0; mi < 2; mi++)
#pragma unroll
            for (int ni = 0; ni < 4; ni++) {
                int r0 = wm + mi * 16 + erow, s0 = wn + ni * 8 + ecol;
                float v0 = (s0 <= r0) ? accA[mi][ni][0] : 0.f;
                float v1 = (s0 + 1 <= r0) ? accA[mi][ni][1] : 0.f;
                uint32_t hp, lp;
                split2(v0, v1, hp, lp);
                *(uint32_t*)&pR4h[r0 * P72 + s0] = hp;
                *(uint32_t*)&pR4l[r0 * P72 + s0] = lp;
                int r2 = r0 + 8;
                float v2 = (s0 <= r2) ? accA[mi][ni][2] : 0.f;
                float v3 = (s0 + 1 <= r2) ? accA[mi][ni][3] : 0.f;
                split2(v2, v3, hp, lp);
                *(uint32_t*)&pR4h[r2 * P72 + s0] = hp;
                *(uint32_t*)&pR4l[r2 * P72 + s0] = lp;
            }
    }
    __syncthreads();

    // Phase 6: AV (all 8 warps), add xo_acc, split, store
    {
        float accV[1][4][4];
#pragma unroll
        for (int ni = 0; ni < 4; ni++)
#pragma unroll
            for (int q = 0; q < 4; q++) accV[0][ni][q] = 0.f;
        int wm = (wid & 3) * 16, wn = (wid >> 2) * 32;
        mm_tile<1, 2>(R4h, R4l, R5h, R5l, wm, wn, a_mrow, a_g, b_nrow, b_g, accV);
#pragma unroll
        for (int ni = 0; ni < 4; ni++) {
            int r = wm + erow, d = wn + ni * 8 + ecol;
            uint32_t hp, lp;
            float x0 = accV[0][ni][0] + R1f[r * PAD + d];
            float x1 = accV[0][ni][1] + R1f[r * PAD + d + 1];
            split2(x0, x1, hp, lp);
            size_t g0 = (size_t)(b * TT + ck * CHUNK + r) * DM + h * HS + d;
            *(uint32_t*)&g_xoh[g0] = hp;
            *(uint32_t*)&g_xol[g0] = lp;
            int r2 = r + 8;
            float x2 = accV[0][ni][2] + R1f[r2 * PAD + d];
            float x3 = accV[0][ni][3] + R1f[r2 * PAD + d + 1];
            split2(x2, x3, hp, lp);
            size_t g2 = (size_t)(b * TT + ck * CHUNK + r2) * DM + h * HS + d;
            *(uint32_t*)&g_xoh[g2] = hp;
            *(uint32_t*)&g_xol[g2] = lp;
        }
    }
}

// ---------------------------------------------------------------------------
extern "C" void kernel_launch(void* const* d_in, const int* in_sizes, int n_in,
                              void* d_out, int out_size) {
    const float* x    = (const float*)d_in[0];
    const float* Wqkv = (const float*)d_in[1];
    const float* Wout = (const float*)d_in[2];
    float* out = (float*)d_out;

    float* qkv;
    cudaGetSymbolAddress((void**)&qkv, g_qkv);
    __nv_bfloat16 *xhi, *xlo, *wqh, *wql, *woh, *wol, *xoh, *xol;
    cudaGetSymbolAddress((void**)&xhi, g_xhi);
    cudaGetSymbolAddress((void**)&xlo, g_xlo);
    cudaGetSymbolAddress((void**)&wqh, g_wqh);
    cudaGetSymbolAddress((void**)&wql, g_wql);
    cudaGetSymbolAddress((void**)&woh, g_woh);
    cudaGetSymbolAddress((void**)&wol, g_wol);
    cudaGetSymbolAddress((void**)&xoh, g_xoh);
    cudaGetSymbolAddress((void**)&xol, g_xol);

    cudaFuncSetAttribute(gemm_bf16, cudaFuncAttributeMaxDynamicSharedMemorySize, GEMM_SMEM_B);
    cudaFuncSetAttribute(intra_tc, cudaFuncAttributeMaxDynamicSharedMemorySize, IC2_SMEM);

    // 0) split inputs
    split_f32<<<(BB * TT * DM) / 1024, 256>>>(x, xhi, xlo, BB * TT * DM);
    split_f32<<<(QKVW * DM) / 1024, 256>>>(Wqkv, wqh, wql, QKVW * DM);
    split_f32<<<(DM * DM) / 1024, 256>>>(Wout, woh, wol, DM * DM);

    // 1) qkv = x @ Wqkv^T
    gemm_bf16<<<dim3(QKVW / 128, (BB * TT) / 128), 256, GEMM_SMEM_B>>>(
        xhi, xlo, wqh, wql, qkv, BB * TT, QKVW, DM);
    // 2) chunk totals (tensor cores)
    chunk_sums_tc<<<dim3(NCK, NBH), 256>>>();
    // 3) exclusive prefix
    chunk_prefix<<<dim3((STSZ + 255) / 256, NBH), 256>>>();
    // 4) intra-chunk attention (tensor cores)
    intra_tc<<<dim3(NCK, NBH), 256, IC2_SMEM>>>();
    // 5) out = xo @ Wout^T
    gemm_bf16<<<dim3(DM / 128, (BB * TT) / 128), 256, GEMM_SMEM_B>>>(
        xoh, xol, woh, wol, out, BB * TT, DM, DM);
}

// round 11
// speedup vs baseline: 3.3880x; 1.0629x over previous
#include <cuda_runtime.h>
#include <cuda_bf16.h>
#include <cstdint>

// Problem constants
#define BB 2
#define TT 2048
#define DM 1024
#define NH 16
#define HS 64
#define QKVW 3072
#define CHUNK 64
#define NCK (TT / CHUNK)
#define NBH (BB * NH)
#define STSZ (HS * HS + HS)
#define PAD 68
#define P72 72

// Scratch
__device__ float g_qkv[(size_t)BB * TT * QKVW];
__device__ float g_state[(size_t)NBH * NCK * STSZ];
__device__ __nv_bfloat16 g_xhi[(size_t)BB * TT * DM];
__device__ __nv_bfloat16 g_xlo[(size_t)BB * TT * DM];
__device__ __nv_bfloat16 g_wqh[(size_t)QKVW * DM];
__device__ __nv_bfloat16 g_wql[(size_t)QKVW * DM];
__device__ __nv_bfloat16 g_woh[(size_t)DM * DM];
__device__ __nv_bfloat16 g_wol[(size_t)DM * DM];
__device__ __nv_bfloat16 g_xoh[(size_t)BB * TT * DM];
__device__ __nv_bfloat16 g_xol[(size_t)BB * TT * DM];

// ===========================================================================
// Helpers
// ===========================================================================
__device__ __forceinline__ uint32_t smem_u32(const void* p) {
    uint32_t a;
    asm("{ .reg .u64 t; cvta.to.shared.u64 t, %1; cvt.u32.u64 %0, t; }"
        : "=r"(a) : "l"(p));
    return a;
}

#define CP_ASYNC16(dst, src) \
    asm volatile("cp.async.cg.shared.global [%0], [%1], 16;" :: "r"(dst), "l"(src))
#define CP_COMMIT() asm volatile("cp.async.commit_group;" ::: "memory")
#define CP_WAIT1()  asm volatile("cp.async.wait_group 1;" ::: "memory")
#define CP_WAIT0()  asm volatile("cp.async.wait_group 0;" ::: "memory")

#define BAR_ARRIVE() asm volatile("bar.arrive 1, 512;" ::: "memory")
#define BAR_SYNC()   asm volatile("bar.sync 1, 512;" ::: "memory")
// 128-thread variant
#define BAR2_ARRIVE() asm volatile("bar.arrive 1, 256;" ::: "memory")
#define BAR2_SYNC()   asm volatile("bar.sync 1, 256;" ::: "memory")

__device__ __forceinline__ void ldsm_x4(uint32_t* r, uint32_t addr) {
    asm volatile("ldmatrix.sync.aligned.m8n8.x4.shared.b16 {%0,%1,%2,%3}, [%4];"
                 : "=r"(r[0]), "=r"(r[1]), "=r"(r[2]), "=r"(r[3]) : "r"(addr));
}

__device__ __forceinline__ void mma_bf16(float* c, const uint32_t* a, const uint32_t* b) {
    asm volatile(
        "mma.sync.aligned.m16n8k16.row.col.f32.bf16.bf16.f32 "
        "{%0,%1,%2,%3}, {%4,%5,%6,%7}, {%8,%9}, {%0,%1,%2,%3};"
        : "+f"(c[0]), "+f"(c[1]), "+f"(c[2]), "+f"(c[3])
        : "r"(a[0]), "r"(a[1]), "r"(a[2]), "r"(a[3]), "r"(b[0]), "r"(b[1]));
}

__device__ __forceinline__ void split2(float a, float b, uint32_t& hp, uint32_t& lp) {
    __nv_bfloat162 h = __floats2bfloat162_rn(a, b);
    float2 hf = __bfloat1622float2(h);
    __nv_bfloat162 l = __floats2bfloat162_rn(a - hf.x, b - hf.y);
    hp = *(uint32_t*)&h;
    lp = *(uint32_t*)&l;
}

__device__ __forceinline__ void split1(float v, __nv_bfloat16& h, __nv_bfloat16& l) {
    h = __float2bfloat16(v);
    l = __float2bfloat16(v - __bfloat162float(h));
}

// Generic split-bf16 MMA tile (pitch-72 bf16 smem, NT, K=64). Term-major.
template<int MI, int NB>
__device__ __forceinline__ void mm_tile(uint32_t Ahb, uint32_t Alb,
                                        uint32_t Bhb, uint32_t Blb,
                                        int wm, int wn,
                                        int a_mrow, int a_g, int b_nrow, int b_g,
                                        float acc[MI][2 * NB][4]) {
#pragma unroll
    for (int ks = 0; ks < 4; ks++) {
        uint32_t Ah[MI][4], Al[MI][4], Bh[2 * NB][2], Bl[2 * NB][2];
#pragma unroll
        for (int mi = 0; mi < MI; mi++) {
            uint32_t ao = (uint32_t)((wm + mi * 16 + a_mrow) * (P72 * 2) + (ks * 2 + a_g) * 16);
            ldsm_x4(Ah[mi], Ahb + ao);
            ldsm_x4(Al[mi], Alb + ao);
        }
#pragma unroll
        for (int nb = 0; nb < NB; nb++) {
            uint32_t bo = (uint32_t)((wn + nb * 16 + b_nrow) * (P72 * 2) + (ks * 2 + b_g) * 16);
            uint32_t t0[4], t1[4];
            ldsm_x4(t0, Bhb + bo);
            ldsm_x4(t1, Blb + bo);
            Bh[nb * 2][0] = t0[0]; Bh[nb * 2][1] = t0[1];
            Bh[nb * 2 + 1][0] = t0[2]; Bh[nb * 2 + 1][1] = t0[3];
            Bl[nb * 2][0] = t1[0]; Bl[nb * 2][1] = t1[1];
            Bl[nb * 2 + 1][0] = t1[2]; Bl[nb * 2 + 1][1] = t1[3];
        }
#pragma unroll
        for (int mi = 0; mi < MI; mi++)
#pragma unroll
            for (int ni = 0; ni < 2 * NB; ni++) mma_bf16(acc[mi][ni], Ah[mi], Bh[ni]);
#pragma unroll
        for (int mi = 0; mi < MI; mi++)
#pragma unroll
            for (int ni = 0; ni < 2 * NB; ni++) mma_bf16(acc[mi][ni], Ah[mi], Bl[ni]);
#pragma unroll
        for (int mi = 0; mi < MI; mi++)
#pragma unroll
            for (int ni = 0; ni < 2 * NB; ni++) mma_bf16(acc[mi][ni], Al[mi], Bh[ni]);
    }
}

// ---------------------------------------------------------------------------
// Prep: fp32 -> bf16 hi/lo split
// ---------------------------------------------------------------------------
__global__ __launch_bounds__(256) void split_f32(const float* __restrict__ src,
                                                 __nv_bfloat16* __restrict__ hi,
                                                 __nv_bfloat16* __restrict__ lo,
                                                 int n) {
    int i = (blockIdx.x * 256 + threadIdx.x) * 4;
    if (i >= n) return;
    float4 v = *(const float4*)(src + i);
    uint32_t h0, l0, h1, l1;
    split2(v.x, v.y, h0, l0);
    split2(v.z, v.w, h1, l1);
    *(uint2*)(hi + i) = make_uint2(h0, h1);
    *(uint2*)(lo + i) = make_uint2(l0, l1);
}

// ===========================================================================
// GEMM v1: 128x128 tile, 256 threads, 2 CTA/SM (used for gemm2: clean 1-wave)
// ===========================================================================
#define KT 32
#define TILE_B 8192
#define STAGE_B (4 * TILE_B)
#define NSTAGE 3
#define GEMM_SMEM_B (NSTAGE * STAGE_B)

__global__ __launch_bounds__(256) void gemm_bf16(const __nv_bfloat16* __restrict__ Ahi,
                                                 const __nv_bfloat16* __restrict__ Alo,
                                                 const __nv_bfloat16* __restrict__ Bhi,
                                                 const __nv_bfloat16* __restrict__ Blo,
                                                 float* __restrict__ C,
                                                 int M, int N, int K) {
    extern __shared__ char smraw[];
    const uint32_t sb = smem_u32(smraw);
    const int tid = threadIdx.x, wid = tid >> 5, lid = tid & 31;
    const int bm = blockIdx.y * 128, bn = blockIdx.x * 128;
    const int wm = (wid & 1) * 64, wn = (wid >> 1) * 32;
    const int NC = K / KT;

    const __nv_bfloat16* bases[4] = {Ahi, Alo, Bhi, Blo};

#define CP_STAGE(kc, s)                                                        \
    {                                                                          \
        uint32_t stb = sb + (s) * STAGE_B;                                     \
        _Pragma("unroll")                                                      \
        for (int it = 0; it < 8; it++) {                                       \
            int cid = it * 256 + tid;                                          \
            int tile = cid >> 9;                                               \
            int rem = cid & 511;                                               \
            int r = rem >> 2;                                                  \
            int g = rem & 3;                                                   \
            int row0 = (tile < 2) ? bm : bn;                                   \
            const __nv_bfloat16* src =                                         \
                bases[tile] + (size_t)(row0 + r) * K + (kc) * KT + g * 8;      \
            uint32_t dst = stb + tile * TILE_B + r * 64 +                      \
                           (((g ^ ((r >> 1) & 3))) << 4);                      \
            CP_ASYNC16(dst, src);                                              \
        }                                                                      \
        CP_COMMIT();                                                           \
    }

    float acc[4][4][4];
#pragma unroll
    for (int mi = 0; mi < 4; mi++)
#pragma unroll
        for (int ni = 0; ni < 4; ni++)
#pragma unroll
            for (int q = 0; q < 4; q++) acc[mi][ni][q] = 0.f;

    const int a_mrow = (lid < 16 ? lid : lid - 16);
    const int a_g    = (lid < 16 ? 0 : 1);
    const int b_q = lid & 7, b_g4 = lid >> 3;
    const int b_nrow = b_q + (b_g4 >> 1) * 8;
    const int b_g    = (b_g4 & 1);

    CP_STAGE(0, 0);
    CP_STAGE(1, 1);
    BAR_ARRIVE();

    for (int kc = 0; kc < NC; kc++) {
        if (kc < NC - 1) { CP_WAIT1(); } else { CP_WAIT0(); }
        BAR_SYNC();
        if (kc + 2 < NC) CP_STAGE(kc + 2, (kc + 2) % NSTAGE);

        const uint32_t stage = sb + (kc % NSTAGE) * STAGE_B;
#pragma unroll
        for (int ks = 0; ks < 2; ks++) {
            uint32_t Ah[4][4], Al[4][4], Bh[4][2], Bl[4][2];
#pragma unroll
            for (int mi = 0; mi < 4; mi++) {
                int row = wm + mi * 16 + a_mrow;
                int gran = ks * 2 + a_g;
                uint32_t addr = stage + row * 64 + ((gran ^ ((row >> 1) & 3)) << 4);
                ldsm_x4(Ah[mi], addr);
                ldsm_x4(Al[mi], addr + TILE_B);
            }
#pragma unroll
            for (int nb = 0; nb < 2; nb++) {
                int row = wn + nb * 16 + b_nrow;
                int gran = ks * 2 + b_g;
                uint32_t addr = stage + 2 * TILE_B + row * 64 +
                                ((gran ^ ((row >> 1) & 3)) << 4);
                uint32_t t[4];
                ldsm_x4(t, addr);
                Bh[nb * 2][0] = t[0]; Bh[nb * 2][1] = t[1];
                Bh[nb * 2 + 1][0] = t[2]; Bh[nb * 2 + 1][1] = t[3];
                ldsm_x4(t, addr + TILE_B);
                Bl[nb * 2][0] = t[0]; Bl[nb * 2][1] = t[1];
                Bl[nb * 2 + 1][0] = t[2]; Bl[nb * 2 + 1][1] = t[3];
            }
            if (ks == 1) BAR_ARRIVE();
#pragma unroll
            for (int mi = 0; mi < 4; mi++)
#pragma unroll
                for (int ni = 0; ni < 4; ni++) mma_bf16(acc[mi][ni], Ah[mi], Bh[ni]);
#pragma unroll
            for (int mi = 0; mi < 4; mi++)
#pragma unroll
                for (int ni = 0; ni < 4; ni++) mma_bf16(acc[mi][ni], Ah[mi], Bl[ni]);
#pragma unroll
            for (int mi = 0; mi < 4; mi++)
#pragma unroll
                for (int ni = 0; ni < 4; ni++) mma_bf16(acc[mi][ni], Al[mi], Bh[ni]);
        }
    }

    const int erow = lid >> 2, ecol = 2 * (lid & 3);
#pragma unroll
    for (int mi = 0; mi < 4; mi++) {
#pragma unroll
        for (int ni = 0; ni < 4; ni++) {
            float* c0 = C + (size_t)(bm + wm + mi * 16 + erow) * N + bn + wn + ni * 8 + ecol;
            *(float2*)c0 = make_float2(acc[mi][ni][0], acc[mi][ni][1]);
            *(float2*)(c0 + 8 * N) = make_float2(acc[mi][ni][2], acc[mi][ni][3]);
        }
    }
}

// ===========================================================================
// GEMM v2 (for gemm1): 64x128 tile, 128 threads, warp grid 2x2 (32x64/warp),
// NSTAGE=3, 3 CTAs/SM. Higher reg budget (170/thr) -> ptxas can pipeline
// ldsm under mma; 3 independent CTAs stagger LDSM bursts vs MMA phases.
// Stage layout: Ahi(4KB) Alo(4KB) Bhi(8KB) Blo(8KB) = 24576 B.
// ===========================================================================
#define G1_AT 4096
#define G1_BT 8192
#define G1_STAGE 24576
#define G1_SMEM (3 * G1_STAGE)   // 73728 B

__global__ __launch_bounds__(128, 3) void gemm_bf16_64(
        const __nv_bfloat16* __restrict__ Ahi,
        const __nv_bfloat16* __restrict__ Alo,
        const __nv_bfloat16* __restrict__ Bhi,
        const __nv_bfloat16* __restrict__ Blo,
        float* __restrict__ C,
        int M, int N, int K) {
    extern __shared__ char smraw[];
    const uint32_t sb = smem_u32(smraw);
    const int tid = threadIdx.x, wid = tid >> 5, lid = tid & 31;
    const int bm = blockIdx.y * 64, bn = blockIdx.x * 128;
    const int wm = (wid & 1) * 32, wn = (wid >> 1) * 64;
    const int NC = K / KT;

    // loader: 1536 granules/stage, 12 per thread
#define CP_STAGE1(kc, s)                                                       \
    {                                                                          \
        uint32_t stb = sb + (s) * G1_STAGE;                                    \
        _Pragma("unroll")                                                      \
        for (int it = 0; it < 4; it++) {  /* A: 512 granules */                \
            int cid = it * 128 + tid;                                          \
            int comp = cid >> 8;          /* 0=hi 1=lo */                      \
            int rem = cid & 255;                                               \
            int r = rem >> 2, g = rem & 3;                                     \
            const __nv_bfloat16* src = (comp ? Alo : Ahi) +                    \
                (size_t)(bm + r) * K + (kc) * KT + g * 8;                      \
            uint32_t dst = stb + comp * G1_AT + r * 64 +                       \
                           ((g ^ ((r >> 1) & 3)) << 4);                        \
            CP_ASYNC16(dst, src);                                              \
        }                                                                      \
        _Pragma("unroll")                                                      \
        for (int it = 0; it < 8; it++) {  /* B: 1024 granules */               \
            int cid = it * 128 + tid;                                          \
            int comp = cid >> 9;                                               \
            int rem = cid & 511;                                               \
            int r = rem >> 2, g = rem & 3;                                     \
            const __nv_bfloat16* src = (comp ? Blo : Bhi) +                    \
                (size_t)(bn + r) * K + (kc) * KT + g * 8;                      \
            uint32_t dst = stb + 2 * G1_AT + comp * G1_BT + r * 64 +           \
                           ((g ^ ((r >> 1) & 3)) << 4);                        \
            CP_ASYNC16(dst, src);                                              \
        }                                                                      \
        CP_COMMIT();                                                           \
    }

    float acc[2][8][4];
#pragma unroll
    for (int mi = 0; mi < 2; mi++)
#pragma unroll
        for (int ni = 0; ni < 8; ni++)
#pragma unroll
            for (int q = 0; q < 4; q++) acc[mi][ni][q] = 0.f;

    const int a_mrow = (lid < 16 ? lid : lid - 16);
    const int a_g    = (lid < 16 ? 0 : 1);
    const int b_q = lid & 7, b_g4 = lid >> 3;
    const int b_nrow = b_q + (b_g4 >> 1) * 8;
    const int b_g    = (b_g4 & 1);

    CP_STAGE1(0, 0);
    CP_STAGE1(1, 1);
    BAR2_ARRIVE();

    for (int kc = 0; kc < NC; kc++) {
        if (kc < NC - 1) { CP_WAIT1(); } else { CP_WAIT0(); }
        BAR2_SYNC();
        if (kc + 2 < NC) CP_STAGE1(kc + 2, (kc + 2) % 3);

        const uint32_t stage = sb + (kc % 3) * G1_STAGE;
#pragma unroll
        for (int ks = 0; ks < 2; ks++) {
            uint32_t Ah[2][4], Al[2][4], Bh[8][2], Bl[8][2];
#pragma unroll
            for (int mi = 0; mi < 2; mi++) {
                int row = wm + mi * 16 + a_mrow;
                int gran = ks * 2 + a_g;
                uint32_t addr = stage + row * 64 + ((gran ^ ((row >> 1) & 3)) << 4);
                ldsm_x4(Ah[mi], addr);
                ldsm_x4(Al[mi], addr + G1_AT);
            }
#pragma unroll
            for (int nb = 0; nb < 4; nb++) {
                int row = wn + nb * 16 + b_nrow;
                int gran = ks * 2 + b_g;
                uint32_t addr = stage + 2 * G1_AT + row * 64 +
                                ((gran ^ ((row >> 1) & 3)) << 4);
                uint32_t t[4];
                ldsm_x4(t, addr);
                Bh[nb * 2][0] = t[0]; Bh[nb * 2][1] = t[1];
                Bh[nb * 2 + 1][0] = t[2]; Bh[nb * 2 + 1][1] = t[3];
                ldsm_x4(t, addr + G1_BT);
                Bl[nb * 2][0] = t[0]; Bl[nb * 2][1] = t[1];
                Bl[nb * 2 + 1][0] = t[2]; Bl[nb * 2 + 1][1] = t[3];
            }
            if (ks == 1) BAR2_ARRIVE();
#pragma unroll
            for (int mi = 0; mi < 2; mi++)
#pragma unroll
                for (int ni = 0; ni < 8; ni++) mma_bf16(acc[mi][ni], Ah[mi], Bh[ni]);
#pragma unroll
            for (int mi = 0; mi < 2; mi++)
#pragma unroll
                for (int ni = 0; ni < 8; ni++) mma_bf16(acc[mi][ni], Ah[mi], Bl[ni]);
#pragma unroll
            for (int mi = 0; mi < 2; mi++)
#pragma unroll
                for (int ni = 0; ni < 8; ni++) mma_bf16(acc[mi][ni], Al[mi], Bh[ni]);
        }
    }

    const int erow = lid >> 2, ecol = 2 * (lid & 3);
#pragma unroll
    for (int mi = 0; mi < 2; mi++) {
#pragma unroll
        for (int ni = 0; ni < 8; ni++) {
            float* c0 = C + (size_t)(bm + wm + mi * 16 + erow) * N + bn + wn + ni * 8 + ecol;
            *(float2*)c0 = make_float2(acc[mi][ni][0], acc[mi][ni][1]);
            *(float2*)(c0 + 8 * N) = make_float2(acc[mi][ni][2], acc[mi][ni][3]);
        }
    }
}

// ---------------------------------------------------------------------------
// Pass A (tensor-core): chunk totals
// ---------------------------------------------------------------------------
#define CS_TILE (64 * P72 * 2)

__global__ __launch_bounds__(256) void chunk_sums_tc() {
    __shared__ char sm[4 * CS_TILE];
    const uint32_t sb = smem_u32(sm);
    __nv_bfloat16* Ah = (__nv_bfloat16*)sm;
    __nv_bfloat16* Al = (__nv_bfloat16*)(sm + CS_TILE);
    __nv_bfloat16* Bh = (__nv_bfloat16*)(sm + 2 * CS_TILE);
    __nv_bfloat16* Bl = (__nv_bfloat16*)(sm + 3 * CS_TILE);

    const int ck = blockIdx.x, bh = blockIdx.y;
    const int b = bh >> 4, h = bh & 15;
    const int tid = threadIdx.x;

    for (int i = tid; i < 4096; i += 256) {
        int tt = i >> 6, c = i & 63;
        const float* row = g_qkv + (size_t)(b * TT + ck * CHUNK + tt) * QKVW;
        __nv_bfloat16 hh, ll;
        float e = __expf(row[(NH + h) * HS + c]);
        split1(e, hh, ll);
        Ah[c * P72 + tt] = hh; Al[c * P72 + tt] = ll;
        float v = row[(2 * NH + h) * HS + c];
        split1(v, hh, ll);
        Bh[c * P72 + tt] = hh; Bl[c * P72 + tt] = ll;
    }
    __syncthreads();

    const int wid = tid >> 5, lid = tid & 31;
    const int a_mrow = (lid < 16 ? lid : lid - 16), a_g = (lid < 16 ? 0 : 1);
    const int b_q = lid & 7, b_g4 = lid >> 3;
    const int b_nrow = b_q + (b_g4 >> 1) * 8, b_g = b_g4 & 1;
    const int wm = (wid & 1) * 32, wn = (wid >> 1) * 16;

    float acc[2][2][4];
#pragma unroll
    for (int mi = 0; mi < 2; mi++)
#pragma unroll
        for (int ni = 0; ni < 2; ni++)
#pragma unroll
            for (int q = 0; q < 4; q++) acc[mi][ni][q] = 0.f;

    mm_tile<2, 1>(sb, sb + CS_TILE, sb + 2 * CS_TILE, sb + 3 * CS_TILE,
                  wm, wn, a_mrow, a_g, b_nrow, b_g, acc);

    float* st = g_state + (size_t)(bh * NCK + ck) * STSZ;
    const int erow = lid >> 2, ecol = 2 * (lid & 3);
#pragma unroll
    for (int mi = 0; mi < 2; mi++)
#pragma unroll
        for (int ni = 0; ni < 2; ni++) {
            int r = wm + mi * 16 + erow, cc = wn + ni * 8 + ecol;
            *(float2*)&st[r * 64 + cc] = make_float2(acc[mi][ni][0], acc[mi][ni][1]);
            *(float2*)&st[(r + 8) * 64 + cc] = make_float2(acc[mi][ni][2], acc[mi][ni][3]);
        }

    if (tid < 64) {
        float s = 0.f;
        for (int t2 = 0; t2 < 64; t2++)
            s += __bfloat162float(Ah[tid * P72 + t2]) + __bfloat162float(Al[tid * P72 + t2]);
        st[4096 + tid] = s;
    }
}

// ---------------------------------------------------------------------------
// Pass B: exclusive prefix over the 32 chunks
// ---------------------------------------------------------------------------
__global__ __launch_bounds__(256) void chunk_prefix() {
    const int bh = blockIdx.y;
    const int idx = blockIdx.x * 256 + threadIdx.x;
    if (idx >= STSZ) return;
    float run = 0.f;
    float* base = g_state + (size_t)bh * NCK * STSZ + idx;
    for (int ck = 0; ck < NCK; ck++) {
        float t = base[(size_t)ck * STSZ];
        base[(size_t)ck * STSZ] = run;
        run += t;
    }
}

// ---------------------------------------------------------------------------
// Pass C (tensor-core): intra-chunk attention
// ---------------------------------------------------------------------------
#define IC2_SMEM 91136

__global__ __launch_bounds__(256) void intra_tc() {
    extern __shared__ char sm[];
    float* R1f = (float*)sm;
    const uint32_t sb = smem_u32(sm);
    const uint32_t R2h = sb + 17408, R2l = sb + 26624;
    const uint32_t R3h = sb + 35840, R3l = sb + 45056;
    const uint32_t R4h = sb + 54272, R4l = sb + 63488;
    const uint32_t R5h = sb + 72704, R5l = sb + 81920;
    __nv_bfloat16* pR2h = (__nv_bfloat16*)(sm + 17408);
    __nv_bfloat16* pR2l = (__nv_bfloat16*)(sm + 26624);
    __nv_bfloat16* pR3h = (__nv_bfloat16*)(sm + 35840);
    __nv_bfloat16* pR3l = (__nv_bfloat16*)(sm + 45056);
    __nv_bfloat16* pR4h = (__nv_bfloat16*)(sm + 54272);
    __nv_bfloat16* pR4l = (__nv_bfloat16*)(sm + 63488);
    __nv_bfloat16* pR5h = (__nv_bfloat16*)(sm + 72704);
    __nv_bfloat16* pR5l = (__nv_bfloat16*)(sm + 81920);
    __shared__ float den0[64];

    const int ck = blockIdx.x, bh = blockIdx.y;
    const int b = bh >> 4, h = bh & 15;
    const int tid = threadIdx.x;
    const float* st = g_state + (size_t)(bh * NCK + ck) * STSZ;

    for (int i = tid; i < 4096; i += 256) {
        int tt = i >> 6, c = i & 63;
        const float* row = g_qkv + (size_t)(b * TT + ck * CHUNK + tt) * QKVW;
        R1f[tt * PAD + c] = row[h * HS + c];
        __nv_bfloat16 hh, ll;
        float e = __expf(row[(NH + h) * HS + c]);
        split1(e, hh, ll);
        pR3h[tt * P72 + c] = hh; pR3l[tt * P72 + c] = ll;
        float v = row[(2 * NH + h) * HS + c];
        split1(v, hh, ll);
        pR5h[c * P72 + tt] = hh; pR5l[c * P72 + tt] = ll;
        split1(st[i], hh, ll);
        pR4h[(i & 63) * P72 + (i >> 6)] = hh;
        pR4l[(i & 63) * P72 + (i >> 6)] = ll;
    }
    if (tid < 64) den0[tid] = st[4096 + tid];
    __syncthreads();

    {
        const int tq = tid >> 2, qd = tid & 3;
        float* qseg = R1f + tq * PAD + qd * 16;
        float v[16];
#pragma unroll
        for (int q = 0; q < 4; q++) {
            float4 f = ((const float4*)qseg)[q];
            v[4*q] = f.x; v[4*q+1] = f.y; v[4*q+2] = f.z; v[4*q+3] = f.w;
        }
        float m = v[0];
#pragma unroll
        for (int j = 1; j < 16; j++) m = fmaxf(m, v[j]);
        m = fmaxf(m, __shfl_xor_sync(0xFFFFFFFFu, m, 1));
        m = fmaxf(m, __shfl_xor_sync(0xFFFFFFFFu, m, 2));
        float s = 0.f;
#pragma unroll
        for (int j = 0; j < 16; j++) { v[j] = __expf(v[j] - m); s += v[j]; }
        s += __shfl_xor_sync(0xFFFFFFFFu, s, 1);
        s += __shfl_xor_sync(0xFFFFFFFFu, s, 2);
        float inv = 0.125f / s;
#pragma unroll
        for (int q = 0; q < 4; q++)
            ((float4*)qseg)[q] = make_float4(v[4*q] * inv, v[4*q+1] * inv,
                                             v[4*q+2] * inv, v[4*q+3] * inv);
    }
    __syncthreads();

    {
        const int c = tid >> 2, sg = tid & 3;
        float cum[16];
        float s = 0.f;
#pragma unroll
        for (int j = 0; j < 16; j++) {
            int t2 = sg * 16 + j;
            s += __bfloat162float(pR3h[t2 * P72 + c]) + __bfloat162float(pR3l[t2 * P72 + c]);
            cum[j] = s;
        }
        float x = s;
        float u1 = __shfl_up_sync(0xFFFFFFFFu, x, 1); if (sg >= 1) x += u1;
        float u2 = __shfl_up_sync(0xFFFFFFFFu, x, 2); if (sg >= 2) x += u2;
        float base = den0[c] + (x - s);
#pragma unroll
        for (int j = 0; j < 16; j++) {
            int t2 = sg * 16 + j;
            R1f[t2 * PAD + c] = R1f[t2 * PAD + c] / (base + cum[j] + 1e-9f);
        }
    }
    __syncthreads();

    for (int i = tid; i < 4096; i += 256) {
        int t2 = i >> 6, c = i & 63;
        __nv_bfloat16 hh, ll;
        split1(R1f[t2 * PAD + c], hh, ll);
        pR2h[t2 * P72 + c] = hh; pR2l[t2 * P72 + c] = ll;
    }
    __syncthreads();

    const int wid = tid >> 5, lid = tid & 31;
    const int a_mrow = (lid < 16 ? lid : lid - 16), a_g = (lid < 16 ? 0 : 1);
    const int b_q = lid & 7, b_g4 = lid >> 3;
    const int b_nrow = b_q + (b_g4 >> 1) * 8, b_g = b_g4 & 1;
    const int erow = lid >> 2, ecol = 2 * (lid & 3);

    float accA[2][4][4];
    if (wid < 4) {
        float accS[2][4][4];
#pragma unroll
        for (int mi = 0; mi < 2; mi++)
#pragma unroll
            for (int ni = 0; ni < 4; ni++)
#pragma unroll
                for (int q = 0; q < 4; q++) accS[mi][ni][q] = 0.f;
        int wm = (wid & 1) * 32, wn = (wid >> 1) * 32;
        mm_tile<2, 2>(R2h, R2l, R4h, R4l, wm, wn, a_mrow, a_g, b_nrow, b_g, accS);
#pragma unroll
        for (int mi = 0; mi < 2; mi++)
#pragma unroll
            for (int ni = 0; ni < 4; ni++) {
                int r = wm + mi * 16 + erow, d = wn + ni * 8 + ecol;
                *(float2*)&R1f[r * PAD + d] = make_float2(accS[mi][ni][0], accS[mi][ni][1]);
                *(float2*)&R1f[(r + 8) * PAD + d] = make_float2(accS[mi][ni][2], accS[mi][ni][3]);
            }
    } else {
#pragma unroll
        for (int mi = 0; mi < 2; mi++)
#pragma unroll
            for (int ni = 0; ni < 4; ni++)
#pragma unroll
                for (int q = 0; q < 4; q++) accA[mi][ni][q] = 0.f;
        int w4 = wid - 4;
        int wm = (w4 & 1) * 32, wn = (w4 >> 1) * 32;
        mm_tile<2, 2>(R2h, R2l, R3h, R3l, wm, wn, a_mrow, a_g, b_nrow, b_g, accA);
    }
    __syncthreads();

    if (wid >= 4) {
        int w4 = wid - 4;
        int wm = (w4 & 1) * 32, wn = (w4 >> 1) * 32;
#pragma unroll
        for (int mi = 0; mi < 2; mi++)
#pragma unroll
            for (int ni = 0; ni < 4; ni++) {
                int r0 = wm + mi * 16 + erow, s0 = wn + ni * 8 + ecol;
                float v0 = (s0 <= r0) ? accA[mi][ni][0] : 0.f;
                float v1 = (s0 + 1 <= r0) ? accA[mi][ni][1] : 0.f;
                uint32_t hp, lp;
                split2(v0, v1, hp, lp);
                *(uint32_t*)&pR4h[r0 * P72 + s0] = hp;
                *(uint32_t*)&pR4l[r0 * P72 + s0] = lp;
                int r2 = r0 + 8;
                float v2 = (s0 <= r2) ? accA[mi][ni][2] : 0.f;
                float v3 = (s0 + 1 <= r2) ? accA[mi][ni][3] : 0.f;
                split2(v2, v3, hp, lp);
                *(uint32_t*)&pR4h[r2 * P72 + s0] = hp;
                *(uint32_t*)&pR4l[r2 * P72 + s0] = lp;
            }
    }
    __syncthreads();

    {
        float accV[1][4][4];
#pragma unroll
        for (int ni = 0; ni < 4; ni++)
#pragma unroll
            for (int q = 0; q < 4; q++) accV[0][ni][q] = 0.f;
        int wm = (wid & 3) * 16, wn = (wid >> 2) * 32;
        mm_tile<1, 2>(R4h, R4l, R5h, R5l, wm, wn, a_mrow, a_g, b_nrow, b_g, accV);
#pragma unroll
        for (int ni = 0; ni < 4; ni++) {
            int r = wm + erow, d = wn + ni * 8 + ecol;
            uint32_t hp, lp;
            float x0 = accV[0][ni][0] + R1f[r * PAD + d];
            float x1 = accV[0][ni][1] + R1f[r * PAD + d + 1];
            split2(x0, x1, hp, lp);
            size_t g0 = (size_t)(b * TT + ck * CHUNK + r) * DM + h * HS + d;
            *(uint32_t*)&g_xoh[g0] = hp;
            *(uint32_t*)&g_xol[g0] = lp;
            int r2 = r + 8;
            float x2 = accV[0][ni][2] + R1f[r2 * PAD + d];
            float x3 = accV[0][ni][3] + R1f[r2 * PAD + d + 1];
            split2(x2, x3, hp, lp);
            size_t g2 = (size_t)(b * TT + ck * CHUNK + r2) * DM + h * HS + d;
            *(uint32_t*)&g_xoh[g2] = hp;
            *(uint32_t*)&g_xol[g2] = lp;
        }
    }
}

// ---------------------------------------------------------------------------
extern "C" void kernel_launch(void* const* d_in, const int* in_sizes, int n_in,
                              void* d_out, int out_size) {
    const float* x    = (const float*)d_in[0];
    const float* Wqkv = (const float*)d_in[1];
    const float* Wout = (const float*)d_in[2];
    float* out = (float*)d_out;

    float* qkv;
    cudaGetSymbolAddress((void**)&qkv, g_qkv);
    __nv_bfloat16 *xhi, *xlo, *wqh, *wql, *woh, *wol, *xoh, *xol;
    cudaGetSymbolAddress((void**)&xhi, g_xhi);
    cudaGetSymbolAddress((void**)&xlo, g_xlo);
    cudaGetSymbolAddress((void**)&wqh, g_wqh);
    cudaGetSymbolAddress((void**)&wql, g_wql);
    cudaGetSymbolAddress((void**)&woh, g_woh);
    cudaGetSymbolAddress((void**)&wol, g_wol);
    cudaGetSymbolAddress((void**)&xoh, g_xoh);
    cudaGetSymbolAddress((void**)&xol, g_xol);

    cudaFuncSetAttribute(gemm_bf16, cudaFuncAttributeMaxDynamicSharedMemorySize, GEMM_SMEM_B);
    cudaFuncSetAttribute(gemm_bf16_64, cudaFuncAttributeMaxDynamicSharedMemorySize, G1_SMEM);
    cudaFuncSetAttribute(intra_tc, cudaFuncAttributeMaxDynamicSharedMemorySize, IC2_SMEM);

    // 0) split inputs
    split_f32<<<(BB * TT * DM) / 1024, 256>>>(x, xhi, xlo, BB * TT * DM);
    split_f32<<<(QKVW * DM) / 1024, 256>>>(Wqkv, wqh, wql, QKVW * DM);
    split_f32<<<(DM * DM) / 1024, 256>>>(Wout, woh, wol, DM * DM);

    // 1) qkv = x @ Wqkv^T : 64x128 tiles, 3 CTAs/SM
    gemm_bf16_64<<<dim3(QKVW / 128, (BB * TT) / 64), 128, G1_SMEM>>>(
        xhi, xlo, wqh, wql, qkv, BB * TT, QKVW, DM);
    // 2) chunk totals
    chunk_sums_tc<<<dim3(NCK, NBH), 256>>>();
    // 3) exclusive prefix
    chunk_prefix<<<dim3((STSZ + 255) / 256, NBH), 256>>>();
    // 4) intra-chunk attention
    intra_tc<<<dim3(NCK, NBH), 256, IC2_SMEM>>>();
    // 5) out = xo @ Wout^T : keep 128x128 (single clean wave at 256 CTAs)
    gemm_bf16<<<dim3(DM / 128, (BB * TT) / 128), 256, GEMM_SMEM_B>>>(
        xoh, xol, woh, wol, out, BB * TT, DM, DM);
}

// round 12
// speedup vs baseline: 3.4103x; 1.0066x over previous
#include <cuda_runtime.h>
#include <cuda_bf16.h>
#include <cstdint>

// Problem constants
#define BB 2
#define TT 2048
#define DM 1024
#define NH 16
#define HS 64
#define QKVW 3072
#define CHUNK 64
#define NCK (TT / CHUNK)
#define NBH (BB * NH)
#define STSZ (HS * HS + HS)
#define PAD 68
#define P72 72

// Scratch
__device__ float g_qkv[(size_t)BB * TT * QKVW];
__device__ float g_state[(size_t)NBH * NCK * STSZ];
__device__ __nv_bfloat16 g_xhi[(size_t)BB * TT * DM];
__device__ __nv_bfloat16 g_xlo[(size_t)BB * TT * DM];
__device__ __nv_bfloat16 g_wqh[(size_t)QKVW * DM];
__device__ __nv_bfloat16 g_wql[(size_t)QKVW * DM];
__device__ __nv_bfloat16 g_woh[(size_t)DM * DM];
__device__ __nv_bfloat16 g_wol[(size_t)DM * DM];
__device__ __nv_bfloat16 g_xoh[(size_t)BB * TT * DM];
__device__ __nv_bfloat16 g_xol[(size_t)BB * TT * DM];

// ===========================================================================
// Helpers
// ===========================================================================
__device__ __forceinline__ uint32_t smem_u32(const void* p) {
    uint32_t a;
    asm("{ .reg .u64 t; cvta.to.shared.u64 t, %1; cvt.u32.u64 %0, t; }"
        : "=r"(a) : "l"(p));
    return a;
}

#define CP_ASYNC16(dst, src) \
    asm volatile("cp.async.cg.shared.global [%0], [%1], 16;" :: "r"(dst), "l"(src))
#define CP_COMMIT() asm volatile("cp.async.commit_group;" ::: "memory")
#define CP_WAIT1()  asm volatile("cp.async.wait_group 1;" ::: "memory")
#define CP_WAIT0()  asm volatile("cp.async.wait_group 0;" ::: "memory")

// 128-thread split barrier
#define BAR2_ARRIVE() asm volatile("bar.arrive 1, 256;" ::: "memory")
#define BAR2_SYNC()   asm volatile("bar.sync 1, 256;" ::: "memory")

__device__ __forceinline__ void ldsm_x4(uint32_t* r, uint32_t addr) {
    asm volatile("ldmatrix.sync.aligned.m8n8.x4.shared.b16 {%0,%1,%2,%3}, [%4];"
                 : "=r"(r[0]), "=r"(r[1]), "=r"(r[2]), "=r"(r[3]) : "r"(addr));
}

__device__ __forceinline__ void mma_bf16(float* c, const uint32_t* a, const uint32_t* b) {
    asm volatile(
        "mma.sync.aligned.m16n8k16.row.col.f32.bf16.bf16.f32 "
        "{%0,%1,%2,%3}, {%4,%5,%6,%7}, {%8,%9}, {%0,%1,%2,%3};"
        : "+f"(c[0]), "+f"(c[1]), "+f"(c[2]), "+f"(c[3])
        : "r"(a[0]), "r"(a[1]), "r"(a[2]), "r"(a[3]), "r"(b[0]), "r"(b[1]));
}

__device__ __forceinline__ void split2(float a, float b, uint32_t& hp, uint32_t& lp) {
    __nv_bfloat162 h = __floats2bfloat162_rn(a, b);
    float2 hf = __bfloat1622float2(h);
    __nv_bfloat162 l = __floats2bfloat162_rn(a - hf.x, b - hf.y);
    hp = *(uint32_t*)&h;
    lp = *(uint32_t*)&l;
}

__device__ __forceinline__ void split1(float v, __nv_bfloat16& h, __nv_bfloat16& l) {
    h = __float2bfloat16(v);
    l = __float2bfloat16(v - __bfloat162float(h));
}

// Generic split-bf16 MMA tile (pitch-72 bf16 smem, NT, K=64). Term-major.
template<int MI, int NB>
__device__ __forceinline__ void mm_tile(uint32_t Ahb, uint32_t Alb,
                                        uint32_t Bhb, uint32_t Blb,
                                        int wm, int wn,
                                        int a_mrow, int a_g, int b_nrow, int b_g,
                                        float acc[MI][2 * NB][4]) {
#pragma unroll
    for (int ks = 0; ks < 4; ks++) {
        uint32_t Ah[MI][4], Al[MI][4], Bh[2 * NB][2], Bl[2 * NB][2];
#pragma unroll
        for (int mi = 0; mi < MI; mi++) {
            uint32_t ao = (uint32_t)((wm + mi * 16 + a_mrow) * (P72 * 2) + (ks * 2 + a_g) * 16);
            ldsm_x4(Ah[mi], Ahb + ao);
            ldsm_x4(Al[mi], Alb + ao);
        }
#pragma unroll
        for (int nb = 0; nb < NB; nb++) {
            uint32_t bo = (uint32_t)((wn + nb * 16 + b_nrow) * (P72 * 2) + (ks * 2 + b_g) * 16);
            uint32_t t0[4], t1[4];
            ldsm_x4(t0, Bhb + bo);
            ldsm_x4(t1, Blb + bo);
            Bh[nb * 2][0] = t0[0]; Bh[nb * 2][1] = t0[1];
            Bh[nb * 2 + 1][0] = t0[2]; Bh[nb * 2 + 1][1] = t0[3];
            Bl[nb * 2][0] = t1[0]; Bl[nb * 2][1] = t1[1];
            Bl[nb * 2 + 1][0] = t1[2]; Bl[nb * 2 + 1][1] = t1[3];
        }
#pragma unroll
        for (int mi = 0; mi < MI; mi++)
#pragma unroll
            for (int ni = 0; ni < 2 * NB; ni++) mma_bf16(acc[mi][ni], Ah[mi], Bh[ni]);
#pragma unroll
        for (int mi = 0; mi < MI; mi++)
#pragma unroll
            for (int ni = 0; ni < 2 * NB; ni++) mma_bf16(acc[mi][ni], Ah[mi], Bl[ni]);
#pragma unroll
        for (int mi = 0; mi < MI; mi++)
#pragma unroll
            for (int ni = 0; ni < 2 * NB; ni++) mma_bf16(acc[mi][ni], Al[mi], Bh[ni]);
    }
}

// ---------------------------------------------------------------------------
// Prep: fp32 -> bf16 hi/lo split
// ---------------------------------------------------------------------------
__global__ __launch_bounds__(256) void split_f32(const float* __restrict__ src,
                                                 __nv_bfloat16* __restrict__ hi,
                                                 __nv_bfloat16* __restrict__ lo,
                                                 int n) {
    int i = (blockIdx.x * 256 + threadIdx.x) * 4;
    if (i >= n) return;
    float4 v = *(const float4*)(src + i);
    uint32_t h0, l0, h1, l1;
    split2(v.x, v.y, h0, l0);
    split2(v.z, v.w, h1, l1);
    *(uint2*)(hi + i) = make_uint2(h0, h1);
    *(uint2*)(lo + i) = make_uint2(l0, l1);
}

// ===========================================================================
// GEMM: 64x128 tile, 128 threads, warp grid 2x2 (32x64/warp), NSTAGE=3,
// 3 CTAs/SM. Used for BOTH gemm1 and gemm2.
// Stage layout: Ahi(4KB) Alo(4KB) Bhi(8KB) Blo(8KB) = 24576 B.
// ===========================================================================
#define KT 32
#define G1_AT 4096
#define G1_BT 8192
#define G1_STAGE 24576
#define G1_SMEM (3 * G1_STAGE)   // 73728 B

__global__ __launch_bounds__(128, 3) void gemm_bf16_64(
        const __nv_bfloat16* __restrict__ Ahi,
        const __nv_bfloat16* __restrict__ Alo,
        const __nv_bfloat16* __restrict__ Bhi,
        const __nv_bfloat16* __restrict__ Blo,
        float* __restrict__ C,
        int M, int N, int K) {
    extern __shared__ char smraw[];
    const uint32_t sb = smem_u32(smraw);
    const int tid = threadIdx.x, wid = tid >> 5, lid = tid & 31;
    const int bm = blockIdx.y * 64, bn = blockIdx.x * 128;
    const int wm = (wid & 1) * 32, wn = (wid >> 1) * 64;
    const int NC = K / KT;

#define CP_STAGE1(kc, s)                                                       \
    {                                                                          \
        uint32_t stb = sb + (s) * G1_STAGE;                                    \
        _Pragma("unroll")                                                      \
        for (int it = 0; it < 4; it++) {  /* A: 512 granules */                \
            int cid = it * 128 + tid;                                          \
            int comp = cid >> 8;                                               \
            int rem = cid & 255;                                               \
            int r = rem >> 2, g = rem & 3;                                     \
            const __nv_bfloat16* src = (comp ? Alo : Ahi) +                    \
                (size_t)(bm + r) * K + (kc) * KT + g * 8;                      \
            uint32_t dst = stb + comp * G1_AT + r * 64 +                       \
                           ((g ^ ((r >> 1) & 3)) << 4);                        \
            CP_ASYNC16(dst, src);                                              \
        }                                                                      \
        _Pragma("unroll")                                                      \
        for (int it = 0; it < 8; it++) {  /* B: 1024 granules */               \
            int cid = it * 128 + tid;                                          \
            int comp = cid >> 9;                                               \
            int rem = cid & 511;                                               \
            int r = rem >> 2, g = rem & 3;                                     \
            const __nv_bfloat16* src = (comp ? Blo : Bhi) +                    \
                (size_t)(bn + r) * K + (kc) * KT + g * 8;                      \
            uint32_t dst = stb + 2 * G1_AT + comp * G1_BT + r * 64 +           \
                           ((g ^ ((r >> 1) & 3)) << 4);                        \
            CP_ASYNC16(dst, src);                                              \
        }                                                                      \
        CP_COMMIT();                                                           \
    }

    float acc[2][8][4];
#pragma unroll
    for (int mi = 0; mi < 2; mi++)
#pragma unroll
        for (int ni = 0; ni < 8; ni++)
#pragma unroll
            for (int q = 0; q < 4; q++) acc[mi][ni][q] = 0.f;

    const int a_mrow = (lid < 16 ? lid : lid - 16);
    const int a_g    = (lid < 16 ? 0 : 1);
    const int b_q = lid & 7, b_g4 = lid >> 3;
    const int b_nrow = b_q + (b_g4 >> 1) * 8;
    const int b_g    = (b_g4 & 1);

    CP_STAGE1(0, 0);
    CP_STAGE1(1, 1);
    BAR2_ARRIVE();

    for (int kc = 0; kc < NC; kc++) {
        if (kc < NC - 1) { CP_WAIT1(); } else { CP_WAIT0(); }
        BAR2_SYNC();
        if (kc + 2 < NC) CP_STAGE1(kc + 2, (kc + 2) % 3);

        const uint32_t stage = sb + (kc % 3) * G1_STAGE;
#pragma unroll
        for (int ks = 0; ks < 2; ks++) {
            uint32_t Ah[2][4], Al[2][4], Bh[8][2], Bl[8][2];
#pragma unroll
            for (int mi = 0; mi < 2; mi++) {
                int row = wm + mi * 16 + a_mrow;
                int gran = ks * 2 + a_g;
                uint32_t addr = stage + row * 64 + ((gran ^ ((row >> 1) & 3)) << 4);
                ldsm_x4(Ah[mi], addr);
                ldsm_x4(Al[mi], addr + G1_AT);
            }
#pragma unroll
            for (int nb = 0; nb < 4; nb++) {
                int row = wn + nb * 16 + b_nrow;
                int gran = ks * 2 + b_g;
                uint32_t addr = stage + 2 * G1_AT + row * 64 +
                                ((gran ^ ((row >> 1) & 3)) << 4);
                uint32_t t[4];
                ldsm_x4(t, addr);
                Bh[nb * 2][0] = t[0]; Bh[nb * 2][1] = t[1];
                Bh[nb * 2 + 1][0] = t[2]; Bh[nb * 2 + 1][1] = t[3];
                ldsm_x4(t, addr + G1_BT);
                Bl[nb * 2][0] = t[0]; Bl[nb * 2][1] = t[1];
                Bl[nb * 2 + 1][0] = t[2]; Bl[nb * 2 + 1][1] = t[3];
            }
            if (ks == 1) BAR2_ARRIVE();
#pragma unroll
            for (int mi = 0; mi < 2; mi++)
#pragma unroll
                for (int ni = 0; ni < 8; ni++) mma_bf16(acc[mi][ni], Ah[mi], Bh[ni]);
#pragma unroll
            for (int mi = 0; mi < 2; mi++)
#pragma unroll
                for (int ni = 0; ni < 8; ni++) mma_bf16(acc[mi][ni], Ah[mi], Bl[ni]);
#pragma unroll
            for (int mi = 0; mi < 2; mi++)
#pragma unroll
                for (int ni = 0; ni < 8; ni++) mma_bf16(acc[mi][ni], Al[mi], Bh[ni]);
        }
    }

    const int erow = lid >> 2, ecol = 2 * (lid & 3);
#pragma unroll
    for (int mi = 0; mi < 2; mi++) {
#pragma unroll
        for (int ni = 0; ni < 8; ni++) {
            float* c0 = C + (size_t)(bm + wm + mi * 16 + erow) * N + bn + wn + ni * 8 + ecol;
            *(float2*)c0 = make_float2(acc[mi][ni][0], acc[mi][ni][1]);
            *(float2*)(c0 + 8 * N) = make_float2(acc[mi][ni][2], acc[mi][ni][3]);
        }
    }
}

// ---------------------------------------------------------------------------
// Pass A (tensor-core): chunk totals
// ---------------------------------------------------------------------------
#define CS_TILE (64 * P72 * 2)

__global__ __launch_bounds__(256) void chunk_sums_tc() {
    __shared__ char sm[4 * CS_TILE];
    const uint32_t sb = smem_u32(sm);
    __nv_bfloat16* Ah = (__nv_bfloat16*)sm;
    __nv_bfloat16* Al = (__nv_bfloat16*)(sm + CS_TILE);
    __nv_bfloat16* Bh = (__nv_bfloat16*)(sm + 2 * CS_TILE);
    __nv_bfloat16* Bl = (__nv_bfloat16*)(sm + 3 * CS_TILE);

    const int ck = blockIdx.x, bh = blockIdx.y;
    const int b = bh >> 4, h = bh & 15;
    const int tid = threadIdx.x;

    for (int i = tid; i < 4096; i += 256) {
        int tt = i >> 6, c = i & 63;
        const float* row = g_qkv + (size_t)(b * TT + ck * CHUNK + tt) * QKVW;
        __nv_bfloat16 hh, ll;
        float e = __expf(row[(NH + h) * HS + c]);
        split1(e, hh, ll);
        Ah[c * P72 + tt] = hh; Al[c * P72 + tt] = ll;
        float v = row[(2 * NH + h) * HS + c];
        split1(v, hh, ll);
        Bh[c * P72 + tt] = hh; Bl[c * P72 + tt] = ll;
    }
    __syncthreads();

    const int wid = tid >> 5, lid = tid & 31;
    const int a_mrow = (lid < 16 ? lid : lid - 16), a_g = (lid < 16 ? 0 : 1);
    const int b_q = lid & 7, b_g4 = lid >> 3;
    const int b_nrow = b_q + (b_g4 >> 1) * 8, b_g = b_g4 & 1;
    const int wm = (wid & 1) * 32, wn = (wid >> 1) * 16;

    float acc[2][2][4];
#pragma unroll
    for (int mi = 0; mi < 2; mi++)
#pragma unroll
        for (int ni = 0; ni < 2; ni++)
#pragma unroll
            for (int q = 0; q < 4; q++) acc[mi][ni][q] = 0.f;

    mm_tile<2, 1>(sb, sb + CS_TILE, sb + 2 * CS_TILE, sb + 3 * CS_TILE,
                  wm, wn, a_mrow, a_g, b_nrow, b_g, acc);

    float* st = g_state + (size_t)(bh * NCK + ck) * STSZ;
    const int erow = lid >> 2, ecol = 2 * (lid & 3);
#pragma unroll
    for (int mi = 0; mi < 2; mi++)
#pragma unroll
        for (int ni = 0; ni < 2; ni++) {
            int r = wm + mi * 16 + erow, cc = wn + ni * 8 + ecol;
            *(float2*)&st[r * 64 + cc] = make_float2(acc[mi][ni][0], acc[mi][ni][1]);
            *(float2*)&st[(r + 8) * 64 + cc] = make_float2(acc[mi][ni][2], acc[mi][ni][3]);
        }

    if (tid < 64) {
        float s = 0.f;
        for (int t2 = 0; t2 < 64; t2++)
            s += __bfloat162float(Ah[tid * P72 + t2]) + __bfloat162float(Al[tid * P72 + t2]);
        st[4096 + tid] = s;
    }
}

// ---------------------------------------------------------------------------
// Pass B: exclusive prefix over the 32 chunks
// ---------------------------------------------------------------------------
__global__ __launch_bounds__(256) void chunk_prefix() {
    const int bh = blockIdx.y;
    const int idx = blockIdx.x * 256 + threadIdx.x;
    if (idx >= STSZ) return;
    float run = 0.f;
    float* base = g_state + (size_t)bh * NCK * STSZ + idx;
    for (int ck = 0; ck < NCK; ck++) {
        float t = base[(size_t)ck * STSZ];
        base[(size_t)ck * STSZ] = run;
        run += t;
    }
}

// ---------------------------------------------------------------------------
// Pass C (tensor-core): intra-chunk attention. 72KB smem -> 3 CTAs/SM.
// Region multi-use (all offsets bytes from dynamic base):
//   [0, 18432): phases 1-3 = q f32 (pitch 68); phase 4+ = qn bf16 hi/lo
//               (R2h=0, R2l=9216); after phase-5 sync = xo_acc f32.
//   [18432, 36864): kexp hi/lo   [36864, 55296): S0^T hi/lo -> A hi/lo
//   [55296, 73728): V^T hi/lo
// ---------------------------------------------------------------------------
#define IC3_SMEM 73728

__global__ __launch_bounds__(256) void intra_tc() {
    extern __shared__ char sm[];
    float* Qf = (float*)sm;                         // q f32 / xo_acc f32
    const uint32_t sb = smem_u32(sm);
    const uint32_t R2h = sb,          R2l = sb + 9216;
    const uint32_t R3h = sb + 18432,  R3l = sb + 27648;
    const uint32_t R4h = sb + 36864,  R4l = sb + 46080;
    const uint32_t R5h = sb + 55296,  R5l = sb + 64512;
    __nv_bfloat16* pR2h = (__nv_bfloat16*)(sm);
    __nv_bfloat16* pR2l = (__nv_bfloat16*)(sm + 9216);
    __nv_bfloat16* pR3h = (__nv_bfloat16*)(sm + 18432);
    __nv_bfloat16* pR3l = (__nv_bfloat16*)(sm + 27648);
    __nv_bfloat16* pR4h = (__nv_bfloat16*)(sm + 36864);
    __nv_bfloat16* pR4l = (__nv_bfloat16*)(sm + 46080);
    __nv_bfloat16* pR5h = (__nv_bfloat16*)(sm + 55296);
    __nv_bfloat16* pR5l = (__nv_bfloat16*)(sm + 64512);
    __shared__ float den0[64];

    const int ck = blockIdx.x, bh = blockIdx.y;
    const int b = bh >> 4, h = bh & 15;
    const int tid = threadIdx.x;
    const float* st = g_state + (size_t)(bh * NCK + ck) * STSZ;

    // Phase 1: loads (+ exp, splits, transposes); q kept f32 in Qf
    for (int i = tid; i < 4096; i += 256) {
        int tt = i >> 6, c = i & 63;
        const float* row = g_qkv + (size_t)(b * TT + ck * CHUNK + tt) * QKVW;
        Qf[tt * PAD + c] = row[h * HS + c];
        __nv_bfloat16 hh, ll;
        float e = __expf(row[(NH + h) * HS + c]);
        split1(e, hh, ll);
        pR3h[tt * P72 + c] = hh; pR3l[tt * P72 + c] = ll;
        float v = row[(2 * NH + h) * HS + c];
        split1(v, hh, ll);
        pR5h[c * P72 + tt] = hh; pR5l[c * P72 + tt] = ll;
        split1(st[i], hh, ll);
        pR4h[(i & 63) * P72 + (i >> 6)] = hh;
        pR4l[(i & 63) * P72 + (i >> 6)] = ll;
    }
    if (tid < 64) den0[tid] = st[4096 + tid];
    __syncthreads();

    // Phase 2: softmax over head dim per row t (4 lanes/row)
    {
        const int tq = tid >> 2, qd = tid & 3;
        float* qseg = Qf + tq * PAD + qd * 16;
        float v[16];
#pragma unroll
        for (int q = 0; q < 4; q++) {
            float4 f = ((const float4*)qseg)[q];
            v[4*q] = f.x; v[4*q+1] = f.y; v[4*q+2] = f.z; v[4*q+3] = f.w;
        }
        float m = v[0];
#pragma unroll
        for (int j = 1; j < 16; j++) m = fmaxf(m, v[j]);
        m = fmaxf(m, __shfl_xor_sync(0xFFFFFFFFu, m, 1));
        m = fmaxf(m, __shfl_xor_sync(0xFFFFFFFFu, m, 2));
        float s = 0.f;
#pragma unroll
        for (int j = 0; j < 16; j++) { v[j] = __expf(v[j] - m); s += v[j]; }
        s += __shfl_xor_sync(0xFFFFFFFFu, s, 1);
        s += __shfl_xor_sync(0xFFFFFFFFu, s, 2);
        float inv = 0.125f / s;
#pragma unroll
        for (int q = 0; q < 4; q++)
            ((float4*)qseg)[q] = make_float4(v[4*q] * inv, v[4*q+1] * inv,
                                             v[4*q+2] * inv, v[4*q+3] * inv);
    }
    __syncthreads();

    // Phase 3: per-column denominator cumsum, fold into q
    {
        const int c = tid >> 2, sg = tid & 3;
        float cum[16];
        float s = 0.f;
#pragma unroll
        for (int j = 0; j < 16; j++) {
            int t2 = sg * 16 + j;
            s += __bfloat162float(pR3h[t2 * P72 + c]) + __bfloat162float(pR3l[t2 * P72 + c]);
            cum[j] = s;
        }
        float x = s;
        float u1 = __shfl_up_sync(0xFFFFFFFFu, x, 1); if (sg >= 1) x += u1;
        float u2 = __shfl_up_sync(0xFFFFFFFFu, x, 2); if (sg >= 2) x += u2;
        float base = den0[c] + (x - s);
#pragma unroll
        for (int j = 0; j < 16; j++) {
            int t2 = sg * 16 + j;
            Qf[t2 * PAD + c] = Qf[t2 * PAD + c] / (base + cum[j] + 1e-9f);
        }
    }
    __syncthreads();

    // Phase 4: q f32 -> regs -> sync -> qn bf16 hi/lo into SAME region
    {
        float qreg[16];
#pragma unroll
        for (int it = 0; it < 16; it++) {
            int i = tid + it * 256;
            qreg[it] = Qf[(i >> 6) * PAD + (i & 63)];
        }
        __syncthreads();
#pragma unroll
        for (int it = 0; it < 16; it++) {
            int i = tid + it * 256;
            __nv_bfloat16 hh, ll;
            split1(qreg[it], hh, ll);
            pR2h[(i >> 6) * P72 + (i & 63)] = hh;
            pR2l[(i >> 6) * P72 + (i & 63)] = ll;
        }
    }
    __syncthreads();

    const int wid = tid >> 5, lid = tid & 31;
    const int a_mrow = (lid < 16 ? lid : lid - 16), a_g = (lid < 16 ? 0 : 1);
    const int b_q = lid & 7, b_g4 = lid >> 3;
    const int b_nrow = b_q + (b_g4 >> 1) * 8, b_g = b_g4 & 1;
    const int erow = lid >> 2, ecol = 2 * (lid & 3);

    // Phase 5: QS (warps 0-3) || QK (warps 4-7); keep results in regs
    float accS[2][4][4], accA[2][4][4];
    if (wid < 4) {
#pragma unroll
        for (int mi = 0; mi < 2; mi++)
#pragma unroll
            for (int ni = 0; ni < 4; ni++)
#pragma unroll
                for (int q = 0; q < 4; q++) accS[mi][ni][q] = 0.f;
        int wm = (wid & 1) * 32, wn = (wid >> 1) * 32;
        mm_tile<2, 2>(R2h, R2l, R4h, R4l, wm, wn, a_mrow, a_g, b_nrow, b_g, accS);
    } else {
#pragma unroll
        for (int mi = 0; mi < 2; mi++)
#pragma unroll
            for (int ni = 0; ni < 4; ni++)
#pragma unroll
                for (int q = 0; q < 4; q++) accA[mi][ni][q] = 0.f;
        int w4 = wid - 4;
        int wm = (w4 & 1) * 32, wn = (w4 >> 1) * 32;
        mm_tile<2, 2>(R2h, R2l, R3h, R3l, wm, wn, a_mrow, a_g, b_nrow, b_g, accA);
    }
    __syncthreads();   // all reads of qn (R2) and S0 (R4) complete

    // Phase 5b: w0-3 write xo_acc f32 into Qf; w4-7 mask A -> bf16 into R4
    if (wid < 4) {
        int wm = (wid & 1) * 32, wn = (wid >> 1) * 32;
#pragma unroll
        for (int mi = 0; mi < 2; mi++)
#pragma unroll
            for (int ni = 0; ni < 4; ni++) {
                int r = wm + mi * 16 + erow, d = wn + ni * 8 + ecol;
                *(float2*)&Qf[r * PAD + d] = make_float2(accS[mi][ni][0], accS[mi][ni][1]);
                *(float2*)&Qf[(r + 8) * PAD + d] = make_float2(accS[mi][ni][2], accS[mi][ni][3]);
            }
    } else {
        int w4 = wid - 4;
        int wm = (w4 & 1) * 32, wn = (w4 >> 1) * 32;
#pragma unroll
        for (int mi = 0; mi < 2; mi++)
#pragma unroll
            for (int ni = 0; ni < 4; ni++) {
                int r0 = wm + mi * 16 + erow, s0 = wn + ni * 8 + ecol;
                float v0 = (s0 <= r0) ? accA[mi][ni][0] : 0.f;
                float v1 = (s0 + 1 <= r0) ? accA[mi][ni][1] : 0.f;
                uint32_t hp, lp;
                split2(v0, v1, hp, lp);
                *(uint32_t*)&pR4h[r0 * P72 + s0] = hp;
                *(uint32_t*)&pR4l[r0 * P72 + s0] = lp;
                int r2 = r0 + 8;
                float v2 = (s0 <= r2) ? accA[mi][ni][2] : 0.f;
                float v3 = (s0 + 1 <= r2) ? accA[mi][ni][3] : 0.f;
                split2(v2, v3, hp, lp);
                *(uint32_t*)&pR4h[r2 * P72 + s0] = hp;
                *(uint32_t*)&pR4l[r2 * P72 + s0] = lp;
            }
    }
    __syncthreads();

    // Phase 6: AV (all 8 warps), add xo_acc, split, store
    {
        float accV[1][4][4];
#pragma unroll
        for (int ni = 0; ni < 4; ni++)
#pragma unroll
            for (int q = 0; q < 4; q++) accV[0][ni][q] = 0.f;
        int wm = (wid & 3) * 16, wn = (wid >> 2) * 32;
        mm_tile<1, 2>(R4h, R4l, R5h, R5l, wm, wn, a_mrow, a_g, b_nrow, b_g, accV);
#pragma unroll
        for (int ni = 0; ni < 4; ni++) {
            int r = wm + erow, d = wn + ni * 8 + ecol;
            uint32_t hp, lp;
            float x0 = accV[0][ni][0] + Qf[r * PAD + d];
            float x1 = accV[0][ni][1] + Qf[r * PAD + d + 1];
            split2(x0, x1, hp, lp);
            size_t g0 = (size_t)(b * TT + ck * CHUNK + r) * DM + h * HS + d;
            *(uint32_t*)&g_xoh[g0] = hp;
            *(uint32_t*)&g_xol[g0] = lp;
            int r2 = r + 8;
            float x2 = accV[0][ni][2] + Qf[r2 * PAD + d];
            float x3 = accV[0][ni][3] + Qf[r2 * PAD + d + 1];
            split2(x2, x3, hp, lp);
            size_t g2 = (size_t)(b * TT + ck * CHUNK + r2) * DM + h * HS + d;
            *(uint32_t*)&g_xoh[g2] = hp;
            *(uint32_t*)&g_xol[g2] = lp;
        }
    }
}

// ---------------------------------------------------------------------------
extern "C" void kernel_launch(void* const* d_in, const int* in_sizes, int n_in,
                              void* d_out, int out_size) {
    const float* x    = (const float*)d_in[0];
    const float* Wqkv = (const float*)d_in[1];
    const float* Wout = (const float*)d_in[2];
    float* out = (float*)d_out;

    float* qkv;
    cudaGetSymbolAddress((void**)&qkv, g_qkv);
    __nv_bfloat16 *xhi, *xlo, *wqh, *wql, *woh, *wol, *xoh, *xol;
    cudaGetSymbolAddress((void**)&xhi, g_xhi);
    cudaGetSymbolAddress((void**)&xlo, g_xlo);
    cudaGetSymbolAddress((void**)&wqh, g_wqh);
    cudaGetSymbolAddress((void**)&wql, g_wql);
    cudaGetSymbolAddress((void**)&woh, g_woh);
    cudaGetSymbolAddress((void**)&wol, g_wol);
    cudaGetSymbolAddress((void**)&xoh, g_xoh);
    cudaGetSymbolAddress((void**)&xol, g_xol);

    cudaFuncSetAttribute(gemm_bf16_64, cudaFuncAttributeMaxDynamicSharedMemorySize, G1_SMEM);
    cudaFuncSetAttribute(intra_tc, cudaFuncAttributeMaxDynamicSharedMemorySize, IC3_SMEM);

    // 0) split inputs
    split_f32<<<(BB * TT * DM) / 1024, 256>>>(x, xhi, xlo, BB * TT * DM);
    split_f32<<<(QKVW * DM) / 1024, 256>>>(Wqkv, wqh, wql, QKVW * DM);
    split_f32<<<(DM * DM) / 1024, 256>>>(Wout, woh, wol, DM * DM);

    // 1) qkv = x @ Wqkv^T : 64x128 tiles, 3 CTAs/SM
    gemm_bf16_64<<<dim3(QKVW / 128, (BB * TT) / 64), 128, G1_SMEM>>>(
        xhi, xlo, wqh, wql, qkv, BB * TT, QKVW, DM);
    // 2) chunk totals
    chunk_sums_tc<<<dim3(NCK, NBH), 256>>>();
    // 3) exclusive prefix
    chunk_prefix<<<dim3((STSZ + 255) / 256, NBH), 256>>>();
    // 4) intra-chunk attention (3 CTAs/SM now)
    intra_tc<<<dim3(NCK, NBH), 256, IC3_SMEM>>>();
    // 5) out = xo @ Wout^T : same 64x128 kernel
    gemm_bf16_64<<<dim3(DM / 128, (BB * TT) / 64), 128, G1_SMEM>>>(
        xoh, xol, woh, wol, out, BB * TT, DM, DM);
}